// round 7
// baseline (speedup 1.0000x reference)
#include <cuda_runtime.h>
#include <cuda_bf16.h>
#include <cstdint>
#include <cstddef>

// Problem constants
#define B_   64
#define S_   128
#define Wc_  16
#define E_   256
#define H_   512
#define NC_  20
#define NW_  (B_*S_)        // 8192 words total
#define G_   (4*H_)         // 2048 word-LSTM gate width
#define CH_  (2*H_)         // 1024 char-LSTM hidden
#define CG_  (4*CH_)        // 4096 char-LSTM gate width

#define NBLK_ 128           // persistent word-layer blocks
#define LDS_  72            // hgemm smem halfword stride (64 + 8 pad)

// ---------------- scratch (static device globals; no allocation) ----------------
__device__ __nv_bfloat16 g_Xembs[(size_t)NW_*3*E_];    // split word emb   [8192,768]
__device__ float g_XGf [(size_t)NW_*G_];               // fwd x-gates      [8192,2048]
__device__ float g_XGb [(size_t)NW_*G_];               // bwd x-gates      [8192,2048]
__device__ float g_H0  [(size_t)NW_*CH_];              // layer0 out fp32 (scratch)
__device__ __nv_bfloat16 g_H0s[(size_t)NW_*3*CH_];     // layer0 out split [8192,3072]
__device__ float g_H1  [(size_t)NW_*CH_];              // layer1 output    [8192,1024]
__device__ float g_hpp[(size_t)2*2*B_*H_];             // h ping-pong
__device__ unsigned g_bar;                             // grid barrier counter
__device__ float g_P  [(size_t)128*CG_];               // char_emb @ c_Wih.T [128,4096]
__device__ float g_Zc [(size_t)NW_*CG_];               // char recurrent gates (sorted)
__device__ float g_ch [(size_t)NW_*CH_];               // char h fp32 (sorted slots)
__device__ __nv_bfloat16 g_hs[(size_t)NW_*3*CH_];      // char h split [8192,3072]
__device__ float g_cc [(size_t)NW_*CH_];               // char c state (sorted)
__device__ __nv_bfloat16 g_Wc2   [(size_t)CG_*3*CH_];  // c_Whh split  [4096,3072]
__device__ __nv_bfloat16 g_Wih0s [(size_t)2*G_*3*E_];  // l0_Wih split [2][2048,768]
__device__ __nv_bfloat16 g_Wih1s [(size_t)2*G_*3*CH_]; // l1_Wih split [2][2048,3072]

// ---- length-sort bookkeeping ----
__device__ int g_hist[Wc_ + 1];
__device__ int g_off [Wc_ + 1];
__device__ int g_act [Wc_ + 1];
__device__ int g_perm [NW_];
__device__ int g_iperm[NW_];
__device__ int g_slen [NW_];

__device__ __forceinline__ float sigf(float x) { return 1.f / (1.f + __expf(-x)); }

__device__ __forceinline__ void bf16split(float x, __nv_bfloat16& hi, __nv_bfloat16& lo)
{
    hi = __float2bfloat16(x);
    lo = __float2bfloat16(x - __bfloat162float(hi));
}

__device__ __forceinline__ void cp16(void* dst, const void* src)
{
    uint32_t d = (uint32_t)__cvta_generic_to_shared(dst);
    asm volatile("cp.async.cg.shared.global [%0], [%1], 16;" :: "r"(d), "l"(src));
}

// ---------------- counting sort by char_lens (descending) ----------------
__global__ void hist_k(const int* __restrict__ clens)
{
    const int i = blockIdx.x * blockDim.x + threadIdx.x;
    if (i < NW_) atomicAdd(&g_hist[clens[i]], 1);
}
__global__ void scan_k()
{
    if (threadIdx.x == 0) {
        int off = 0;
        for (int len = Wc_; len >= 1; --len) { g_off[len] = off; off += g_hist[len]; }
        for (int t = 0; t <= Wc_; ++t) {
            int a = 0;
            for (int l = t + 1; l <= Wc_; ++l) a += g_hist[l];
            g_act[t] = a;
        }
    }
}
__global__ void scatter_k(const int* __restrict__ clens)
{
    const int i = blockIdx.x * blockDim.x + threadIdx.x;
    if (i < NW_) {
        const int len = clens[i];
        const int s = atomicAdd(&g_off[len], 1);
        g_perm[s] = i;
        g_iperm[i] = s;
        g_slen[s] = len;
    }
}

// ---------------- fp32 -> bf16x3 split of a weight matrix (B-side: [hi|lo|hi]) --
__global__ void split_k(const float* __restrict__ src, __nv_bfloat16* __restrict__ dst,
                        int K, int total)
{
    const int i = blockIdx.x * blockDim.x + threadIdx.x;
    if (i >= total) return;
    const int n = i / K, k = i % K;
    __nv_bfloat16 hi, lo;
    bf16split(src[i], hi, lo);
    const size_t base = (size_t)n * 3 * K;
    dst[base + k] = hi; dst[base + K + k] = lo; dst[base + 2*K + k] = hi;
}

// ---------------- bf16 tensor-core GEMM: C[M,N] = A'[M,K] @ B'[N,K]^T ----------
// bf16x3-split operands. CTA tile 128x256, 8 warps (2x4) at 64x64 warp tiles,
// BK=64, 2-stage cp.async double buffer, mma.m16n8k16, fp32 accumulate.
// Requires M%128==0, N%256==0, K%64==0. act: row tiles >= act[step] exit early.
#define HS_BYTES ((size_t)2 * 384 * LDS_ * sizeof(__nv_bfloat16))   // 110592

__global__ __launch_bounds__(256)
void hgemm(const __nv_bfloat16* __restrict__ A, const __nv_bfloat16* __restrict__ Bm,
           float* __restrict__ C, int M, int N, int K,
           const int* __restrict__ act, int step)
{
    const int row0 = blockIdx.y * 128;
    if (act && row0 >= act[step]) return;
    const int col0 = blockIdx.x * 256;

    extern __shared__ __nv_bfloat16 smem_[];
    __nv_bfloat16* const sA[2] = { smem_,              smem_ + 384*LDS_ };
    __nv_bfloat16* const sB[2] = { smem_ + 128*LDS_,   smem_ + 384*LDS_ + 128*LDS_ };

    const int tid  = threadIdx.x;
    const int lane = tid & 31;
    const int wid  = tid >> 5;
    const int wm   = (wid & 1) * 64;
    const int wn   = (wid >> 1) * 64;

    const int lr = tid >> 1;          // 0..127
    const int cb = (tid & 1) * 4;     // 16B-chunk base within 64-col row

    float acc[4][8][4];
#pragma unroll
    for (int mi = 0; mi < 4; ++mi)
#pragma unroll
        for (int ni = 0; ni < 8; ++ni)
#pragma unroll
            for (int f = 0; f < 4; ++f) acc[mi][ni][f] = 0.f;

    const int KT = K >> 6;

    // prologue: stage 0
    {
        const __nv_bfloat16* Ap  = A  + (size_t)(row0 + lr) * K + cb * 8;
        const __nv_bfloat16* Bp0 = Bm + (size_t)(col0 + lr) * K + cb * 8;
        const __nv_bfloat16* Bp1 = Bm + (size_t)(col0 + 128 + lr) * K + cb * 8;
#pragma unroll
        for (int c = 0; c < 4; ++c) {
            cp16(&sA[0][lr * LDS_ + (cb + c) * 8],          Ap  + c * 8);
            cp16(&sB[0][lr * LDS_ + (cb + c) * 8],          Bp0 + c * 8);
            cp16(&sB[0][(128 + lr) * LDS_ + (cb + c) * 8],  Bp1 + c * 8);
        }
        asm volatile("cp.async.commit_group;");
    }

    for (int kt = 0; kt < KT; ++kt) {
        const int buf = kt & 1;
        if (kt + 1 < KT) {
            const int k0 = (kt + 1) << 6;
            const __nv_bfloat16* Ap  = A  + (size_t)(row0 + lr) * K + k0 + cb * 8;
            const __nv_bfloat16* Bp0 = Bm + (size_t)(col0 + lr) * K + k0 + cb * 8;
            const __nv_bfloat16* Bp1 = Bm + (size_t)(col0 + 128 + lr) * K + k0 + cb * 8;
#pragma unroll
            for (int c = 0; c < 4; ++c) {
                cp16(&sA[buf ^ 1][lr * LDS_ + (cb + c) * 8],          Ap  + c * 8);
                cp16(&sB[buf ^ 1][lr * LDS_ + (cb + c) * 8],          Bp0 + c * 8);
                cp16(&sB[buf ^ 1][(128 + lr) * LDS_ + (cb + c) * 8],  Bp1 + c * 8);
            }
            asm volatile("cp.async.commit_group;");
            asm volatile("cp.async.wait_group 1;");
        } else {
            asm volatile("cp.async.wait_group 0;");
        }
        __syncthreads();

        const __nv_bfloat16* As = sA[buf];
        const __nv_bfloat16* Bs = sB[buf];
#pragma unroll
        for (int ks = 0; ks < 4; ++ks) {
            uint32_t a[4][4], b[8][2];
#pragma unroll
            for (int mi = 0; mi < 4; ++mi) {
                uint32_t addr = (uint32_t)__cvta_generic_to_shared(
                    &As[(wm + mi*16 + (lane & 15)) * LDS_ + ks*16 + (lane >> 4) * 8]);
                asm volatile("ldmatrix.sync.aligned.m8n8.x4.shared.b16 {%0,%1,%2,%3}, [%4];"
                    : "=r"(a[mi][0]), "=r"(a[mi][1]), "=r"(a[mi][2]), "=r"(a[mi][3])
                    : "r"(addr));
            }
#pragma unroll
            for (int nq = 0; nq < 4; ++nq) {
                uint32_t r0, r1, r2, r3;
                uint32_t addr = (uint32_t)__cvta_generic_to_shared(
                    &Bs[(wn + nq*16 + (lane & 15)) * LDS_ + ks*16 + (lane >> 4) * 8]);
                asm volatile("ldmatrix.sync.aligned.m8n8.x4.shared.b16 {%0,%1,%2,%3}, [%4];"
                    : "=r"(r0), "=r"(r1), "=r"(r2), "=r"(r3) : "r"(addr));
                b[nq*2    ][0] = r0; b[nq*2    ][1] = r2;   // rows nq*16 .. +7
                b[nq*2 + 1][0] = r1; b[nq*2 + 1][1] = r3;   // rows nq*16+8 .. +15
            }
#pragma unroll
            for (int mi = 0; mi < 4; ++mi)
#pragma unroll
                for (int ni = 0; ni < 8; ++ni) {
                    asm volatile(
                        "mma.sync.aligned.m16n8k16.row.col.f32.bf16.bf16.f32 "
                        "{%0,%1,%2,%3}, {%4,%5,%6,%7}, {%8,%9}, {%0,%1,%2,%3};"
                        : "+f"(acc[mi][ni][0]), "+f"(acc[mi][ni][1]),
                          "+f"(acc[mi][ni][2]), "+f"(acc[mi][ni][3])
                        : "r"(a[mi][0]), "r"(a[mi][1]), "r"(a[mi][2]), "r"(a[mi][3]),
                          "r"(b[ni][0]), "r"(b[ni][1]));
                }
        }
        __syncthreads();
    }

#pragma unroll
    for (int mi = 0; mi < 4; ++mi)
#pragma unroll
        for (int ni = 0; ni < 8; ++ni) {
            const int r = row0 + wm + mi*16 + (lane >> 2);
            const int c = col0 + wn + ni*8 + (lane & 3) * 2;
            float2 v0 = make_float2(acc[mi][ni][0], acc[mi][ni][1]);
            float2 v1 = make_float2(acc[mi][ni][2], acc[mi][ni][3]);
            *(float2*)&C[(size_t)r * N + c]       = v0;
            *(float2*)&C[(size_t)(r + 8) * N + c] = v1;
        }
}

// ---------------- fp32 SGEMM (only for P = char_emb @ c_Wih.T, M=128) ----------
__global__ __launch_bounds__(256)
void sgemm128(const float* __restrict__ A, const float* __restrict__ Bm,
              float* __restrict__ C, int M, int N, int K)
{
    __shared__ float As[8][128];
    __shared__ float Bs[8][128];
    const int tid = threadIdx.x;
    const int tx  = tid & 15;
    const int ty  = tid >> 4;
    const int row0 = blockIdx.y * 128;
    const int col0 = blockIdx.x * 128;
    const int lr = tid >> 1;
    const int lk = (tid & 1) * 4;

    const float* Ap = A  + (size_t)(row0 + lr) * K + lk;
    const float* Bp = Bm + (size_t)(col0 + lr) * K + lk;

    float acc[8][8];
#pragma unroll
    for (int i = 0; i < 8; ++i)
#pragma unroll
        for (int j = 0; j < 8; ++j) acc[i][j] = 0.f;

    {
        float4 a = *(const float4*)Ap;
        float4 b = *(const float4*)Bp;
        As[lk+0][lr] = a.x; As[lk+1][lr] = a.y; As[lk+2][lr] = a.z; As[lk+3][lr] = a.w;
        Bs[lk+0][lr] = b.x; Bs[lk+1][lr] = b.y; Bs[lk+2][lr] = b.z; Bs[lk+3][lr] = b.w;
    }
    __syncthreads();

    int k0 = 0;
    while (true) {
        const int kn = k0 + 8;
        const bool more = kn < K;
        float4 an, bn;
        if (more) { an = *(const float4*)(Ap + kn); bn = *(const float4*)(Bp + kn); }
#pragma unroll
        for (int k = 0; k < 8; ++k) {
            float4 a0 = *(const float4*)&As[k][ty*8];
            float4 a1 = *(const float4*)&As[k][ty*8+4];
            float4 b0 = *(const float4*)&Bs[k][tx*8];
            float4 b1 = *(const float4*)&Bs[k][tx*8+4];
            float av[8] = {a0.x,a0.y,a0.z,a0.w,a1.x,a1.y,a1.z,a1.w};
            float bv[8] = {b0.x,b0.y,b0.z,b0.w,b1.x,b1.y,b1.z,b1.w};
#pragma unroll
            for (int i = 0; i < 8; ++i)
#pragma unroll
                for (int j = 0; j < 8; ++j)
                    acc[i][j] = fmaf(av[i], bv[j], acc[i][j]);
        }
        if (!more) break;
        __syncthreads();
        As[lk+0][lr] = an.x; As[lk+1][lr] = an.y; As[lk+2][lr] = an.z; As[lk+3][lr] = an.w;
        Bs[lk+0][lr] = bn.x; Bs[lk+1][lr] = bn.y; Bs[lk+2][lr] = bn.z; Bs[lk+3][lr] = bn.w;
        __syncthreads();
        k0 = kn;
    }

#pragma unroll
    for (int i = 0; i < 8; ++i) {
        const int r = row0 + ty*8 + i;
        float4 o0, o1;
        o0.x = acc[i][0]; o0.y = acc[i][1]; o0.z = acc[i][2]; o0.w = acc[i][3];
        o1.x = acc[i][4]; o1.y = acc[i][5]; o1.z = acc[i][6]; o1.w = acc[i][7];
        *(float4*)(C + (size_t)r*N + col0 + tx*8)     = o0;
        *(float4*)(C + (size_t)r*N + col0 + tx*8 + 4) = o1;
    }
}

// ---------------- persistent word BiLSTM layer ----------------
__global__ __launch_bounds__(256)
void word_layer_persist(const float* __restrict__ Whh0, const float* __restrict__ Whh1,
                        const float* __restrict__ XGf, const float* __restrict__ XGb,
                        const int* __restrict__ lens, const float* __restrict__ bias,
                        float* __restrict__ Hout, __nv_bfloat16* __restrict__ Houts)
{
    __shared__ float hs[64][68];
    __shared__ float ws[32][68];

    const int tid = threadIdx.x;
    const int jj  = tid & 7;
    const int bb  = tid >> 3;             // 0..31
    const int dir = blockIdx.x >> 6;
    const int jt  = (blockIdx.x & 63) << 3;
    const int j   = jt + jj;

    const float* W  = dir ? Whh1 : Whh0;
    const float* XG = dir ? XGb : XGf;
    const float* bv = bias + (size_t)dir * G_;
    float bg[4];
#pragma unroll
    for (int g = 0; g < 4; ++g) bg[g] = bv[g * H_ + j];

    const int len0 = lens[bb];
    const int len1 = lens[bb + 32];

    float hreg0 = 0.f, creg0 = 0.f;
    float hreg1 = 0.f, creg1 = 0.f;

    for (int t = 0; t < S_; ++t) {
        const float* hcur = g_hpp + (size_t)(((t    ) & 1) * 2 + dir) * (B_*H_);
        float*       hnxt = g_hpp + (size_t)(((t + 1) & 1) * 2 + dir) * (B_*H_);

        float acc[2][4];
#pragma unroll
        for (int b2 = 0; b2 < 2; ++b2)
#pragma unroll
            for (int g = 0; g < 4; ++g) acc[b2][g] = 0.f;

        for (int k0 = 0; k0 < H_; k0 += 64) {
#pragma unroll
            for (int i = 0; i < 4; ++i) {
                const int idx = tid + i * 256;
                const int r = idx >> 4, c = idx & 15;
                float4 v = __ldcg((const float4*)(hcur + (size_t)r * H_ + k0 + c * 4));
                *(float4*)&hs[r][c * 4] = v;
            }
#pragma unroll
            for (int i = 0; i < 2; ++i) {
                const int idx = tid + i * 256;
                const int w = idx >> 4, c = idx & 15;
                const int g = w >> 3, jl = w & 7;
                float4 v = *(const float4*)(W + (size_t)(g * H_ + jt + jl) * H_ + k0 + c * 4);
                *(float4*)&ws[w][c * 4] = v;
            }
            __syncthreads();
#pragma unroll
            for (int k4 = 0; k4 < 16; ++k4) {
                float4 a0 = *(const float4*)&hs[bb][k4 * 4];
                float4 a1 = *(const float4*)&hs[bb + 32][k4 * 4];
#pragma unroll
                for (int g = 0; g < 4; ++g) {
                    float4 w4 = *(const float4*)&ws[g * 8 + jj][k4 * 4];
                    acc[0][g] = fmaf(a0.x, w4.x, acc[0][g]);
                    acc[0][g] = fmaf(a0.y, w4.y, acc[0][g]);
                    acc[0][g] = fmaf(a0.z, w4.z, acc[0][g]);
                    acc[0][g] = fmaf(a0.w, w4.w, acc[0][g]);
                    acc[1][g] = fmaf(a1.x, w4.x, acc[1][g]);
                    acc[1][g] = fmaf(a1.y, w4.y, acc[1][g]);
                    acc[1][g] = fmaf(a1.z, w4.z, acc[1][g]);
                    acc[1][g] = fmaf(a1.w, w4.w, acc[1][g]);
                }
            }
            __syncthreads();
        }

#pragma unroll
        for (int b2 = 0; b2 < 2; ++b2) {
            const int b = bb + b2 * 32;
            const int len = b2 ? len1 : len0;
            const bool valid = t < len;
            const int src = (dir == 0) ? t : (valid ? (len - 1 - t) : t);
            const float* xg = XG + (size_t)(b * S_ + src) * G_ + jt + jj;
            float zi = acc[b2][0] + xg[0]      + bg[0];
            float zf = acc[b2][1] + xg[H_]     + bg[1];
            float zg = acc[b2][2] + xg[2*H_]   + bg[2];
            float zo = acc[b2][3] + xg[3*H_]   + bg[3];
            float c_old = b2 ? creg1 : creg0;
            float cn = sigf(zf) * c_old + sigf(zi) * tanhf(zg);
            float hn = sigf(zo) * tanhf(cn);
            float h_old = b2 ? hreg1 : hreg0;
            float h_out = valid ? hn : h_old;
            float c_out = valid ? cn : c_old;
            if (b2) { hreg1 = h_out; creg1 = c_out; }
            else    { hreg0 = h_out; creg0 = c_out; }
            __stcg(hnxt + (size_t)b * H_ + j, h_out);
            if (dir == 0) {
                const float v = valid ? hn : 0.f;
                Hout[(size_t)(b * S_ + t) * CH_ + j] = v;
                if (Houts) {
                    __nv_bfloat16 hi, lo; bf16split(v, hi, lo);
                    const size_t base = (size_t)(b * S_ + t) * (3*CH_) + j;
                    Houts[base] = hi; Houts[base + CH_] = hi; Houts[base + 2*CH_] = lo;
                }
            } else if (valid) {
                Hout[(size_t)(b * S_ + src) * CH_ + H_ + j] = hn;
                if (Houts) {
                    __nv_bfloat16 hi, lo; bf16split(hn, hi, lo);
                    const size_t base = (size_t)(b * S_ + src) * (3*CH_) + H_ + j;
                    Houts[base] = hi; Houts[base + CH_] = hi; Houts[base + 2*CH_] = lo;
                }
            }
        }

        if (t < S_ - 1) {
            __syncthreads();
            if (tid == 0) {
                __threadfence();
                atomicAdd(&g_bar, 1u);
                const unsigned tgt = (unsigned)(t + 1) * (unsigned)NBLK_;
                volatile unsigned* p = &g_bar;
                while (*p < tgt) __nanosleep(64);
            }
            __syncthreads();
        }
    }
}

// ---------------- word embedding gather (writes split directly) ----------------
__global__ void embed_words(const int* __restrict__ words, const float* __restrict__ emb)
{
    const int m = blockIdx.x;
    const int e = threadIdx.x;
    const float x = emb[(size_t)words[m] * E_ + e];
    __nv_bfloat16 hi, lo; bf16split(x, hi, lo);
    const size_t base = (size_t)m * (3*E_) + e;
    g_Xembs[base] = hi; g_Xembs[base + E_] = hi; g_Xembs[base + 2*E_] = lo;
}

// ---------------- char LSTM gate step (sorted slots; writes split h) ----------
__global__ void char_gate(const int* __restrict__ chars,
                          const float* __restrict__ cbias, int t, int useZ)
{
    const int n = blockIdx.y;                  // slot
    if (t >= g_slen[n]) return;                // frozen slots are a suffix
    const int j = blockIdx.x * blockDim.x + threadIdx.x;   // 0..1023
    const int tok = chars[g_perm[n] * Wc_ + t];
    const float* p = g_P + (size_t)tok * CG_;
    float zi = p[j]        + cbias[j];
    float zf = p[CH_+j]    + cbias[CH_+j];
    float zg = p[2*CH_+j]  + cbias[2*CH_+j];
    float zo = p[3*CH_+j]  + cbias[3*CH_+j];
    if (useZ) {
        const float* Z = g_Zc + (size_t)n * CG_;
        zi += Z[j]; zf += Z[CH_+j]; zg += Z[2*CH_+j]; zo += Z[3*CH_+j];
    }
    float c  = g_cc[(size_t)n*CH_+j];
    float cn = sigf(zf)*c + sigf(zi)*tanhf(zg);
    float hn = sigf(zo)*tanhf(cn);
    g_cc[(size_t)n*CH_+j] = cn;
    g_ch[(size_t)n*CH_+j] = hn;
    __nv_bfloat16 hi, lo; bf16split(hn, hi, lo);
    const size_t base = (size_t)n * (3*CH_) + j;
    g_hs[base] = hi; g_hs[base + CH_] = hi; g_hs[base + 2*CH_] = lo;
}

// ---------------- final head ----------------
__global__ __launch_bounds__(256)
void final_linear(const int* __restrict__ wnum, const float* __restrict__ W,
                  const float* __restrict__ bias, float* __restrict__ out)
{
    const int row = blockIdx.x;         // 0..8191
    const int b = row >> 7;
    const int s = row & (S_ - 1);
    const bool valid = s < wnum[b];
    const int slot = g_iperm[row];
    __shared__ float v[CH_];
    __shared__ float sred[8*NC_];
    const int tid = threadIdx.x;
    for (int j = tid; j < CH_; j += 256) {
        float x = g_H1[(size_t)row*CH_ + j];
        if (valid) x += g_ch[(size_t)slot*CH_ + j];
        v[j] = x;
    }
    __syncthreads();
    float acc[NC_];
#pragma unroll
    for (int c2 = 0; c2 < NC_; ++c2) acc[c2] = 0.f;
    for (int j = tid; j < CH_; j += 256) {
        float x = v[j];
#pragma unroll
        for (int c2 = 0; c2 < NC_; ++c2)
            acc[c2] = fmaf(x, W[c2*CH_ + j], acc[c2]);
    }
#pragma unroll
    for (int c2 = 0; c2 < NC_; ++c2)
#pragma unroll
        for (int off = 16; off > 0; off >>= 1)
            acc[c2] += __shfl_down_sync(0xffffffffu, acc[c2], off);
    const int lane = tid & 31, w = tid >> 5;
    if (lane == 0)
#pragma unroll
        for (int c2 = 0; c2 < NC_; ++c2) sred[w*NC_ + c2] = acc[c2];
    __syncthreads();
    if (tid < NC_) {
        float sum = bias[tid];
#pragma unroll
        for (int w2 = 0; w2 < 8; ++w2) sum += sred[w2*NC_ + tid];
        out[(size_t)row*NC_ + tid] = sum;
    }
}

// ================================================================================
extern "C" void kernel_launch(void* const* d_in, const int* in_sizes, int n_in,
                              void* d_out, int out_size)
{
    (void)in_sizes; (void)n_in; (void)out_size;
    const int*   words     = (const int*)  d_in[0];
    const int*   words_num = (const int*)  d_in[1];
    const int*   chars     = (const int*)  d_in[2];
    const int*   char_lens = (const int*)  d_in[3];
    const float* word_emb  = (const float*)d_in[4];
    const float* char_emb  = (const float*)d_in[5];
    const float* l0_Wih    = (const float*)d_in[6];
    const float* l0_Whh    = (const float*)d_in[7];
    const float* l0_b      = (const float*)d_in[8];
    const float* l1_Wih    = (const float*)d_in[9];
    const float* l1_Whh    = (const float*)d_in[10];
    const float* l1_b      = (const float*)d_in[11];
    const float* c_Wih     = (const float*)d_in[12];
    const float* c_Whh     = (const float*)d_in[13];
    const float* c_b       = (const float*)d_in[14];
    const float* lin_W     = (const float*)d_in[15];
    const float* lin_b     = (const float*)d_in[16];
    float* out = (float*)d_out;

    float *XGf, *XGb, *H0, *H1, *hpp, *P, *Zc, *ch, *cc;
    __nv_bfloat16 *Xembs, *H0s, *hsb, *Wc2, *Wih0s, *Wih1s;
    unsigned* bar;
    int *hist, *act;
    cudaGetSymbolAddress((void**)&Xembs, g_Xembs);
    cudaGetSymbolAddress((void**)&XGf,  g_XGf);
    cudaGetSymbolAddress((void**)&XGb,  g_XGb);
    cudaGetSymbolAddress((void**)&H0,   g_H0);
    cudaGetSymbolAddress((void**)&H0s,  g_H0s);
    cudaGetSymbolAddress((void**)&H1,   g_H1);
    cudaGetSymbolAddress((void**)&hpp,  g_hpp);
    cudaGetSymbolAddress((void**)&bar,  g_bar);
    cudaGetSymbolAddress((void**)&P,    g_P);
    cudaGetSymbolAddress((void**)&Zc,   g_Zc);
    cudaGetSymbolAddress((void**)&ch,   g_ch);
    cudaGetSymbolAddress((void**)&hsb,  g_hs);
    cudaGetSymbolAddress((void**)&cc,   g_cc);
    cudaGetSymbolAddress((void**)&Wc2,  g_Wc2);
    cudaGetSymbolAddress((void**)&Wih0s,g_Wih0s);
    cudaGetSymbolAddress((void**)&Wih1s,g_Wih1s);
    cudaGetSymbolAddress((void**)&hist, g_hist);
    cudaGetSymbolAddress((void**)&act,  g_act);

    cudaFuncSetAttribute(hgemm, cudaFuncAttributeMaxDynamicSharedMemorySize, (int)HS_BYTES);

    // ---- char length sort ----
    cudaMemsetAsync(hist, 0, (Wc_ + 1) * sizeof(int), 0);
    hist_k<<<NW_/256, 256>>>(char_lens);
    scan_k<<<1, 32>>>();
    scatter_k<<<NW_/256, 256>>>(char_lens);

    // ---- weight splits (bf16x3, B-side layout [hi|lo|hi]) ----
    split_k<<<(G_*E_ + 255)/256, 256>>>(l0_Wih,                     Wih0s,                     E_,  G_*E_);
    split_k<<<(G_*E_ + 255)/256, 256>>>(l0_Wih + (size_t)G_*E_,     Wih0s + (size_t)G_*3*E_,   E_,  G_*E_);
    split_k<<<(G_*CH_ + 255)/256, 256>>>(l1_Wih,                    Wih1s,                     CH_, G_*CH_);
    split_k<<<(G_*CH_ + 255)/256, 256>>>(l1_Wih + (size_t)G_*CH_,   Wih1s + (size_t)G_*3*CH_,  CH_, G_*CH_);
    split_k<<<(CG_*CH_ + 255)/256, 256>>>(c_Whh,                    Wc2,                       CH_, CG_*CH_);

    // ---- word embeddings (split) ----
    embed_words<<<NW_, E_>>>(words, word_emb);

    // ---- word BiLSTM layer 0 (K'=768) ----
    {
        const float* Whh0 = l0_Whh;
        const float* Whh1 = l0_Whh + (size_t)G_ * H_;
        hgemm<<<dim3(G_/256, NW_/128), 256, HS_BYTES>>>(Xembs, Wih0s,                    XGf, NW_, G_, 3*E_, nullptr, 0);
        hgemm<<<dim3(G_/256, NW_/128), 256, HS_BYTES>>>(Xembs, Wih0s + (size_t)G_*3*E_,  XGb, NW_, G_, 3*E_, nullptr, 0);
        cudaMemsetAsync(H0,  0, (size_t)NW_*CH_*sizeof(float), 0);
        cudaMemsetAsync(H0s, 0, (size_t)NW_*3*CH_*sizeof(__nv_bfloat16), 0);
        cudaMemsetAsync(hpp, 0, (size_t)2*2*B_*H_*sizeof(float), 0);
        cudaMemsetAsync(bar, 0, sizeof(unsigned), 0);
        word_layer_persist<<<NBLK_, 256>>>(Whh0, Whh1, XGf, XGb, words_num, l0_b, H0, H0s);
    }

    // ---- word BiLSTM layer 1 (K'=3072) ----
    {
        const float* Whh0 = l1_Whh;
        const float* Whh1 = l1_Whh + (size_t)G_ * H_;
        hgemm<<<dim3(G_/256, NW_/128), 256, HS_BYTES>>>(H0s, Wih1s,                     XGf, NW_, G_, 3*CH_, nullptr, 0);
        hgemm<<<dim3(G_/256, NW_/128), 256, HS_BYTES>>>(H0s, Wih1s + (size_t)G_*3*CH_,  XGb, NW_, G_, 3*CH_, nullptr, 0);
        cudaMemsetAsync(H1,  0, (size_t)NW_*CH_*sizeof(float), 0);
        cudaMemsetAsync(hpp, 0, (size_t)2*2*B_*H_*sizeof(float), 0);
        cudaMemsetAsync(bar, 0, sizeof(unsigned), 0);
        word_layer_persist<<<NBLK_, 256>>>(Whh0, Whh1, XGf, XGb, words_num, l1_b, H1, nullptr);
    }

    // ---- char LSTM (sorted by length desc, bf16x3 tensor-core recurrence) ----
    sgemm128<<<dim3(CG_/128, 1), 256>>>(char_emb, c_Wih, P, 128, CG_, E_);
    cudaMemsetAsync(ch,  0, (size_t)NW_*CH_*sizeof(float), 0);
    cudaMemsetAsync(cc,  0, (size_t)NW_*CH_*sizeof(float), 0);
    cudaMemsetAsync(hsb, 0, (size_t)NW_*3*CH_*sizeof(__nv_bfloat16), 0);
    for (int t = 0; t < Wc_; ++t) {
        if (t > 0)
            hgemm<<<dim3(CG_/256, NW_/128), 256, HS_BYTES>>>(hsb, Wc2, Zc, NW_, CG_, 3*CH_, act, t);
        char_gate<<<dim3(CH_/256, NW_), 256>>>(chars, c_b, t, t > 0);
    }

    // ---- head ----
    final_linear<<<NW_, 256>>>(words_num, lin_W, lin_b, out);
}

// round 8
// speedup vs baseline: 1.1264x; 1.1264x over previous
#include <cuda_runtime.h>
#include <cuda_bf16.h>
#include <cstdint>
#include <cstddef>

// Problem constants
#define B_   64
#define S_   128
#define Wc_  16
#define E_   256
#define H_   512
#define NC_  20
#define NW_  (B_*S_)        // 8192 words total
#define G_   (4*H_)         // 2048 word-LSTM gate width
#define CH_  (2*H_)         // 1024 char-LSTM hidden
#define CG_  (4*CH_)        // 4096 char-LSTM gate width

#define NBLK_ 128           // persistent word-layer blocks
#define LDS_  72            // hgemm smem halfword stride (64 + 8 pad)
#define HS_BYTES ((size_t)4 * 128 * LDS_ * sizeof(__nv_bfloat16))   // 73728

// ---------------- scratch (static device globals; no allocation) ----------------
__device__ __nv_bfloat16 g_Xembs[(size_t)NW_*3*E_];    // split word emb   [8192,768]
__device__ float g_XGf [(size_t)NW_*G_];               // fwd x-gates      [8192,2048]
__device__ float g_XGb [(size_t)NW_*G_];               // bwd x-gates      [8192,2048]
__device__ float g_H0  [(size_t)NW_*CH_];              // layer0 out fp32
__device__ __nv_bfloat16 g_H0s[(size_t)NW_*3*CH_];     // layer0 out split [8192,3072]
__device__ float g_H1  [(size_t)NW_*CH_];              // layer1 output    [8192,1024]
__device__ float g_hpp[(size_t)2*2*B_*H_];             // h ping-pong
__device__ unsigned g_bar;                             // grid barrier counter
__device__ float g_P  [(size_t)128*CG_];               // char_emb @ c_Wih.T (gate-major)
__device__ float g_Pp [(size_t)128*CG_];               // P interleaved j*4+g, + bias
__device__ float g_ch [(size_t)NW_*CH_];               // char h fp32 (sorted slots)
__device__ float g_cc [(size_t)NW_*CH_];               // char c state (sorted)
__device__ __nv_bfloat16 g_hsA[(size_t)NW_*3*CH_];     // char h split buf A
__device__ __nv_bfloat16 g_hsB[(size_t)NW_*3*CH_];     // char h split buf B
__device__ __nv_bfloat16 g_Wc2   [(size_t)CG_*3*CH_];  // c_Whh split, rows j*4+g
__device__ __nv_bfloat16 g_Wih0s [(size_t)2*G_*3*E_];  // l0_Wih split [2][2048,768]
__device__ __nv_bfloat16 g_Wih1s [(size_t)2*G_*3*CH_]; // l1_Wih split [2][2048,3072]

// ---- length-sort bookkeeping ----
__device__ int g_hist[Wc_ + 1];
__device__ int g_off [Wc_ + 1];
__device__ int g_act [Wc_ + 1];
__device__ int g_perm [NW_];
__device__ int g_iperm[NW_];
__device__ int g_slen [NW_];

__device__ __forceinline__ float sigf(float x) { return 1.f / (1.f + __expf(-x)); }

__device__ __forceinline__ void bf16split(float x, __nv_bfloat16& hi, __nv_bfloat16& lo)
{
    hi = __float2bfloat16(x);
    lo = __float2bfloat16(x - __bfloat162float(hi));
}

__device__ __forceinline__ void cp16(void* dst, const void* src)
{
    uint32_t d = (uint32_t)__cvta_generic_to_shared(dst);
    asm volatile("cp.async.cg.shared.global [%0], [%1], 16;" :: "r"(d), "l"(src));
}

// ---------------- counting sort by char_lens (descending) ----------------
__global__ void hist_k(const int* __restrict__ clens)
{
    const int i = blockIdx.x * blockDim.x + threadIdx.x;
    if (i < NW_) atomicAdd(&g_hist[clens[i]], 1);
}
__global__ void scan_k()
{
    if (threadIdx.x == 0) {
        int off = 0;
        for (int len = Wc_; len >= 1; --len) { g_off[len] = off; off += g_hist[len]; }
        for (int t = 0; t <= Wc_; ++t) {
            int a = 0;
            for (int l = t + 1; l <= Wc_; ++l) a += g_hist[l];
            g_act[t] = a;
        }
    }
}
__global__ void scatter_k(const int* __restrict__ clens)
{
    const int i = blockIdx.x * blockDim.x + threadIdx.x;
    if (i < NW_) {
        const int len = clens[i];
        const int s = atomicAdd(&g_off[len], 1);
        g_perm[s] = i;
        g_iperm[i] = s;
        g_slen[s] = len;
    }
}

// ---------------- fp32 -> bf16x3 split (B-side layout [hi|lo|hi]) ----------------
__global__ void split_k(const float* __restrict__ src, __nv_bfloat16* __restrict__ dst,
                        int K, int total)
{
    const int i = blockIdx.x * blockDim.x + threadIdx.x;
    if (i >= total) return;
    const int n = i / K, k = i % K;
    __nv_bfloat16 hi, lo;
    bf16split(src[i], hi, lo);
    const size_t base = (size_t)n * 3 * K;
    dst[base + k] = hi; dst[base + K + k] = lo; dst[base + 2*K + k] = hi;
}

// split of c_Whh with gate-interleaved row remap: src row r = g*CH+j -> dst row j*4+g
__global__ void split_remap_k(const float* __restrict__ src, __nv_bfloat16* __restrict__ dst)
{
    const int i = blockIdx.x * blockDim.x + threadIdx.x;
    if (i >= CG_ * CH_) return;
    const int r = i / CH_, k = i % CH_;
    const int g = r / CH_, j = r % CH_;
    const int outr = j * 4 + g;
    __nv_bfloat16 hi, lo;
    bf16split(src[i], hi, lo);
    const size_t base = (size_t)outr * 3 * CH_;
    dst[base + k] = hi; dst[base + CH_ + k] = lo; dst[base + 2*CH_ + k] = hi;
}

// P reorder to interleaved + fold bias: Pp[tok][j*4+g] = P[tok][g*CH+j] + c_b[g*CH+j]
__global__ void reorderP_k(const float* __restrict__ cbias)
{
    const int i = blockIdx.x * blockDim.x + threadIdx.x;
    if (i >= 128 * CG_) return;
    const int tok = i / CG_, col = i % CG_;
    const int j = col >> 2, g = col & 3;
    const int src = g * CH_ + j;
    g_Pp[i] = g_P[(size_t)tok * CG_ + src] + cbias[src];
}

// ---------------- bf16 tensor-core GEMM: C[M,N] = A'[M,K] @ B'[N,K]^T ----------
// R5 config: 128x128 tile, 8 warps (2x4), warp tile 64x32, BK=64,
// 2-stage cp.async double buffer, mma.m16n8k16, fp32 accumulate. K%64==0.
__global__ __launch_bounds__(256)
void hgemm(const __nv_bfloat16* __restrict__ A, const __nv_bfloat16* __restrict__ Bm,
           float* __restrict__ C, int M, int N, int K)
{
    const int row0 = blockIdx.y * 128;
    const int col0 = blockIdx.x * 128;

    extern __shared__ __nv_bfloat16 smem_[];
    __nv_bfloat16* const sA[2] = { smem_,                smem_ + 2*128*LDS_ };
    __nv_bfloat16* const sB[2] = { smem_ + 128*LDS_,     smem_ + 3*128*LDS_ };

    const int tid  = threadIdx.x;
    const int lane = tid & 31;
    const int wid  = tid >> 5;
    const int wm   = (wid & 1) * 64;
    const int wn   = (wid >> 1) * 32;

    const int lr = tid >> 1;
    const int cb = (tid & 1) * 4;

    float acc[4][4][4];
#pragma unroll
    for (int mi = 0; mi < 4; ++mi)
#pragma unroll
        for (int ni = 0; ni < 4; ++ni)
#pragma unroll
            for (int f = 0; f < 4; ++f) acc[mi][ni][f] = 0.f;

    const int KT = K >> 6;

    {
        const __nv_bfloat16* Ap = A  + (size_t)(row0 + lr) * K + cb * 8;
        const __nv_bfloat16* Bp = Bm + (size_t)(col0 + lr) * K + cb * 8;
#pragma unroll
        for (int c = 0; c < 4; ++c) {
            cp16(&sA[0][lr * LDS_ + (cb + c) * 8], Ap + c * 8);
            cp16(&sB[0][lr * LDS_ + (cb + c) * 8], Bp + c * 8);
        }
        asm volatile("cp.async.commit_group;");
    }

    for (int kt = 0; kt < KT; ++kt) {
        const int buf = kt & 1;
        if (kt + 1 < KT) {
            const int k0 = (kt + 1) << 6;
            const __nv_bfloat16* Ap = A  + (size_t)(row0 + lr) * K + k0 + cb * 8;
            const __nv_bfloat16* Bp = Bm + (size_t)(col0 + lr) * K + k0 + cb * 8;
#pragma unroll
            for (int c = 0; c < 4; ++c) {
                cp16(&sA[buf ^ 1][lr * LDS_ + (cb + c) * 8], Ap + c * 8);
                cp16(&sB[buf ^ 1][lr * LDS_ + (cb + c) * 8], Bp + c * 8);
            }
            asm volatile("cp.async.commit_group;");
            asm volatile("cp.async.wait_group 1;");
        } else {
            asm volatile("cp.async.wait_group 0;");
        }
        __syncthreads();

        const __nv_bfloat16* As = sA[buf];
        const __nv_bfloat16* Bs = sB[buf];
#pragma unroll
        for (int ks = 0; ks < 4; ++ks) {
            uint32_t a[4][4], b[4][2];
#pragma unroll
            for (int mi = 0; mi < 4; ++mi) {
                uint32_t addr = (uint32_t)__cvta_generic_to_shared(
                    &As[(wm + mi*16 + (lane & 15)) * LDS_ + ks*16 + (lane >> 4) * 8]);
                asm volatile("ldmatrix.sync.aligned.m8n8.x4.shared.b16 {%0,%1,%2,%3}, [%4];"
                    : "=r"(a[mi][0]), "=r"(a[mi][1]), "=r"(a[mi][2]), "=r"(a[mi][3])
                    : "r"(addr));
            }
#pragma unroll
            for (int ni = 0; ni < 4; ++ni) {
                uint32_t addr = (uint32_t)__cvta_generic_to_shared(
                    &Bs[(wn + ni*8 + (lane & 7)) * LDS_ + ks*16 + ((lane >> 3) & 1) * 8]);
                asm volatile("ldmatrix.sync.aligned.m8n8.x2.shared.b16 {%0,%1}, [%2];"
                    : "=r"(b[ni][0]), "=r"(b[ni][1]) : "r"(addr));
            }
#pragma unroll
            for (int mi = 0; mi < 4; ++mi)
#pragma unroll
                for (int ni = 0; ni < 4; ++ni) {
                    asm volatile(
                        "mma.sync.aligned.m16n8k16.row.col.f32.bf16.bf16.f32 "
                        "{%0,%1,%2,%3}, {%4,%5,%6,%7}, {%8,%9}, {%0,%1,%2,%3};"
                        : "+f"(acc[mi][ni][0]), "+f"(acc[mi][ni][1]),
                          "+f"(acc[mi][ni][2]), "+f"(acc[mi][ni][3])
                        : "r"(a[mi][0]), "r"(a[mi][1]), "r"(a[mi][2]), "r"(a[mi][3]),
                          "r"(b[ni][0]), "r"(b[ni][1]));
                }
        }
        __syncthreads();
    }

#pragma unroll
    for (int mi = 0; mi < 4; ++mi)
#pragma unroll
        for (int ni = 0; ni < 4; ++ni) {
            const int r = row0 + wm + mi*16 + (lane >> 2);
            const int c = col0 + wn + ni*8 + (lane & 3) * 2;
            float2 v0 = make_float2(acc[mi][ni][0], acc[mi][ni][1]);
            float2 v1 = make_float2(acc[mi][ni][2], acc[mi][ni][3]);
            *(float2*)&C[(size_t)r * N + c]       = v0;
            *(float2*)&C[(size_t)(r + 8) * N + c] = v1;
        }
}

// ========== fused char-LSTM GEMM step: Z = h_{t-1} @ Wc2^T, then cell update ====
// B (g_Wc2) rows are gate-interleaved (j*4+g) so each 128-col tile holds complete
// gate quadruples for 32 j. Epilogue stages fp32 tile in smem, applies LSTM cell,
// writes cc/ch (fp32) and split h into hsW. Active rows: n < g_act[t].
__global__ __launch_bounds__(256)
void hgemm_lstm(const __nv_bfloat16* __restrict__ A,   // hsRead [8192,3072]
                const __nv_bfloat16* __restrict__ Bm,  // g_Wc2 [4096,3072]
                __nv_bfloat16* __restrict__ hsW,       // hsWrite
                const int* __restrict__ chars, int t)
{
    const int act_t = g_act[t];
    const int row0 = blockIdx.y * 128;
    if (row0 >= act_t) return;
    const int col0 = blockIdx.x * 128;
    const int K = 3 * CH_;

    extern __shared__ __nv_bfloat16 smem_[];
    __nv_bfloat16* const sA[2] = { smem_,                smem_ + 2*128*LDS_ };
    __nv_bfloat16* const sB[2] = { smem_ + 128*LDS_,     smem_ + 3*128*LDS_ };

    const int tid  = threadIdx.x;
    const int lane = tid & 31;
    const int wid  = tid >> 5;
    const int wm   = (wid & 1) * 64;
    const int wn   = (wid >> 1) * 32;

    const int lr = tid >> 1;
    const int cb = (tid & 1) * 4;

    float acc[4][4][4];
#pragma unroll
    for (int mi = 0; mi < 4; ++mi)
#pragma unroll
        for (int ni = 0; ni < 4; ++ni)
#pragma unroll
            for (int f = 0; f < 4; ++f) acc[mi][ni][f] = 0.f;

    const int KT = K >> 6;   // 48

    {
        const __nv_bfloat16* Ap = A  + (size_t)(row0 + lr) * K + cb * 8;
        const __nv_bfloat16* Bp = Bm + (size_t)(col0 + lr) * K + cb * 8;
#pragma unroll
        for (int c = 0; c < 4; ++c) {
            cp16(&sA[0][lr * LDS_ + (cb + c) * 8], Ap + c * 8);
            cp16(&sB[0][lr * LDS_ + (cb + c) * 8], Bp + c * 8);
        }
        asm volatile("cp.async.commit_group;");
    }

    for (int kt = 0; kt < KT; ++kt) {
        const int buf = kt & 1;
        if (kt + 1 < KT) {
            const int k0 = (kt + 1) << 6;
            const __nv_bfloat16* Ap = A  + (size_t)(row0 + lr) * K + k0 + cb * 8;
            const __nv_bfloat16* Bp = Bm + (size_t)(col0 + lr) * K + k0 + cb * 8;
#pragma unroll
            for (int c = 0; c < 4; ++c) {
                cp16(&sA[buf ^ 1][lr * LDS_ + (cb + c) * 8], Ap + c * 8);
                cp16(&sB[buf ^ 1][lr * LDS_ + (cb + c) * 8], Bp + c * 8);
            }
            asm volatile("cp.async.commit_group;");
            asm volatile("cp.async.wait_group 1;");
        } else {
            asm volatile("cp.async.wait_group 0;");
        }
        __syncthreads();

        const __nv_bfloat16* As = sA[buf];
        const __nv_bfloat16* Bs = sB[buf];
#pragma unroll
        for (int ks = 0; ks < 4; ++ks) {
            uint32_t a[4][4], b[4][2];
#pragma unroll
            for (int mi = 0; mi < 4; ++mi) {
                uint32_t addr = (uint32_t)__cvta_generic_to_shared(
                    &As[(wm + mi*16 + (lane & 15)) * LDS_ + ks*16 + (lane >> 4) * 8]);
                asm volatile("ldmatrix.sync.aligned.m8n8.x4.shared.b16 {%0,%1,%2,%3}, [%4];"
                    : "=r"(a[mi][0]), "=r"(a[mi][1]), "=r"(a[mi][2]), "=r"(a[mi][3])
                    : "r"(addr));
            }
#pragma unroll
            for (int ni = 0; ni < 4; ++ni) {
                uint32_t addr = (uint32_t)__cvta_generic_to_shared(
                    &Bs[(wn + ni*8 + (lane & 7)) * LDS_ + ks*16 + ((lane >> 3) & 1) * 8]);
                asm volatile("ldmatrix.sync.aligned.m8n8.x2.shared.b16 {%0,%1}, [%2];"
                    : "=r"(b[ni][0]), "=r"(b[ni][1]) : "r"(addr));
            }
#pragma unroll
            for (int mi = 0; mi < 4; ++mi)
#pragma unroll
                for (int ni = 0; ni < 4; ++ni) {
                    asm volatile(
                        "mma.sync.aligned.m16n8k16.row.col.f32.bf16.bf16.f32 "
                        "{%0,%1,%2,%3}, {%4,%5,%6,%7}, {%8,%9}, {%0,%1,%2,%3};"
                        : "+f"(acc[mi][ni][0]), "+f"(acc[mi][ni][1]),
                          "+f"(acc[mi][ni][2]), "+f"(acc[mi][ni][3])
                        : "r"(a[mi][0]), "r"(a[mi][1]), "r"(a[mi][2]), "r"(a[mi][3]),
                          "r"(b[ni][0]), "r"(b[ni][1]));
                }
        }
        __syncthreads();
    }

    // ---- fused LSTM cell epilogue ----
    float* Sg = (float*)smem_;          // 128 x 132 fp32 = 67584 B
#pragma unroll
    for (int mi = 0; mi < 4; ++mi)
#pragma unroll
        for (int ni = 0; ni < 4; ++ni) {
            const int r = wm + mi*16 + (lane >> 2);
            const int c = wn + ni*8 + (lane & 3) * 2;
            Sg[r * 132 + c]           = acc[mi][ni][0];
            Sg[r * 132 + c + 1]       = acc[mi][ni][1];
            Sg[(r + 8) * 132 + c]     = acc[mi][ni][2];
            Sg[(r + 8) * 132 + c + 1] = acc[mi][ni][3];
        }
    __syncthreads();

    const int jb = col0 >> 2;           // 32 j per tile
#pragma unroll
    for (int q = 0; q < 16; ++q) {
        const int cid = tid + q * 256;
        const int nl = cid >> 5, jl = cid & 31;
        const int n = row0 + nl;
        if (n >= act_t) continue;
        const int j = jb + jl;
        float4 z = *(float4*)&Sg[nl * 132 + jl * 4];
        const int tok = chars[g_perm[n] * Wc_ + t];
        float4 p = *(const float4*)&g_Pp[(size_t)tok * CG_ + j * 4];
        const float zi = z.x + p.x, zf = z.y + p.y, zg = z.z + p.z, zo = z.w + p.w;
        const float c_old = g_cc[(size_t)n * CH_ + j];
        const float cn = sigf(zf) * c_old + sigf(zi) * tanhf(zg);
        const float hn = sigf(zo) * tanhf(cn);
        g_cc[(size_t)n * CH_ + j] = cn;
        g_ch[(size_t)n * CH_ + j] = hn;
        __nv_bfloat16 hi, lo; bf16split(hn, hi, lo);
        __nv_bfloat16* hb = hsW + (size_t)n * (3 * CH_) + j;
        hb[0] = hi; hb[CH_] = hi; hb[2 * CH_] = lo;
    }
}

// ---------------- char t=0 gate (all slots active; c_prev = 0) ----------------
__global__ void char_gate0(const int* __restrict__ chars, __nv_bfloat16* __restrict__ hsW)
{
    const int n = blockIdx.y;
    const int j = blockIdx.x * blockDim.x + threadIdx.x;   // 0..1023
    const int tok = chars[g_perm[n] * Wc_ + 0];
    float4 p = *(const float4*)&g_Pp[(size_t)tok * CG_ + j * 4];
    const float cn = sigf(p.x) * tanhf(p.z);
    const float hn = sigf(p.w) * tanhf(cn);
    g_cc[(size_t)n * CH_ + j] = cn;
    g_ch[(size_t)n * CH_ + j] = hn;
    __nv_bfloat16 hi, lo; bf16split(hn, hi, lo);
    __nv_bfloat16* hb = hsW + (size_t)n * (3 * CH_) + j;
    hb[0] = hi; hb[CH_] = hi; hb[2 * CH_] = lo;
}

// ---------------- fp32 SGEMM (only for P = char_emb @ c_Wih.T, M=128) ----------
__global__ __launch_bounds__(256)
void sgemm128(const float* __restrict__ A, const float* __restrict__ Bm,
              float* __restrict__ C, int M, int N, int K)
{
    __shared__ float As[8][128];
    __shared__ float Bs[8][128];
    const int tid = threadIdx.x;
    const int tx  = tid & 15;
    const int ty  = tid >> 4;
    const int row0 = blockIdx.y * 128;
    const int col0 = blockIdx.x * 128;
    const int lr = tid >> 1;
    const int lk = (tid & 1) * 4;

    const float* Ap = A  + (size_t)(row0 + lr) * K + lk;
    const float* Bp = Bm + (size_t)(col0 + lr) * K + lk;

    float acc[8][8];
#pragma unroll
    for (int i = 0; i < 8; ++i)
#pragma unroll
        for (int j = 0; j < 8; ++j) acc[i][j] = 0.f;

    {
        float4 a = *(const float4*)Ap;
        float4 b = *(const float4*)Bp;
        As[lk+0][lr] = a.x; As[lk+1][lr] = a.y; As[lk+2][lr] = a.z; As[lk+3][lr] = a.w;
        Bs[lk+0][lr] = b.x; Bs[lk+1][lr] = b.y; Bs[lk+2][lr] = b.z; Bs[lk+3][lr] = b.w;
    }
    __syncthreads();

    int k0 = 0;
    while (true) {
        const int kn = k0 + 8;
        const bool more = kn < K;
        float4 an, bn;
        if (more) { an = *(const float4*)(Ap + kn); bn = *(const float4*)(Bp + kn); }
#pragma unroll
        for (int k = 0; k < 8; ++k) {
            float4 a0 = *(const float4*)&As[k][ty*8];
            float4 a1 = *(const float4*)&As[k][ty*8+4];
            float4 b0 = *(const float4*)&Bs[k][tx*8];
            float4 b1 = *(const float4*)&Bs[k][tx*8+4];
            float av[8] = {a0.x,a0.y,a0.z,a0.w,a1.x,a1.y,a1.z,a1.w};
            float bv[8] = {b0.x,b0.y,b0.z,b0.w,b1.x,b1.y,b1.z,b1.w};
#pragma unroll
            for (int i = 0; i < 8; ++i)
#pragma unroll
                for (int j = 0; j < 8; ++j)
                    acc[i][j] = fmaf(av[i], bv[j], acc[i][j]);
        }
        if (!more) break;
        __syncthreads();
        As[lk+0][lr] = an.x; As[lk+1][lr] = an.y; As[lk+2][lr] = an.z; As[lk+3][lr] = an.w;
        Bs[lk+0][lr] = bn.x; Bs[lk+1][lr] = bn.y; Bs[lk+2][lr] = bn.z; Bs[lk+3][lr] = bn.w;
        __syncthreads();
        k0 = kn;
    }

#pragma unroll
    for (int i = 0; i < 8; ++i) {
        const int r = row0 + ty*8 + i;
        float4 o0, o1;
        o0.x = acc[i][0]; o0.y = acc[i][1]; o0.z = acc[i][2]; o0.w = acc[i][3];
        o1.x = acc[i][4]; o1.y = acc[i][5]; o1.z = acc[i][6]; o1.w = acc[i][7];
        *(float4*)(C + (size_t)r*N + col0 + tx*8)     = o0;
        *(float4*)(C + (size_t)r*N + col0 + tx*8 + 4) = o1;
    }
}

// ---------------- persistent word BiLSTM layer ----------------
__global__ __launch_bounds__(256)
void word_layer_persist(const float* __restrict__ Whh0, const float* __restrict__ Whh1,
                        const float* __restrict__ XGf, const float* __restrict__ XGb,
                        const int* __restrict__ lens, const float* __restrict__ bias,
                        float* __restrict__ Hout, __nv_bfloat16* __restrict__ Houts)
{
    __shared__ float hs[64][68];
    __shared__ float ws[32][68];

    const int tid = threadIdx.x;
    const int jj  = tid & 7;
    const int bb  = tid >> 3;             // 0..31
    const int dir = blockIdx.x >> 6;
    const int jt  = (blockIdx.x & 63) << 3;
    const int j   = jt + jj;

    const float* W  = dir ? Whh1 : Whh0;
    const float* XG = dir ? XGb : XGf;
    const float* bv = bias + (size_t)dir * G_;
    float bg[4];
#pragma unroll
    for (int g = 0; g < 4; ++g) bg[g] = bv[g * H_ + j];

    const int len0 = lens[bb];
    const int len1 = lens[bb + 32];

    float hreg0 = 0.f, creg0 = 0.f;
    float hreg1 = 0.f, creg1 = 0.f;

    for (int t = 0; t < S_; ++t) {
        const float* hcur = g_hpp + (size_t)(((t    ) & 1) * 2 + dir) * (B_*H_);
        float*       hnxt = g_hpp + (size_t)(((t + 1) & 1) * 2 + dir) * (B_*H_);

        float acc[2][4];
#pragma unroll
        for (int b2 = 0; b2 < 2; ++b2)
#pragma unroll
            for (int g = 0; g < 4; ++g) acc[b2][g] = 0.f;

        for (int k0 = 0; k0 < H_; k0 += 64) {
#pragma unroll
            for (int i = 0; i < 4; ++i) {
                const int idx = tid + i * 256;
                const int r = idx >> 4, c = idx & 15;
                float4 v = __ldcg((const float4*)(hcur + (size_t)r * H_ + k0 + c * 4));
                *(float4*)&hs[r][c * 4] = v;
            }
#pragma unroll
            for (int i = 0; i < 2; ++i) {
                const int idx = tid + i * 256;
                const int w = idx >> 4, c = idx & 15;
                const int g = w >> 3, jl = w & 7;
                float4 v = *(const float4*)(W + (size_t)(g * H_ + jt + jl) * H_ + k0 + c * 4);
                *(float4*)&ws[w][c * 4] = v;
            }
            __syncthreads();
#pragma unroll
            for (int k4 = 0; k4 < 16; ++k4) {
                float4 a0 = *(const float4*)&hs[bb][k4 * 4];
                float4 a1 = *(const float4*)&hs[bb + 32][k4 * 4];
#pragma unroll
                for (int g = 0; g < 4; ++g) {
                    float4 w4 = *(const float4*)&ws[g * 8 + jj][k4 * 4];
                    acc[0][g] = fmaf(a0.x, w4.x, acc[0][g]);
                    acc[0][g] = fmaf(a0.y, w4.y, acc[0][g]);
                    acc[0][g] = fmaf(a0.z, w4.z, acc[0][g]);
                    acc[0][g] = fmaf(a0.w, w4.w, acc[0][g]);
                    acc[1][g] = fmaf(a1.x, w4.x, acc[1][g]);
                    acc[1][g] = fmaf(a1.y, w4.y, acc[1][g]);
                    acc[1][g] = fmaf(a1.z, w4.z, acc[1][g]);
                    acc[1][g] = fmaf(a1.w, w4.w, acc[1][g]);
                }
            }
            __syncthreads();
        }

#pragma unroll
        for (int b2 = 0; b2 < 2; ++b2) {
            const int b = bb + b2 * 32;
            const int len = b2 ? len1 : len0;
            const bool valid = t < len;
            const int src = (dir == 0) ? t : (valid ? (len - 1 - t) : t);
            const float* xg = XG + (size_t)(b * S_ + src) * G_ + jt + jj;
            float zi = acc[b2][0] + xg[0]      + bg[0];
            float zf = acc[b2][1] + xg[H_]     + bg[1];
            float zg = acc[b2][2] + xg[2*H_]   + bg[2];
            float zo = acc[b2][3] + xg[3*H_]   + bg[3];
            float c_old = b2 ? creg1 : creg0;
            float cn = sigf(zf) * c_old + sigf(zi) * tanhf(zg);
            float hn = sigf(zo) * tanhf(cn);
            float h_old = b2 ? hreg1 : hreg0;
            float h_out = valid ? hn : h_old;
            float c_out = valid ? cn : c_old;
            if (b2) { hreg1 = h_out; creg1 = c_out; }
            else    { hreg0 = h_out; creg0 = c_out; }
            __stcg(hnxt + (size_t)b * H_ + j, h_out);
            if (dir == 0) {
                const float v = valid ? hn : 0.f;
                Hout[(size_t)(b * S_ + t) * CH_ + j] = v;
                if (Houts) {
                    __nv_bfloat16 hi, lo; bf16split(v, hi, lo);
                    const size_t base = (size_t)(b * S_ + t) * (3*CH_) + j;
                    Houts[base] = hi; Houts[base + CH_] = hi; Houts[base + 2*CH_] = lo;
                }
            } else if (valid) {
                Hout[(size_t)(b * S_ + src) * CH_ + H_ + j] = hn;
                if (Houts) {
                    __nv_bfloat16 hi, lo; bf16split(hn, hi, lo);
                    const size_t base = (size_t)(b * S_ + src) * (3*CH_) + H_ + j;
                    Houts[base] = hi; Houts[base + CH_] = hi; Houts[base + 2*CH_] = lo;
                }
            }
        }

        if (t < S_ - 1) {
            __syncthreads();
            if (tid == 0) {
                __threadfence();
                atomicAdd(&g_bar, 1u);
                const unsigned tgt = (unsigned)(t + 1) * (unsigned)NBLK_;
                volatile unsigned* p = &g_bar;
                while (*p < tgt) __nanosleep(64);
            }
            __syncthreads();
        }
    }
}

// ---------------- word embedding gather (writes split directly) ----------------
__global__ void embed_words(const int* __restrict__ words, const float* __restrict__ emb)
{
    const int m = blockIdx.x;
    const int e = threadIdx.x;
    const float x = emb[(size_t)words[m] * E_ + e];
    __nv_bfloat16 hi, lo; bf16split(x, hi, lo);
    const size_t base = (size_t)m * (3*E_) + e;
    g_Xembs[base] = hi; g_Xembs[base + E_] = hi; g_Xembs[base + 2*E_] = lo;
}

// ---------------- final head ----------------
__global__ __launch_bounds__(256)
void final_linear(const int* __restrict__ wnum, const float* __restrict__ W,
                  const float* __restrict__ bias, float* __restrict__ out)
{
    const int row = blockIdx.x;         // 0..8191
    const int b = row >> 7;
    const int s = row & (S_ - 1);
    const bool valid = s < wnum[b];
    const int slot = g_iperm[row];
    __shared__ float v[CH_];
    __shared__ float sred[8*NC_];
    const int tid = threadIdx.x;
    for (int j = tid; j < CH_; j += 256) {
        float x = g_H1[(size_t)row*CH_ + j];
        if (valid) x += g_ch[(size_t)slot*CH_ + j];
        v[j] = x;
    }
    __syncthreads();
    float acc[NC_];
#pragma unroll
    for (int c2 = 0; c2 < NC_; ++c2) acc[c2] = 0.f;
    for (int j = tid; j < CH_; j += 256) {
        float x = v[j];
#pragma unroll
        for (int c2 = 0; c2 < NC_; ++c2)
            acc[c2] = fmaf(x, W[c2*CH_ + j], acc[c2]);
    }
#pragma unroll
    for (int c2 = 0; c2 < NC_; ++c2)
#pragma unroll
        for (int off = 16; off > 0; off >>= 1)
            acc[c2] += __shfl_down_sync(0xffffffffu, acc[c2], off);
    const int lane = tid & 31, w = tid >> 5;
    if (lane == 0)
#pragma unroll
        for (int c2 = 0; c2 < NC_; ++c2) sred[w*NC_ + c2] = acc[c2];
    __syncthreads();
    if (tid < NC_) {
        float sum = bias[tid];
#pragma unroll
        for (int w2 = 0; w2 < 8; ++w2) sum += sred[w2*NC_ + tid];
        out[(size_t)row*NC_ + tid] = sum;
    }
}

// ================================================================================
extern "C" void kernel_launch(void* const* d_in, const int* in_sizes, int n_in,
                              void* d_out, int out_size)
{
    (void)in_sizes; (void)n_in; (void)out_size;
    const int*   words     = (const int*)  d_in[0];
    const int*   words_num = (const int*)  d_in[1];
    const int*   chars     = (const int*)  d_in[2];
    const int*   char_lens = (const int*)  d_in[3];
    const float* word_emb  = (const float*)d_in[4];
    const float* char_emb  = (const float*)d_in[5];
    const float* l0_Wih    = (const float*)d_in[6];
    const float* l0_Whh    = (const float*)d_in[7];
    const float* l0_b      = (const float*)d_in[8];
    const float* l1_Wih    = (const float*)d_in[9];
    const float* l1_Whh    = (const float*)d_in[10];
    const float* l1_b      = (const float*)d_in[11];
    const float* c_Wih     = (const float*)d_in[12];
    const float* c_Whh     = (const float*)d_in[13];
    const float* c_b       = (const float*)d_in[14];
    const float* lin_W     = (const float*)d_in[15];
    const float* lin_b     = (const float*)d_in[16];
    float* out = (float*)d_out;

    float *XGf, *XGb, *H0, *H1, *hpp, *P;
    __nv_bfloat16 *Xembs, *H0s, *hsA, *hsB, *Wc2, *Wih0s, *Wih1s;
    unsigned* bar;
    int *hist;
    cudaGetSymbolAddress((void**)&Xembs, g_Xembs);
    cudaGetSymbolAddress((void**)&XGf,  g_XGf);
    cudaGetSymbolAddress((void**)&XGb,  g_XGb);
    cudaGetSymbolAddress((void**)&H0,   g_H0);
    cudaGetSymbolAddress((void**)&H0s,  g_H0s);
    cudaGetSymbolAddress((void**)&H1,   g_H1);
    cudaGetSymbolAddress((void**)&hpp,  g_hpp);
    cudaGetSymbolAddress((void**)&bar,  g_bar);
    cudaGetSymbolAddress((void**)&P,    g_P);
    cudaGetSymbolAddress((void**)&hsA,  g_hsA);
    cudaGetSymbolAddress((void**)&hsB,  g_hsB);
    cudaGetSymbolAddress((void**)&Wc2,  g_Wc2);
    cudaGetSymbolAddress((void**)&Wih0s,g_Wih0s);
    cudaGetSymbolAddress((void**)&Wih1s,g_Wih1s);
    cudaGetSymbolAddress((void**)&hist, g_hist);

    cudaFuncSetAttribute(hgemm,      cudaFuncAttributeMaxDynamicSharedMemorySize, (int)HS_BYTES);
    cudaFuncSetAttribute(hgemm_lstm, cudaFuncAttributeMaxDynamicSharedMemorySize, (int)HS_BYTES);

    // ---- fork-join streams (char path on s_char, word path on capture stream) ----
    static cudaStream_t s_char = nullptr;
    static cudaEvent_t ev_fork = nullptr, ev_join = nullptr;
    if (!s_char) {
        cudaStreamCreateWithFlags(&s_char, cudaStreamNonBlocking);
        cudaEventCreateWithFlags(&ev_fork, cudaEventDisableTiming);
        cudaEventCreateWithFlags(&ev_join, cudaEventDisableTiming);
    }
    cudaEventRecord(ev_fork, 0);
    cudaStreamWaitEvent(s_char, ev_fork, 0);

    // ======================= char path (stream s_char) ==========================
    cudaMemsetAsync(hist, 0, (Wc_ + 1) * sizeof(int), s_char);
    hist_k<<<NW_/256, 256, 0, s_char>>>(char_lens);
    scan_k<<<1, 32, 0, s_char>>>();
    scatter_k<<<NW_/256, 256, 0, s_char>>>(char_lens);
    split_remap_k<<<(CG_*CH_ + 255)/256, 256, 0, s_char>>>(c_Whh, Wc2);
    sgemm128<<<dim3(CG_/128, 1), 256, 0, s_char>>>(char_emb, c_Wih, P, 128, CG_, E_);
    reorderP_k<<<(128*CG_ + 255)/256, 256, 0, s_char>>>(c_b);
    char_gate0<<<dim3(CH_/256, NW_), 256, 0, s_char>>>(chars, hsA);
    for (int t = 1; t < Wc_; ++t) {
        const __nv_bfloat16* rd = ((t - 1) & 1) ? hsB : hsA;
        __nv_bfloat16*       wr = (t & 1)       ? hsB : hsA;
        hgemm_lstm<<<dim3(CG_/128, NW_/128), 256, HS_BYTES, s_char>>>(rd, Wc2, wr, chars, t);
    }
    cudaEventRecord(ev_join, s_char);

    // ======================= word path (capture stream) =========================
    split_k<<<(G_*E_ + 255)/256, 256>>>(l0_Wih,                     Wih0s,                     E_,  G_*E_);
    split_k<<<(G_*E_ + 255)/256, 256>>>(l0_Wih + (size_t)G_*E_,     Wih0s + (size_t)G_*3*E_,   E_,  G_*E_);
    split_k<<<(G_*CH_ + 255)/256, 256>>>(l1_Wih,                    Wih1s,                     CH_, G_*CH_);
    split_k<<<(G_*CH_ + 255)/256, 256>>>(l1_Wih + (size_t)G_*CH_,   Wih1s + (size_t)G_*3*CH_,  CH_, G_*CH_);
    embed_words<<<NW_, E_>>>(words, word_emb);

    {   // layer 0 (K'=768)
        const float* Whh0 = l0_Whh;
        const float* Whh1 = l0_Whh + (size_t)G_ * H_;
        hgemm<<<dim3(G_/128, NW_/128), 256, HS_BYTES>>>(Xembs, Wih0s,                    XGf, NW_, G_, 3*E_);
        hgemm<<<dim3(G_/128, NW_/128), 256, HS_BYTES>>>(Xembs, Wih0s + (size_t)G_*3*E_,  XGb, NW_, G_, 3*E_);
        cudaMemsetAsync(H0,  0, (size_t)NW_*CH_*sizeof(float), 0);
        cudaMemsetAsync(H0s, 0, (size_t)NW_*3*CH_*sizeof(__nv_bfloat16), 0);
        cudaMemsetAsync(hpp, 0, (size_t)2*2*B_*H_*sizeof(float), 0);
        cudaMemsetAsync(bar, 0, sizeof(unsigned), 0);
        word_layer_persist<<<NBLK_, 256>>>(Whh0, Whh1, XGf, XGb, words_num, l0_b, H0, H0s);
    }
    {   // layer 1 (K'=3072)
        const float* Whh0 = l1_Whh;
        const float* Whh1 = l1_Whh + (size_t)G_ * H_;
        hgemm<<<dim3(G_/128, NW_/128), 256, HS_BYTES>>>(H0s, Wih1s,                     XGf, NW_, G_, 3*CH_);
        hgemm<<<dim3(G_/128, NW_/128), 256, HS_BYTES>>>(H0s, Wih1s + (size_t)G_*3*CH_,  XGb, NW_, G_, 3*CH_);
        cudaMemsetAsync(H1,  0, (size_t)NW_*CH_*sizeof(float), 0);
        cudaMemsetAsync(hpp, 0, (size_t)2*2*B_*H_*sizeof(float), 0);
        cudaMemsetAsync(bar, 0, sizeof(unsigned), 0);
        word_layer_persist<<<NBLK_, 256>>>(Whh0, Whh1, XGf, XGb, words_num, l1_b, H1, nullptr);
    }

    // ======================= join + head =========================
    cudaStreamWaitEvent(0, ev_join, 0);
    final_linear<<<NW_, 256>>>(words_num, lin_W, lin_b, out);
}

// round 9
// speedup vs baseline: 1.1495x; 1.0204x over previous
#include <cuda_runtime.h>
#include <cuda_bf16.h>
#include <cstdint>
#include <cstddef>

// Problem constants
#define B_   64
#define S_   128
#define Wc_  16
#define E_   256
#define H_   512
#define NC_  20
#define NW_  (B_*S_)        // 8192 words total
#define G_   (4*H_)         // 2048 word-LSTM gate width
#define CH_  (2*H_)         // 1024 char-LSTM hidden
#define CG_  (4*CH_)        // 4096 char-LSTM gate width

#define NBLK_ 128           // persistent word-layer blocks
#define LDS_  72            // hgemm smem halfword stride (64 + 8 pad)
#define HS_BYTES ((size_t)4 * 128 * LDS_ * sizeof(__nv_bfloat16))   // 73728

// ---------------- scratch (static device globals; no allocation) ----------------
__device__ float g_Xemb[(size_t)NW_*E_];               // word embeddings  [8192,256]
__device__ float g_XGf [(size_t)NW_*G_];               // fwd x-gates      [8192,2048]
__device__ float g_XGb [(size_t)NW_*G_];               // bwd x-gates      [8192,2048]
__device__ float g_H0  [(size_t)NW_*CH_];              // layer0 out fp32
__device__ float g_H1  [(size_t)NW_*CH_];              // layer1 output    [8192,1024]
__device__ float g_hpp[(size_t)2*2*B_*H_];             // h ping-pong
__device__ unsigned g_bar;                             // grid barrier counter
__device__ float g_P  [(size_t)128*CG_];               // char_emb @ c_Wih.T (gate-major)
__device__ float g_Pp [(size_t)128*CG_];               // P interleaved j*4+g, + bias
__device__ float g_ch [(size_t)NW_*CH_];               // char h fp32 (sorted slots)
__device__ float g_cc [(size_t)NW_*CH_];               // char c state (sorted)
__device__ __nv_bfloat16 g_hsA[(size_t)NW_*3*CH_];     // char h split buf A
__device__ __nv_bfloat16 g_hsB[(size_t)NW_*3*CH_];     // char h split buf B
__device__ __nv_bfloat16 g_Wc2[(size_t)CG_*3*CH_];     // c_Whh split, rows j*4+g

// ---- length-sort bookkeeping ----
__device__ int g_hist[Wc_ + 1];
__device__ int g_off [Wc_ + 1];
__device__ int g_act [Wc_ + 1];
__device__ int g_perm [NW_];
__device__ int g_iperm[NW_];
__device__ int g_slen [NW_];

__device__ __forceinline__ float sigf(float x) { return 1.f / (1.f + __expf(-x)); }

__device__ __forceinline__ void bf16split(float x, __nv_bfloat16& hi, __nv_bfloat16& lo)
{
    hi = __float2bfloat16(x);
    lo = __float2bfloat16(x - __bfloat162float(hi));
}

__device__ __forceinline__ void cp16(void* dst, const void* src)
{
    uint32_t d = (uint32_t)__cvta_generic_to_shared(dst);
    asm volatile("cp.async.cg.shared.global [%0], [%1], 16;" :: "r"(d), "l"(src));
}

// ---------------- counting sort by char_lens (descending) ----------------
__global__ void hist_k(const int* __restrict__ clens)
{
    const int i = blockIdx.x * blockDim.x + threadIdx.x;
    if (i < NW_) atomicAdd(&g_hist[clens[i]], 1);
}
__global__ void scan_k()
{
    if (threadIdx.x == 0) {
        int off = 0;
        for (int len = Wc_; len >= 1; --len) { g_off[len] = off; off += g_hist[len]; }
        for (int t = 0; t <= Wc_; ++t) {
            int a = 0;
            for (int l = t + 1; l <= Wc_; ++l) a += g_hist[l];
            g_act[t] = a;
        }
    }
}
__global__ void scatter_k(const int* __restrict__ clens)
{
    const int i = blockIdx.x * blockDim.x + threadIdx.x;
    if (i < NW_) {
        const int len = clens[i];
        const int s = atomicAdd(&g_off[len], 1);
        g_perm[s] = i;
        g_iperm[i] = s;
        g_slen[s] = len;
    }
}

// split of c_Whh (bf16x3, B-side [hi|lo|hi]) with gate-interleaved row remap:
// src row r = g*CH+j -> dst row j*4+g
__global__ void split_remap_k(const float* __restrict__ src, __nv_bfloat16* __restrict__ dst)
{
    const int i = blockIdx.x * blockDim.x + threadIdx.x;
    if (i >= CG_ * CH_) return;
    const int r = i / CH_, k = i % CH_;
    const int g = r / CH_, j = r % CH_;
    const int outr = j * 4 + g;
    __nv_bfloat16 hi, lo;
    bf16split(src[i], hi, lo);
    const size_t base = (size_t)outr * 3 * CH_;
    dst[base + k] = hi; dst[base + CH_ + k] = lo; dst[base + 2*CH_ + k] = hi;
}

// P reorder to interleaved + fold bias: Pp[tok][j*4+g] = P[tok][g*CH+j] + c_b[g*CH+j]
__global__ void reorderP_k(const float* __restrict__ cbias)
{
    const int i = blockIdx.x * blockDim.x + threadIdx.x;
    if (i >= 128 * CG_) return;
    const int tok = i / CG_, col = i % CG_;
    const int j = col >> 2, g = col & 3;
    const int src = g * CH_ + j;
    g_Pp[i] = g_P[(size_t)tok * CG_ + src] + cbias[src];
}

// ========== fused char-LSTM GEMM step: Z = h_{t-1} @ Wc2^T, then cell update ====
// bf16x3 operands, 128x128 tile, 8 warps, BK=64, cp.async double buffer.
// B (g_Wc2) rows gate-interleaved (j*4+g). Epilogue applies the LSTM cell and
// writes cc/ch (fp32) + split h into hsW. Active rows: n < g_act[t].
__global__ __launch_bounds__(256)
void hgemm_lstm(const __nv_bfloat16* __restrict__ A,   // hsRead [8192,3072]
                const __nv_bfloat16* __restrict__ Bm,  // g_Wc2 [4096,3072]
                __nv_bfloat16* __restrict__ hsW,       // hsWrite
                const int* __restrict__ chars, int t)
{
    const int act_t = g_act[t];
    const int row0 = blockIdx.y * 128;
    if (row0 >= act_t) return;
    const int col0 = blockIdx.x * 128;
    const int K = 3 * CH_;

    extern __shared__ __nv_bfloat16 smem_[];
    __nv_bfloat16* const sA[2] = { smem_,                smem_ + 2*128*LDS_ };
    __nv_bfloat16* const sB[2] = { smem_ + 128*LDS_,     smem_ + 3*128*LDS_ };

    const int tid  = threadIdx.x;
    const int lane = tid & 31;
    const int wid  = tid >> 5;
    const int wm   = (wid & 1) * 64;
    const int wn   = (wid >> 1) * 32;

    const int lr = tid >> 1;
    const int cb = (tid & 1) * 4;

    float acc[4][4][4];
#pragma unroll
    for (int mi = 0; mi < 4; ++mi)
#pragma unroll
        for (int ni = 0; ni < 4; ++ni)
#pragma unroll
            for (int f = 0; f < 4; ++f) acc[mi][ni][f] = 0.f;

    const int KT = K >> 6;   // 48

    {
        const __nv_bfloat16* Ap = A  + (size_t)(row0 + lr) * K + cb * 8;
        const __nv_bfloat16* Bp = Bm + (size_t)(col0 + lr) * K + cb * 8;
#pragma unroll
        for (int c = 0; c < 4; ++c) {
            cp16(&sA[0][lr * LDS_ + (cb + c) * 8], Ap + c * 8);
            cp16(&sB[0][lr * LDS_ + (cb + c) * 8], Bp + c * 8);
        }
        asm volatile("cp.async.commit_group;");
    }

    for (int kt = 0; kt < KT; ++kt) {
        const int buf = kt & 1;
        if (kt + 1 < KT) {
            const int k0 = (kt + 1) << 6;
            const __nv_bfloat16* Ap = A  + (size_t)(row0 + lr) * K + k0 + cb * 8;
            const __nv_bfloat16* Bp = Bm + (size_t)(col0 + lr) * K + k0 + cb * 8;
#pragma unroll
            for (int c = 0; c < 4; ++c) {
                cp16(&sA[buf ^ 1][lr * LDS_ + (cb + c) * 8], Ap + c * 8);
                cp16(&sB[buf ^ 1][lr * LDS_ + (cb + c) * 8], Bp + c * 8);
            }
            asm volatile("cp.async.commit_group;");
            asm volatile("cp.async.wait_group 1;");
        } else {
            asm volatile("cp.async.wait_group 0;");
        }
        __syncthreads();

        const __nv_bfloat16* As = sA[buf];
        const __nv_bfloat16* Bs = sB[buf];
#pragma unroll
        for (int ks = 0; ks < 4; ++ks) {
            uint32_t a[4][4], b[4][2];
#pragma unroll
            for (int mi = 0; mi < 4; ++mi) {
                uint32_t addr = (uint32_t)__cvta_generic_to_shared(
                    &As[(wm + mi*16 + (lane & 15)) * LDS_ + ks*16 + (lane >> 4) * 8]);
                asm volatile("ldmatrix.sync.aligned.m8n8.x4.shared.b16 {%0,%1,%2,%3}, [%4];"
                    : "=r"(a[mi][0]), "=r"(a[mi][1]), "=r"(a[mi][2]), "=r"(a[mi][3])
                    : "r"(addr));
            }
#pragma unroll
            for (int ni = 0; ni < 4; ++ni) {
                uint32_t addr = (uint32_t)__cvta_generic_to_shared(
                    &Bs[(wn + ni*8 + (lane & 7)) * LDS_ + ks*16 + ((lane >> 3) & 1) * 8]);
                asm volatile("ldmatrix.sync.aligned.m8n8.x2.shared.b16 {%0,%1}, [%2];"
                    : "=r"(b[ni][0]), "=r"(b[ni][1]) : "r"(addr));
            }
#pragma unroll
            for (int mi = 0; mi < 4; ++mi)
#pragma unroll
                for (int ni = 0; ni < 4; ++ni) {
                    asm volatile(
                        "mma.sync.aligned.m16n8k16.row.col.f32.bf16.bf16.f32 "
                        "{%0,%1,%2,%3}, {%4,%5,%6,%7}, {%8,%9}, {%0,%1,%2,%3};"
                        : "+f"(acc[mi][ni][0]), "+f"(acc[mi][ni][1]),
                          "+f"(acc[mi][ni][2]), "+f"(acc[mi][ni][3])
                        : "r"(a[mi][0]), "r"(a[mi][1]), "r"(a[mi][2]), "r"(a[mi][3]),
                          "r"(b[ni][0]), "r"(b[ni][1]));
                }
        }
        __syncthreads();
    }

    // ---- fused LSTM cell epilogue ----
    float* Sg = (float*)smem_;          // 128 x 132 fp32 = 67584 B
#pragma unroll
    for (int mi = 0; mi < 4; ++mi)
#pragma unroll
        for (int ni = 0; ni < 4; ++ni) {
            const int r = wm + mi*16 + (lane >> 2);
            const int c = wn + ni*8 + (lane & 3) * 2;
            Sg[r * 132 + c]           = acc[mi][ni][0];
            Sg[r * 132 + c + 1]       = acc[mi][ni][1];
            Sg[(r + 8) * 132 + c]     = acc[mi][ni][2];
            Sg[(r + 8) * 132 + c + 1] = acc[mi][ni][3];
        }
    __syncthreads();

    const int jb = col0 >> 2;           // 32 j per tile
#pragma unroll
    for (int q = 0; q < 16; ++q) {
        const int cid = tid + q * 256;
        const int nl = cid >> 5, jl = cid & 31;
        const int n = row0 + nl;
        if (n >= act_t) continue;
        const int j = jb + jl;
        float4 z = *(float4*)&Sg[nl * 132 + jl * 4];
        const int tok = chars[g_perm[n] * Wc_ + t];
        float4 p = *(const float4*)&g_Pp[(size_t)tok * CG_ + j * 4];
        const float zi = z.x + p.x, zf = z.y + p.y, zg = z.z + p.z, zo = z.w + p.w;
        const float c_old = g_cc[(size_t)n * CH_ + j];
        const float cn = sigf(zf) * c_old + sigf(zi) * tanhf(zg);
        const float hn = sigf(zo) * tanhf(cn);
        g_cc[(size_t)n * CH_ + j] = cn;
        g_ch[(size_t)n * CH_ + j] = hn;
        __nv_bfloat16 hi, lo; bf16split(hn, hi, lo);
        __nv_bfloat16* hb = hsW + (size_t)n * (3 * CH_) + j;
        hb[0] = hi; hb[CH_] = hi; hb[2 * CH_] = lo;
    }
}

// ---------------- char t=0 gate (all slots active; c_prev = 0) ----------------
__global__ void char_gate0(const int* __restrict__ chars, __nv_bfloat16* __restrict__ hsW)
{
    const int n = blockIdx.y;
    const int j = blockIdx.x * blockDim.x + threadIdx.x;   // 0..1023
    const int tok = chars[g_perm[n] * Wc_ + 0];
    float4 p = *(const float4*)&g_Pp[(size_t)tok * CG_ + j * 4];
    const float cn = sigf(p.x) * tanhf(p.z);
    const float hn = sigf(p.w) * tanhf(cn);
    g_cc[(size_t)n * CH_ + j] = cn;
    g_ch[(size_t)n * CH_ + j] = hn;
    __nv_bfloat16 hi, lo; bf16split(hn, hi, lo);
    __nv_bfloat16* hb = hsW + (size_t)n * (3 * CH_) + j;
    hb[0] = hi; hb[CH_] = hi; hb[2 * CH_] = lo;
}

// ---------------- fp32 SGEMM: C[M,N] = A[M,K] @ B[N,K]^T ----------------
// 128x128 tile, 256 threads, 8x8 microtile, K-chunk 8. M%128==0,N%128==0,K%8==0.
__global__ __launch_bounds__(256)
void sgemm128(const float* __restrict__ A, const float* __restrict__ Bm,
              float* __restrict__ C, int M, int N, int K)
{
    __shared__ float As[8][128];
    __shared__ float Bs[8][128];
    const int tid = threadIdx.x;
    const int tx  = tid & 15;
    const int ty  = tid >> 4;
    const int row0 = blockIdx.y * 128;
    const int col0 = blockIdx.x * 128;
    const int lr = tid >> 1;
    const int lk = (tid & 1) * 4;

    const float* Ap = A  + (size_t)(row0 + lr) * K + lk;
    const float* Bp = Bm + (size_t)(col0 + lr) * K + lk;

    float acc[8][8];
#pragma unroll
    for (int i = 0; i < 8; ++i)
#pragma unroll
        for (int j = 0; j < 8; ++j) acc[i][j] = 0.f;

    {
        float4 a = *(const float4*)Ap;
        float4 b = *(const float4*)Bp;
        As[lk+0][lr] = a.x; As[lk+1][lr] = a.y; As[lk+2][lr] = a.z; As[lk+3][lr] = a.w;
        Bs[lk+0][lr] = b.x; Bs[lk+1][lr] = b.y; Bs[lk+2][lr] = b.z; Bs[lk+3][lr] = b.w;
    }
    __syncthreads();

    int k0 = 0;
    while (true) {
        const int kn = k0 + 8;
        const bool more = kn < K;
        float4 an, bn;
        if (more) { an = *(const float4*)(Ap + kn); bn = *(const float4*)(Bp + kn); }
#pragma unroll
        for (int k = 0; k < 8; ++k) {
            float4 a0 = *(const float4*)&As[k][ty*8];
            float4 a1 = *(const float4*)&As[k][ty*8+4];
            float4 b0 = *(const float4*)&Bs[k][tx*8];
            float4 b1 = *(const float4*)&Bs[k][tx*8+4];
            float av[8] = {a0.x,a0.y,a0.z,a0.w,a1.x,a1.y,a1.z,a1.w};
            float bv[8] = {b0.x,b0.y,b0.z,b0.w,b1.x,b1.y,b1.z,b1.w};
#pragma unroll
            for (int i = 0; i < 8; ++i)
#pragma unroll
                for (int j = 0; j < 8; ++j)
                    acc[i][j] = fmaf(av[i], bv[j], acc[i][j]);
        }
        if (!more) break;
        __syncthreads();
        As[lk+0][lr] = an.x; As[lk+1][lr] = an.y; As[lk+2][lr] = an.z; As[lk+3][lr] = an.w;
        Bs[lk+0][lr] = bn.x; Bs[lk+1][lr] = bn.y; Bs[lk+2][lr] = bn.z; Bs[lk+3][lr] = bn.w;
        __syncthreads();
        k0 = kn;
    }

#pragma unroll
    for (int i = 0; i < 8; ++i) {
        const int r = row0 + ty*8 + i;
        float4 o0, o1;
        o0.x = acc[i][0]; o0.y = acc[i][1]; o0.z = acc[i][2]; o0.w = acc[i][3];
        o1.x = acc[i][4]; o1.y = acc[i][5]; o1.z = acc[i][6]; o1.w = acc[i][7];
        *(float4*)(C + (size_t)r*N + col0 + tx*8)     = o0;
        *(float4*)(C + (size_t)r*N + col0 + tx*8 + 4) = o1;
    }
}

// ---------------- persistent word BiLSTM layer (fp32) ----------------
__global__ __launch_bounds__(256)
void word_layer_persist(const float* __restrict__ Whh0, const float* __restrict__ Whh1,
                        const float* __restrict__ XGf, const float* __restrict__ XGb,
                        const int* __restrict__ lens, const float* __restrict__ bias,
                        float* __restrict__ Hout)
{
    __shared__ float hs[64][68];
    __shared__ float ws[32][68];

    const int tid = threadIdx.x;
    const int jj  = tid & 7;
    const int bb  = tid >> 3;             // 0..31
    const int dir = blockIdx.x >> 6;
    const int jt  = (blockIdx.x & 63) << 3;
    const int j   = jt + jj;

    const float* W  = dir ? Whh1 : Whh0;
    const float* XG = dir ? XGb : XGf;
    const float* bv = bias + (size_t)dir * G_;
    float bg[4];
#pragma unroll
    for (int g = 0; g < 4; ++g) bg[g] = bv[g * H_ + j];

    const int len0 = lens[bb];
    const int len1 = lens[bb + 32];

    float hreg0 = 0.f, creg0 = 0.f;
    float hreg1 = 0.f, creg1 = 0.f;

    for (int t = 0; t < S_; ++t) {
        const float* hcur = g_hpp + (size_t)(((t    ) & 1) * 2 + dir) * (B_*H_);
        float*       hnxt = g_hpp + (size_t)(((t + 1) & 1) * 2 + dir) * (B_*H_);

        float acc[2][4];
#pragma unroll
        for (int b2 = 0; b2 < 2; ++b2)
#pragma unroll
            for (int g = 0; g < 4; ++g) acc[b2][g] = 0.f;

        for (int k0 = 0; k0 < H_; k0 += 64) {
#pragma unroll
            for (int i = 0; i < 4; ++i) {
                const int idx = tid + i * 256;
                const int r = idx >> 4, c = idx & 15;
                float4 v = __ldcg((const float4*)(hcur + (size_t)r * H_ + k0 + c * 4));
                *(float4*)&hs[r][c * 4] = v;
            }
#pragma unroll
            for (int i = 0; i < 2; ++i) {
                const int idx = tid + i * 256;
                const int w = idx >> 4, c = idx & 15;
                const int g = w >> 3, jl = w & 7;
                float4 v = *(const float4*)(W + (size_t)(g * H_ + jt + jl) * H_ + k0 + c * 4);
                *(float4*)&ws[w][c * 4] = v;
            }
            __syncthreads();
#pragma unroll
            for (int k4 = 0; k4 < 16; ++k4) {
                float4 a0 = *(const float4*)&hs[bb][k4 * 4];
                float4 a1 = *(const float4*)&hs[bb + 32][k4 * 4];
#pragma unroll
                for (int g = 0; g < 4; ++g) {
                    float4 w4 = *(const float4*)&ws[g * 8 + jj][k4 * 4];
                    acc[0][g] = fmaf(a0.x, w4.x, acc[0][g]);
                    acc[0][g] = fmaf(a0.y, w4.y, acc[0][g]);
                    acc[0][g] = fmaf(a0.z, w4.z, acc[0][g]);
                    acc[0][g] = fmaf(a0.w, w4.w, acc[0][g]);
                    acc[1][g] = fmaf(a1.x, w4.x, acc[1][g]);
                    acc[1][g] = fmaf(a1.y, w4.y, acc[1][g]);
                    acc[1][g] = fmaf(a1.z, w4.z, acc[1][g]);
                    acc[1][g] = fmaf(a1.w, w4.w, acc[1][g]);
                }
            }
            __syncthreads();
        }

#pragma unroll
        for (int b2 = 0; b2 < 2; ++b2) {
            const int b = bb + b2 * 32;
            const int len = b2 ? len1 : len0;
            const bool valid = t < len;
            const int src = (dir == 0) ? t : (valid ? (len - 1 - t) : t);
            const float* xg = XG + (size_t)(b * S_ + src) * G_ + jt + jj;
            float zi = acc[b2][0] + xg[0]      + bg[0];
            float zf = acc[b2][1] + xg[H_]     + bg[1];
            float zg = acc[b2][2] + xg[2*H_]   + bg[2];
            float zo = acc[b2][3] + xg[3*H_]   + bg[3];
            float c_old = b2 ? creg1 : creg0;
            float cn = sigf(zf) * c_old + sigf(zi) * tanhf(zg);
            float hn = sigf(zo) * tanhf(cn);
            float h_old = b2 ? hreg1 : hreg0;
            float h_out = valid ? hn : h_old;
            float c_out = valid ? cn : c_old;
            if (b2) { hreg1 = h_out; creg1 = c_out; }
            else    { hreg0 = h_out; creg0 = c_out; }
            __stcg(hnxt + (size_t)b * H_ + j, h_out);
            if (dir == 0) {
                Hout[(size_t)(b * S_ + t) * CH_ + j] = valid ? hn : 0.f;
            } else if (valid) {
                Hout[(size_t)(b * S_ + src) * CH_ + H_ + j] = hn;
            }
        }

        if (t < S_ - 1) {
            __syncthreads();
            if (tid == 0) {
                __threadfence();
                atomicAdd(&g_bar, 1u);
                const unsigned tgt = (unsigned)(t + 1) * (unsigned)NBLK_;
                volatile unsigned* p = &g_bar;
                while (*p < tgt) __nanosleep(64);
            }
            __syncthreads();
        }
    }
}

// ---------------- word embedding gather (fp32) ----------------
__global__ void embed_words(const int* __restrict__ words, const float* __restrict__ emb)
{
    const int m = blockIdx.x;
    const int e = threadIdx.x;
    g_Xemb[(size_t)m*E_ + e] = emb[(size_t)words[m] * E_ + e];
}

// ---------------- final head ----------------
__global__ __launch_bounds__(256)
void final_linear(const int* __restrict__ wnum, const float* __restrict__ W,
                  const float* __restrict__ bias, float* __restrict__ out)
{
    const int row = blockIdx.x;         // 0..8191
    const int b = row >> 7;
    const int s = row & (S_ - 1);
    const bool valid = s < wnum[b];
    const int slot = g_iperm[row];
    __shared__ float v[CH_];
    __shared__ float sred[8*NC_];
    const int tid = threadIdx.x;
    for (int j = tid; j < CH_; j += 256) {
        float x = g_H1[(size_t)row*CH_ + j];
        if (valid) x += g_ch[(size_t)slot*CH_ + j];
        v[j] = x;
    }
    __syncthreads();
    float acc[NC_];
#pragma unroll
    for (int c2 = 0; c2 < NC_; ++c2) acc[c2] = 0.f;
    for (int j = tid; j < CH_; j += 256) {
        float x = v[j];
#pragma unroll
        for (int c2 = 0; c2 < NC_; ++c2)
            acc[c2] = fmaf(x, W[c2*CH_ + j], acc[c2]);
    }
#pragma unroll
    for (int c2 = 0; c2 < NC_; ++c2)
#pragma unroll
        for (int off = 16; off > 0; off >>= 1)
            acc[c2] += __shfl_down_sync(0xffffffffu, acc[c2], off);
    const int lane = tid & 31, w = tid >> 5;
    if (lane == 0)
#pragma unroll
        for (int c2 = 0; c2 < NC_; ++c2) sred[w*NC_ + c2] = acc[c2];
    __syncthreads();
    if (tid < NC_) {
        float sum = bias[tid];
#pragma unroll
        for (int w2 = 0; w2 < 8; ++w2) sum += sred[w2*NC_ + tid];
        out[(size_t)row*NC_ + tid] = sum;
    }
}

// ================================================================================
extern "C" void kernel_launch(void* const* d_in, const int* in_sizes, int n_in,
                              void* d_out, int out_size)
{
    (void)in_sizes; (void)n_in; (void)out_size;
    const int*   words     = (const int*)  d_in[0];
    const int*   words_num = (const int*)  d_in[1];
    const int*   chars     = (const int*)  d_in[2];
    const int*   char_lens = (const int*)  d_in[3];
    const float* word_emb  = (const float*)d_in[4];
    const float* char_emb  = (const float*)d_in[5];
    const float* l0_Wih    = (const float*)d_in[6];
    const float* l0_Whh    = (const float*)d_in[7];
    const float* l0_b      = (const float*)d_in[8];
    const float* l1_Wih    = (const float*)d_in[9];
    const float* l1_Whh    = (const float*)d_in[10];
    const float* l1_b      = (const float*)d_in[11];
    const float* c_Wih     = (const float*)d_in[12];
    const float* c_Whh     = (const float*)d_in[13];
    const float* c_b       = (const float*)d_in[14];
    const float* lin_W     = (const float*)d_in[15];
    const float* lin_b     = (const float*)d_in[16];
    float* out = (float*)d_out;

    float *Xemb, *XGf, *XGb, *H0, *H1, *hpp, *P;
    __nv_bfloat16 *hsA, *hsB, *Wc2;
    unsigned* bar;
    int *hist;
    cudaGetSymbolAddress((void**)&Xemb, g_Xemb);
    cudaGetSymbolAddress((void**)&XGf,  g_XGf);
    cudaGetSymbolAddress((void**)&XGb,  g_XGb);
    cudaGetSymbolAddress((void**)&H0,   g_H0);
    cudaGetSymbolAddress((void**)&H1,   g_H1);
    cudaGetSymbolAddress((void**)&hpp,  g_hpp);
    cudaGetSymbolAddress((void**)&bar,  g_bar);
    cudaGetSymbolAddress((void**)&P,    g_P);
    cudaGetSymbolAddress((void**)&hsA,  g_hsA);
    cudaGetSymbolAddress((void**)&hsB,  g_hsB);
    cudaGetSymbolAddress((void**)&Wc2,  g_Wc2);
    cudaGetSymbolAddress((void**)&hist, g_hist);

    cudaFuncSetAttribute(hgemm_lstm, cudaFuncAttributeMaxDynamicSharedMemorySize, (int)HS_BYTES);

    // ---- fork-join streams (char path on s_char, word path on capture stream) ----
    static cudaStream_t s_char = nullptr;
    static cudaEvent_t ev_fork = nullptr, ev_join = nullptr;
    if (!s_char) {
        cudaStreamCreateWithFlags(&s_char, cudaStreamNonBlocking);
        cudaEventCreateWithFlags(&ev_fork, cudaEventDisableTiming);
        cudaEventCreateWithFlags(&ev_join, cudaEventDisableTiming);
    }
    cudaEventRecord(ev_fork, 0);
    cudaStreamWaitEvent(s_char, ev_fork, 0);

    // ======================= char path (stream s_char, tensor pipe) ==============
    cudaMemsetAsync(hist, 0, (Wc_ + 1) * sizeof(int), s_char);
    hist_k<<<NW_/256, 256, 0, s_char>>>(char_lens);
    scan_k<<<1, 32, 0, s_char>>>();
    scatter_k<<<NW_/256, 256, 0, s_char>>>(char_lens);
    split_remap_k<<<(CG_*CH_ + 255)/256, 256, 0, s_char>>>(c_Whh, Wc2);
    sgemm128<<<dim3(CG_/128, 1), 256, 0, s_char>>>(char_emb, c_Wih, P, 128, CG_, E_);
    reorderP_k<<<(128*CG_ + 255)/256, 256, 0, s_char>>>(c_b);
    char_gate0<<<dim3(CH_/256, NW_), 256, 0, s_char>>>(chars, hsA);
    for (int t = 1; t < Wc_; ++t) {
        const __nv_bfloat16* rd = ((t - 1) & 1) ? hsB : hsA;
        __nv_bfloat16*       wr = (t & 1)       ? hsB : hsA;
        hgemm_lstm<<<dim3(CG_/128, NW_/128), 256, HS_BYTES, s_char>>>(rd, Wc2, wr, chars, t);
    }
    cudaEventRecord(ev_join, s_char);

    // ======================= word path (capture stream, fp32 FMA pipe) ===========
    embed_words<<<NW_, E_>>>(words, word_emb);

    {   // layer 0 (K=256)
        const float* Wih0 = l0_Wih;
        const float* Wih1 = l0_Wih + (size_t)G_ * E_;
        const float* Whh0 = l0_Whh;
        const float* Whh1 = l0_Whh + (size_t)G_ * H_;
        sgemm128<<<dim3(G_/128, NW_/128), 256>>>(Xemb, Wih0, XGf, NW_, G_, E_);
        sgemm128<<<dim3(G_/128, NW_/128), 256>>>(Xemb, Wih1, XGb, NW_, G_, E_);
        cudaMemsetAsync(H0,  0, (size_t)NW_*CH_*sizeof(float), 0);
        cudaMemsetAsync(hpp, 0, (size_t)2*2*B_*H_*sizeof(float), 0);
        cudaMemsetAsync(bar, 0, sizeof(unsigned), 0);
        word_layer_persist<<<NBLK_, 256>>>(Whh0, Whh1, XGf, XGb, words_num, l0_b, H0);
    }
    {   // layer 1 (K=1024)
        const float* Wih0 = l1_Wih;
        const float* Wih1 = l1_Wih + (size_t)G_ * CH_;
        const float* Whh0 = l1_Whh;
        const float* Whh1 = l1_Whh + (size_t)G_ * H_;
        sgemm128<<<dim3(G_/128, NW_/128), 256>>>(H0, Wih0, XGf, NW_, G_, CH_);
        sgemm128<<<dim3(G_/128, NW_/128), 256>>>(H0, Wih1, XGb, NW_, G_, CH_);
        cudaMemsetAsync(H1,  0, (size_t)NW_*CH_*sizeof(float), 0);
        cudaMemsetAsync(hpp, 0, (size_t)2*2*B_*H_*sizeof(float), 0);
        cudaMemsetAsync(bar, 0, sizeof(unsigned), 0);
        word_layer_persist<<<NBLK_, 256>>>(Whh0, Whh1, XGf, XGb, words_num, l1_b, H1);
    }

    // ======================= join + head =========================
    cudaStreamWaitEvent(0, ev_join, 0);
    final_linear<<<NW_, 256>>>(words_num, lin_W, lin_b, out);
}

// round 10
// speedup vs baseline: 1.4641x; 1.2737x over previous
#include <cuda_runtime.h>
#include <cuda_fp16.h>
#include <cstdint>
#include <cstddef>

// Problem constants
#define B_   64
#define S_   128
#define Wc_  16
#define E_   256
#define H_   512
#define NC_  20
#define NW_  (B_*S_)        // 8192 words total
#define G_   (4*H_)         // 2048 word-LSTM gate width
#define CH_  (2*H_)         // 1024 char-LSTM hidden
#define CG_  (4*CH_)        // 4096 char-LSTM gate width

#define NBLK_ 128           // persistent word-layer blocks
#define LDS_  72            // hgemm smem halfword stride (64 + 8 pad)
#define HS_BYTES ((size_t)4 * 128 * LDS_ * sizeof(__half))   // 73728

// ---------------- scratch (static device globals; no allocation) ----------------
__device__ float g_Xemb[(size_t)NW_*E_];               // word embeddings  [8192,256]
__device__ float g_XGf [(size_t)NW_*G_];               // fwd x-gates      [8192,2048]
__device__ float g_XGb [(size_t)NW_*G_];               // bwd x-gates      [8192,2048]
__device__ float g_H0  [(size_t)NW_*CH_];              // layer0 out fp32
__device__ float g_H1  [(size_t)NW_*CH_];              // layer1 output    [8192,1024]
__device__ float g_hpp[(size_t)2*2*B_*H_];             // h ping-pong
__device__ unsigned g_bar;                             // grid barrier counter
__device__ float g_P  [(size_t)128*CG_];               // char_emb @ c_Wih.T (gate-major)
__device__ float g_Pp [(size_t)128*CG_];               // P interleaved j*4+g, + bias
__device__ float g_ch [(size_t)NW_*CH_];               // char h fp32 (sorted slots)
__device__ float g_cc [(size_t)NW_*CH_];               // char c state (sorted)
__device__ __half g_hsA[(size_t)NW_*CH_];              // char h fp16 buf A
__device__ __half g_hsB[(size_t)NW_*CH_];              // char h fp16 buf B
__device__ __half g_Wc2[(size_t)CG_*CH_];              // c_Whh fp16, rows j*4+g

// ---- length-sort bookkeeping ----
__device__ int g_hist[Wc_ + 1];
__device__ int g_off [Wc_ + 1];
__device__ int g_act [Wc_ + 1];
__device__ int g_perm [NW_];
__device__ int g_iperm[NW_];
__device__ int g_slen [NW_];

__device__ __forceinline__ float sigf(float x) { return 1.f / (1.f + __expf(-x)); }

__device__ __forceinline__ void cp16(void* dst, const void* src)
{
    uint32_t d = (uint32_t)__cvta_generic_to_shared(dst);
    asm volatile("cp.async.cg.shared.global [%0], [%1], 16;" :: "r"(d), "l"(src));
}

// ---------------- counting sort by char_lens (descending) ----------------
__global__ void hist_k(const int* __restrict__ clens)
{
    const int i = blockIdx.x * blockDim.x + threadIdx.x;
    if (i < NW_) atomicAdd(&g_hist[clens[i]], 1);
}
__global__ void scan_k()
{
    if (threadIdx.x == 0) {
        int off = 0;
        for (int len = Wc_; len >= 1; --len) { g_off[len] = off; off += g_hist[len]; }
        for (int t = 0; t <= Wc_; ++t) {
            int a = 0;
            for (int l = t + 1; l <= Wc_; ++l) a += g_hist[l];
            g_act[t] = a;
        }
    }
}
__global__ void scatter_k(const int* __restrict__ clens)
{
    const int i = blockIdx.x * blockDim.x + threadIdx.x;
    if (i < NW_) {
        const int len = clens[i];
        const int s = atomicAdd(&g_off[len], 1);
        g_perm[s] = i;
        g_iperm[i] = s;
        g_slen[s] = len;
    }
}

// c_Whh -> fp16 with gate-interleaved row remap: src row r = g*CH+j -> dst row j*4+g
__global__ void half_remap_k(const float* __restrict__ src, __half* __restrict__ dst)
{
    const int i = blockIdx.x * blockDim.x + threadIdx.x;
    if (i >= CG_ * CH_) return;
    const int r = i / CH_, k = i % CH_;
    const int g = r / CH_, j = r % CH_;
    const int outr = j * 4 + g;
    dst[(size_t)outr * CH_ + k] = __float2half(src[i]);
}

// P reorder to interleaved + fold bias: Pp[tok][j*4+g] = P[tok][g*CH+j] + c_b[g*CH+j]
__global__ void reorderP_k(const float* __restrict__ cbias)
{
    const int i = blockIdx.x * blockDim.x + threadIdx.x;
    if (i >= 128 * CG_) return;
    const int tok = i / CG_, col = i % CG_;
    const int j = col >> 2, g = col & 3;
    const int src = g * CH_ + j;
    g_Pp[i] = g_P[(size_t)tok * CG_ + src] + cbias[src];
}

// ========== fused char-LSTM GEMM step: Z = h_{t-1} @ Wc2^T, then cell update ====
// fp16 operands (K=1024), 128x128 tile, 8 warps, BK=64, cp.async double buffer,
// mma.m16n8k16.f16, fp32 accumulate. B rows gate-interleaved (j*4+g).
// Epilogue applies LSTM cell, writes cc/ch (fp32) + fp16 h into hsW.
__global__ __launch_bounds__(256)
void hgemm_lstm(const __half* __restrict__ A,   // hsRead [8192,1024]
                const __half* __restrict__ Bm,  // g_Wc2 [4096,1024]
                __half* __restrict__ hsW,       // hsWrite
                const int* __restrict__ chars, int t)
{
    const int act_t = g_act[t];
    const int row0 = blockIdx.y * 128;
    if (row0 >= act_t) return;
    const int col0 = blockIdx.x * 128;
    const int K = CH_;                  // 1024

    extern __shared__ __half smem_[];
    __half* const sA[2] = { smem_,                smem_ + 2*128*LDS_ };
    __half* const sB[2] = { smem_ + 128*LDS_,     smem_ + 3*128*LDS_ };

    const int tid  = threadIdx.x;
    const int lane = tid & 31;
    const int wid  = tid >> 5;
    const int wm   = (wid & 1) * 64;
    const int wn   = (wid >> 1) * 32;

    const int lr = tid >> 1;
    const int cb = (tid & 1) * 4;

    float acc[4][4][4];
#pragma unroll
    for (int mi = 0; mi < 4; ++mi)
#pragma unroll
        for (int ni = 0; ni < 4; ++ni)
#pragma unroll
            for (int f = 0; f < 4; ++f) acc[mi][ni][f] = 0.f;

    const int KT = K >> 6;              // 16

    {
        const __half* Ap = A  + (size_t)(row0 + lr) * K + cb * 8;
        const __half* Bp = Bm + (size_t)(col0 + lr) * K + cb * 8;
#pragma unroll
        for (int c = 0; c < 4; ++c) {
            cp16(&sA[0][lr * LDS_ + (cb + c) * 8], Ap + c * 8);
            cp16(&sB[0][lr * LDS_ + (cb + c) * 8], Bp + c * 8);
        }
        asm volatile("cp.async.commit_group;");
    }

    for (int kt = 0; kt < KT; ++kt) {
        const int buf = kt & 1;
        if (kt + 1 < KT) {
            const int k0 = (kt + 1) << 6;
            const __half* Ap = A  + (size_t)(row0 + lr) * K + k0 + cb * 8;
            const __half* Bp = Bm + (size_t)(col0 + lr) * K + k0 + cb * 8;
#pragma unroll
            for (int c = 0; c < 4; ++c) {
                cp16(&sA[buf ^ 1][lr * LDS_ + (cb + c) * 8], Ap + c * 8);
                cp16(&sB[buf ^ 1][lr * LDS_ + (cb + c) * 8], Bp + c * 8);
            }
            asm volatile("cp.async.commit_group;");
            asm volatile("cp.async.wait_group 1;");
        } else {
            asm volatile("cp.async.wait_group 0;");
        }
        __syncthreads();

        const __half* As = sA[buf];
        const __half* Bs = sB[buf];
#pragma unroll
        for (int ks = 0; ks < 4; ++ks) {
            uint32_t a[4][4], b[4][2];
#pragma unroll
            for (int mi = 0; mi < 4; ++mi) {
                uint32_t addr = (uint32_t)__cvta_generic_to_shared(
                    &As[(wm + mi*16 + (lane & 15)) * LDS_ + ks*16 + (lane >> 4) * 8]);
                asm volatile("ldmatrix.sync.aligned.m8n8.x4.shared.b16 {%0,%1,%2,%3}, [%4];"
                    : "=r"(a[mi][0]), "=r"(a[mi][1]), "=r"(a[mi][2]), "=r"(a[mi][3])
                    : "r"(addr));
            }
#pragma unroll
            for (int ni = 0; ni < 4; ++ni) {
                uint32_t addr = (uint32_t)__cvta_generic_to_shared(
                    &Bs[(wn + ni*8 + (lane & 7)) * LDS_ + ks*16 + ((lane >> 3) & 1) * 8]);
                asm volatile("ldmatrix.sync.aligned.m8n8.x2.shared.b16 {%0,%1}, [%2];"
                    : "=r"(b[ni][0]), "=r"(b[ni][1]) : "r"(addr));
            }
#pragma unroll
            for (int mi = 0; mi < 4; ++mi)
#pragma unroll
                for (int ni = 0; ni < 4; ++ni) {
                    asm volatile(
                        "mma.sync.aligned.m16n8k16.row.col.f32.f16.f16.f32 "
                        "{%0,%1,%2,%3}, {%4,%5,%6,%7}, {%8,%9}, {%0,%1,%2,%3};"
                        : "+f"(acc[mi][ni][0]), "+f"(acc[mi][ni][1]),
                          "+f"(acc[mi][ni][2]), "+f"(acc[mi][ni][3])
                        : "r"(a[mi][0]), "r"(a[mi][1]), "r"(a[mi][2]), "r"(a[mi][3]),
                          "r"(b[ni][0]), "r"(b[ni][1]));
                }
        }
        __syncthreads();
    }

    // ---- fused LSTM cell epilogue ----
    float* Sg = (float*)smem_;          // 128 x 132 fp32 = 67584 B
#pragma unroll
    for (int mi = 0; mi < 4; ++mi)
#pragma unroll
        for (int ni = 0; ni < 4; ++ni) {
            const int r = wm + mi*16 + (lane >> 2);
            const int c = wn + ni*8 + (lane & 3) * 2;
            Sg[r * 132 + c]           = acc[mi][ni][0];
            Sg[r * 132 + c + 1]       = acc[mi][ni][1];
            Sg[(r + 8) * 132 + c]     = acc[mi][ni][2];
            Sg[(r + 8) * 132 + c + 1] = acc[mi][ni][3];
        }
    __syncthreads();

    const int jb = col0 >> 2;           // 32 j per tile
#pragma unroll
    for (int q = 0; q < 16; ++q) {
        const int cid = tid + q * 256;
        const int nl = cid >> 5, jl = cid & 31;
        const int n = row0 + nl;
        if (n >= act_t) continue;
        const int j = jb + jl;
        float4 z = *(float4*)&Sg[nl * 132 + jl * 4];
        const int tok = chars[g_perm[n] * Wc_ + t];
        float4 p = *(const float4*)&g_Pp[(size_t)tok * CG_ + j * 4];
        const float zi = z.x + p.x, zf = z.y + p.y, zg = z.z + p.z, zo = z.w + p.w;
        const float c_old = g_cc[(size_t)n * CH_ + j];
        const float cn = sigf(zf) * c_old + sigf(zi) * tanhf(zg);
        const float hn = sigf(zo) * tanhf(cn);
        g_cc[(size_t)n * CH_ + j] = cn;
        g_ch[(size_t)n * CH_ + j] = hn;
        hsW[(size_t)n * CH_ + j] = __float2half(hn);
    }
}

// ---------------- char t=0 gate (all slots active; c_prev = 0) ----------------
__global__ void char_gate0(const int* __restrict__ chars, __half* __restrict__ hsW)
{
    const int n = blockIdx.y;
    const int j = blockIdx.x * blockDim.x + threadIdx.x;   // 0..1023
    const int tok = chars[g_perm[n] * Wc_ + 0];
    float4 p = *(const float4*)&g_Pp[(size_t)tok * CG_ + j * 4];
    const float cn = sigf(p.x) * tanhf(p.z);
    const float hn = sigf(p.w) * tanhf(cn);
    g_cc[(size_t)n * CH_ + j] = cn;
    g_ch[(size_t)n * CH_ + j] = hn;
    hsW[(size_t)n * CH_ + j] = __float2half(hn);
}

// ---------------- fp32 SGEMM: C[M,N] = A[M,K] @ B[N,K]^T ----------------
__global__ __launch_bounds__(256)
void sgemm128(const float* __restrict__ A, const float* __restrict__ Bm,
              float* __restrict__ C, int M, int N, int K)
{
    __shared__ float As[8][128];
    __shared__ float Bs[8][128];
    const int tid = threadIdx.x;
    const int tx  = tid & 15;
    const int ty  = tid >> 4;
    const int row0 = blockIdx.y * 128;
    const int col0 = blockIdx.x * 128;
    const int lr = tid >> 1;
    const int lk = (tid & 1) * 4;

    const float* Ap = A  + (size_t)(row0 + lr) * K + lk;
    const float* Bp = Bm + (size_t)(col0 + lr) * K + lk;

    float acc[8][8];
#pragma unroll
    for (int i = 0; i < 8; ++i)
#pragma unroll
        for (int j = 0; j < 8; ++j) acc[i][j] = 0.f;

    {
        float4 a = *(const float4*)Ap;
        float4 b = *(const float4*)Bp;
        As[lk+0][lr] = a.x; As[lk+1][lr] = a.y; As[lk+2][lr] = a.z; As[lk+3][lr] = a.w;
        Bs[lk+0][lr] = b.x; Bs[lk+1][lr] = b.y; Bs[lk+2][lr] = b.z; Bs[lk+3][lr] = b.w;
    }
    __syncthreads();

    int k0 = 0;
    while (true) {
        const int kn = k0 + 8;
        const bool more = kn < K;
        float4 an, bn;
        if (more) { an = *(const float4*)(Ap + kn); bn = *(const float4*)(Bp + kn); }
#pragma unroll
        for (int k = 0; k < 8; ++k) {
            float4 a0 = *(const float4*)&As[k][ty*8];
            float4 a1 = *(const float4*)&As[k][ty*8+4];
            float4 b0 = *(const float4*)&Bs[k][tx*8];
            float4 b1 = *(const float4*)&Bs[k][tx*8+4];
            float av[8] = {a0.x,a0.y,a0.z,a0.w,a1.x,a1.y,a1.z,a1.w};
            float bv[8] = {b0.x,b0.y,b0.z,b0.w,b1.x,b1.y,b1.z,b1.w};
#pragma unroll
            for (int i = 0; i < 8; ++i)
#pragma unroll
                for (int j = 0; j < 8; ++j)
                    acc[i][j] = fmaf(av[i], bv[j], acc[i][j]);
        }
        if (!more) break;
        __syncthreads();
        As[lk+0][lr] = an.x; As[lk+1][lr] = an.y; As[lk+2][lr] = an.z; As[lk+3][lr] = an.w;
        Bs[lk+0][lr] = bn.x; Bs[lk+1][lr] = bn.y; Bs[lk+2][lr] = bn.z; Bs[lk+3][lr] = bn.w;
        __syncthreads();
        k0 = kn;
    }

#pragma unroll
    for (int i = 0; i < 8; ++i) {
        const int r = row0 + ty*8 + i;
        float4 o0, o1;
        o0.x = acc[i][0]; o0.y = acc[i][1]; o0.z = acc[i][2]; o0.w = acc[i][3];
        o1.x = acc[i][4]; o1.y = acc[i][5]; o1.z = acc[i][6]; o1.w = acc[i][7];
        *(float4*)(C + (size_t)r*N + col0 + tx*8)     = o0;
        *(float4*)(C + (size_t)r*N + col0 + tx*8 + 4) = o1;
    }
}

// ---------------- persistent word BiLSTM layer (fp32) ----------------
__global__ __launch_bounds__(256)
void word_layer_persist(const float* __restrict__ Whh0, const float* __restrict__ Whh1,
                        const float* __restrict__ XGf, const float* __restrict__ XGb,
                        const int* __restrict__ lens, const float* __restrict__ bias,
                        float* __restrict__ Hout)
{
    __shared__ float hs[64][68];
    __shared__ float ws[32][68];

    const int tid = threadIdx.x;
    const int jj  = tid & 7;
    const int bb  = tid >> 3;             // 0..31
    const int dir = blockIdx.x >> 6;
    const int jt  = (blockIdx.x & 63) << 3;
    const int j   = jt + jj;

    const float* W  = dir ? Whh1 : Whh0;
    const float* XG = dir ? XGb : XGf;
    const float* bv = bias + (size_t)dir * G_;
    float bg[4];
#pragma unroll
    for (int g = 0; g < 4; ++g) bg[g] = bv[g * H_ + j];

    const int len0 = lens[bb];
    const int len1 = lens[bb + 32];

    float hreg0 = 0.f, creg0 = 0.f;
    float hreg1 = 0.f, creg1 = 0.f;

    for (int t = 0; t < S_; ++t) {
        const float* hcur = g_hpp + (size_t)(((t    ) & 1) * 2 + dir) * (B_*H_);
        float*       hnxt = g_hpp + (size_t)(((t + 1) & 1) * 2 + dir) * (B_*H_);

        float acc[2][4];
#pragma unroll
        for (int b2 = 0; b2 < 2; ++b2)
#pragma unroll
            for (int g = 0; g < 4; ++g) acc[b2][g] = 0.f;

        for (int k0 = 0; k0 < H_; k0 += 64) {
#pragma unroll
            for (int i = 0; i < 4; ++i) {
                const int idx = tid + i * 256;
                const int r = idx >> 4, c = idx & 15;
                float4 v = __ldcg((const float4*)(hcur + (size_t)r * H_ + k0 + c * 4));
                *(float4*)&hs[r][c * 4] = v;
            }
#pragma unroll
            for (int i = 0; i < 2; ++i) {
                const int idx = tid + i * 256;
                const int w = idx >> 4, c = idx & 15;
                const int g = w >> 3, jl = w & 7;
                float4 v = *(const float4*)(W + (size_t)(g * H_ + jt + jl) * H_ + k0 + c * 4);
                *(float4*)&ws[w][c * 4] = v;
            }
            __syncthreads();
#pragma unroll
            for (int k4 = 0; k4 < 16; ++k4) {
                float4 a0 = *(const float4*)&hs[bb][k4 * 4];
                float4 a1 = *(const float4*)&hs[bb + 32][k4 * 4];
#pragma unroll
                for (int g = 0; g < 4; ++g) {
                    float4 w4 = *(const float4*)&ws[g * 8 + jj][k4 * 4];
                    acc[0][g] = fmaf(a0.x, w4.x, acc[0][g]);
                    acc[0][g] = fmaf(a0.y, w4.y, acc[0][g]);
                    acc[0][g] = fmaf(a0.z, w4.z, acc[0][g]);
                    acc[0][g] = fmaf(a0.w, w4.w, acc[0][g]);
                    acc[1][g] = fmaf(a1.x, w4.x, acc[1][g]);
                    acc[1][g] = fmaf(a1.y, w4.y, acc[1][g]);
                    acc[1][g] = fmaf(a1.z, w4.z, acc[1][g]);
                    acc[1][g] = fmaf(a1.w, w4.w, acc[1][g]);
                }
            }
            __syncthreads();
        }

#pragma unroll
        for (int b2 = 0; b2 < 2; ++b2) {
            const int b = bb + b2 * 32;
            const int len = b2 ? len1 : len0;
            const bool valid = t < len;
            const int src = (dir == 0) ? t : (valid ? (len - 1 - t) : t);
            const float* xg = XG + (size_t)(b * S_ + src) * G_ + jt + jj;
            float zi = acc[b2][0] + xg[0]      + bg[0];
            float zf = acc[b2][1] + xg[H_]     + bg[1];
            float zg = acc[b2][2] + xg[2*H_]   + bg[2];
            float zo = acc[b2][3] + xg[3*H_]   + bg[3];
            float c_old = b2 ? creg1 : creg0;
            float cn = sigf(zf) * c_old + sigf(zi) * tanhf(zg);
            float hn = sigf(zo) * tanhf(cn);
            float h_old = b2 ? hreg1 : hreg0;
            float h_out = valid ? hn : h_old;
            float c_out = valid ? cn : c_old;
            if (b2) { hreg1 = h_out; creg1 = c_out; }
            else    { hreg0 = h_out; creg0 = c_out; }
            __stcg(hnxt + (size_t)b * H_ + j, h_out);
            if (dir == 0) {
                Hout[(size_t)(b * S_ + t) * CH_ + j] = valid ? hn : 0.f;
            } else if (valid) {
                Hout[(size_t)(b * S_ + src) * CH_ + H_ + j] = hn;
            }
        }

        if (t < S_ - 1) {
            __syncthreads();
            if (tid == 0) {
                __threadfence();
                atomicAdd(&g_bar, 1u);
                const unsigned tgt = (unsigned)(t + 1) * (unsigned)NBLK_;
                volatile unsigned* p = &g_bar;
                while (*p < tgt) __nanosleep(64);
            }
            __syncthreads();
        }
    }
}

// ---------------- word embedding gather (fp32) ----------------
__global__ void embed_words(const int* __restrict__ words, const float* __restrict__ emb)
{
    const int m = blockIdx.x;
    const int e = threadIdx.x;
    g_Xemb[(size_t)m*E_ + e] = emb[(size_t)words[m] * E_ + e];
}

// ---------------- final head ----------------
__global__ __launch_bounds__(256)
void final_linear(const int* __restrict__ wnum, const float* __restrict__ W,
                  const float* __restrict__ bias, float* __restrict__ out)
{
    const int row = blockIdx.x;         // 0..8191
    const int b = row >> 7;
    const int s = row & (S_ - 1);
    const bool valid = s < wnum[b];
    const int slot = g_iperm[row];
    __shared__ float v[CH_];
    __shared__ float sred[8*NC_];
    const int tid = threadIdx.x;
    for (int j = tid; j < CH_; j += 256) {
        float x = g_H1[(size_t)row*CH_ + j];
        if (valid) x += g_ch[(size_t)slot*CH_ + j];
        v[j] = x;
    }
    __syncthreads();
    float acc[NC_];
#pragma unroll
    for (int c2 = 0; c2 < NC_; ++c2) acc[c2] = 0.f;
    for (int j = tid; j < CH_; j += 256) {
        float x = v[j];
#pragma unroll
        for (int c2 = 0; c2 < NC_; ++c2)
            acc[c2] = fmaf(x, W[c2*CH_ + j], acc[c2]);
    }
#pragma unroll
    for (int c2 = 0; c2 < NC_; ++c2)
#pragma unroll
        for (int off = 16; off > 0; off >>= 1)
            acc[c2] += __shfl_down_sync(0xffffffffu, acc[c2], off);
    const int lane = tid & 31, w = tid >> 5;
    if (lane == 0)
#pragma unroll
        for (int c2 = 0; c2 < NC_; ++c2) sred[w*NC_ + c2] = acc[c2];
    __syncthreads();
    if (tid < NC_) {
        float sum = bias[tid];
#pragma unroll
        for (int w2 = 0; w2 < 8; ++w2) sum += sred[w2*NC_ + tid];
        out[(size_t)row*NC_ + tid] = sum;
    }
}

// ================================================================================
extern "C" void kernel_launch(void* const* d_in, const int* in_sizes, int n_in,
                              void* d_out, int out_size)
{
    (void)in_sizes; (void)n_in; (void)out_size;
    const int*   words     = (const int*)  d_in[0];
    const int*   words_num = (const int*)  d_in[1];
    const int*   chars     = (const int*)  d_in[2];
    const int*   char_lens = (const int*)  d_in[3];
    const float* word_emb  = (const float*)d_in[4];
    const float* char_emb  = (const float*)d_in[5];
    const float* l0_Wih    = (const float*)d_in[6];
    const float* l0_Whh    = (const float*)d_in[7];
    const float* l0_b      = (const float*)d_in[8];
    const float* l1_Wih    = (const float*)d_in[9];
    const float* l1_Whh    = (const float*)d_in[10];
    const float* l1_b      = (const float*)d_in[11];
    const float* c_Wih     = (const float*)d_in[12];
    const float* c_Whh     = (const float*)d_in[13];
    const float* c_b       = (const float*)d_in[14];
    const float* lin_W     = (const float*)d_in[15];
    const float* lin_b     = (const float*)d_in[16];
    float* out = (float*)d_out;

    float *Xemb, *XGf, *XGb, *H0, *H1, *hpp, *P;
    __half *hsA, *hsB, *Wc2;
    unsigned* bar;
    int *hist;
    cudaGetSymbolAddress((void**)&Xemb, g_Xemb);
    cudaGetSymbolAddress((void**)&XGf,  g_XGf);
    cudaGetSymbolAddress((void**)&XGb,  g_XGb);
    cudaGetSymbolAddress((void**)&H0,   g_H0);
    cudaGetSymbolAddress((void**)&H1,   g_H1);
    cudaGetSymbolAddress((void**)&hpp,  g_hpp);
    cudaGetSymbolAddress((void**)&bar,  g_bar);
    cudaGetSymbolAddress((void**)&P,    g_P);
    cudaGetSymbolAddress((void**)&hsA,  g_hsA);
    cudaGetSymbolAddress((void**)&hsB,  g_hsB);
    cudaGetSymbolAddress((void**)&Wc2,  g_Wc2);
    cudaGetSymbolAddress((void**)&hist, g_hist);

    cudaFuncSetAttribute(hgemm_lstm, cudaFuncAttributeMaxDynamicSharedMemorySize, (int)HS_BYTES);

    // ---- fork-join streams (char path on s_char, word path on capture stream) ----
    static cudaStream_t s_char = nullptr;
    static cudaEvent_t ev_fork = nullptr, ev_join = nullptr;
    if (!s_char) {
        cudaStreamCreateWithFlags(&s_char, cudaStreamNonBlocking);
        cudaEventCreateWithFlags(&ev_fork, cudaEventDisableTiming);
        cudaEventCreateWithFlags(&ev_join, cudaEventDisableTiming);
    }
    cudaEventRecord(ev_fork, 0);
    cudaStreamWaitEvent(s_char, ev_fork, 0);

    // ======================= char path (stream s_char, tensor pipe) ==============
    cudaMemsetAsync(hist, 0, (Wc_ + 1) * sizeof(int), s_char);
    hist_k<<<NW_/256, 256, 0, s_char>>>(char_lens);
    scan_k<<<1, 32, 0, s_char>>>();
    scatter_k<<<NW_/256, 256, 0, s_char>>>(char_lens);
    half_remap_k<<<(CG_*CH_ + 255)/256, 256, 0, s_char>>>(c_Whh, Wc2);
    sgemm128<<<dim3(CG_/128, 1), 256, 0, s_char>>>(char_emb, c_Wih, P, 128, CG_, E_);
    reorderP_k<<<(128*CG_ + 255)/256, 256, 0, s_char>>>(c_b);
    char_gate0<<<dim3(CH_/256, NW_), 256, 0, s_char>>>(chars, hsA);
    for (int t = 1; t < Wc_; ++t) {
        const __half* rd = ((t - 1) & 1) ? hsB : hsA;
        __half*       wr = (t & 1)       ? hsB : hsA;
        hgemm_lstm<<<dim3(CG_/128, NW_/128), 256, HS_BYTES, s_char>>>(rd, Wc2, wr, chars, t);
    }
    cudaEventRecord(ev_join, s_char);

    // ======================= word path (capture stream, fp32 FMA pipe) ===========
    embed_words<<<NW_, E_>>>(words, word_emb);

    {   // layer 0 (K=256)
        const float* Wih0 = l0_Wih;
        const float* Wih1 = l0_Wih + (size_t)G_ * E_;
        const float* Whh0 = l0_Whh;
        const float* Whh1 = l0_Whh + (size_t)G_ * H_;
        sgemm128<<<dim3(G_/128, NW_/128), 256>>>(Xemb, Wih0, XGf, NW_, G_, E_);
        sgemm128<<<dim3(G_/128, NW_/128), 256>>>(Xemb, Wih1, XGb, NW_, G_, E_);
        cudaMemsetAsync(H0,  0, (size_t)NW_*CH_*sizeof(float), 0);
        cudaMemsetAsync(hpp, 0, (size_t)2*2*B_*H_*sizeof(float), 0);
        cudaMemsetAsync(bar, 0, sizeof(unsigned), 0);
        word_layer_persist<<<NBLK_, 256>>>(Whh0, Whh1, XGf, XGb, words_num, l0_b, H0);
    }
    {   // layer 1 (K=1024)
        const float* Wih0 = l1_Wih;
        const float* Wih1 = l1_Wih + (size_t)G_ * CH_;
        const float* Whh0 = l1_Whh;
        const float* Whh1 = l1_Whh + (size_t)G_ * H_;
        sgemm128<<<dim3(G_/128, NW_/128), 256>>>(H0, Wih0, XGf, NW_, G_, CH_);
        sgemm128<<<dim3(G_/128, NW_/128), 256>>>(H0, Wih1, XGb, NW_, G_, CH_);
        cudaMemsetAsync(H1,  0, (size_t)NW_*CH_*sizeof(float), 0);
        cudaMemsetAsync(hpp, 0, (size_t)2*2*B_*H_*sizeof(float), 0);
        cudaMemsetAsync(bar, 0, sizeof(unsigned), 0);
        word_layer_persist<<<NBLK_, 256>>>(Whh0, Whh1, XGf, XGb, words_num, l1_b, H1);
    }

    // ======================= join + head =========================
    cudaStreamWaitEvent(0, ev_join, 0);
    final_linear<<<NW_, 256>>>(words_num, lin_W, lin_b, out);
}

// round 11
// speedup vs baseline: 1.7058x; 1.1651x over previous
#include <cuda_runtime.h>
#include <cuda_fp16.h>
#include <cstdint>
#include <cstddef>

// Problem constants
#define B_   64
#define S_   128
#define Wc_  16
#define E_   256
#define H_   512
#define NC_  20
#define NW_  (B_*S_)        // 8192 words total
#define G_   (4*H_)         // 2048 word-LSTM gate width
#define CH_  (2*H_)         // 1024 char-LSTM hidden
#define CG_  (4*CH_)        // 4096 char-LSTM gate width

#define NBLK_ 128           // persistent word-layer blocks
#define LDS_  72            // hgemm smem halfword stride (64 + 8 pad)
#define HS_BYTES ((size_t)4 * 128 * LDS_ * sizeof(__half))   // 73728

// ---------------- scratch (static device globals; no allocation) ----------------
__device__ __half g_XembH[(size_t)NW_*E_];             // word embeddings fp16
__device__ __half g_Wih0H[(size_t)2*G_*E_];            // l0_Wih fp16 [2][2048,256]
__device__ __half g_Wih1H[(size_t)2*G_*CH_];           // l1_Wih fp16 [2][2048,1024]
__device__ float g_XGf [(size_t)NW_*G_];               // fwd x-gates      [8192,2048]
__device__ float g_XGb [(size_t)NW_*G_];               // bwd x-gates      [8192,2048]
__device__ float g_H0  [(size_t)NW_*CH_];              // layer0 out fp32
__device__ __half g_H0h[(size_t)NW_*CH_];              // layer0 out fp16
__device__ float g_H1  [(size_t)NW_*CH_];              // layer1 output    [8192,1024]
__device__ float g_hpp[(size_t)2*2*B_*H_];             // h ping-pong
__device__ unsigned g_bar;                             // grid barrier counter
__device__ float g_P  [(size_t)128*CG_];               // char_emb @ c_Wih.T (gate-major)
__device__ float g_Pp [(size_t)128*CG_];               // P interleaved j*4+g, + bias
__device__ float g_ch [(size_t)NW_*CH_];               // char h fp32 (sorted slots)
__device__ float g_cc [(size_t)NW_*CH_];               // char c state (sorted)
__device__ __half g_hsA[(size_t)NW_*CH_];              // char h fp16 buf A
__device__ __half g_hsB[(size_t)NW_*CH_];              // char h fp16 buf B
__device__ __half g_Wc2[(size_t)CG_*CH_];              // c_Whh fp16, rows j*4+g

// ---- length-sort bookkeeping ----
__device__ int g_hist[Wc_ + 1];
__device__ int g_off [Wc_ + 1];
__device__ int g_act [Wc_ + 1];
__device__ int g_perm [NW_];
__device__ int g_iperm[NW_];
__device__ int g_slen [NW_];

__device__ __forceinline__ float sigf(float x) { return 1.f / (1.f + __expf(-x)); }

__device__ __forceinline__ void cp16(void* dst, const void* src)
{
    uint32_t d = (uint32_t)__cvta_generic_to_shared(dst);
    asm volatile("cp.async.cg.shared.global [%0], [%1], 16;" :: "r"(d), "l"(src));
}

// ---------------- counting sort by char_lens (descending) ----------------
__global__ void hist_k(const int* __restrict__ clens)
{
    const int i = blockIdx.x * blockDim.x + threadIdx.x;
    if (i < NW_) atomicAdd(&g_hist[clens[i]], 1);
}
__global__ void scan_k()
{
    if (threadIdx.x == 0) {
        int off = 0;
        for (int len = Wc_; len >= 1; --len) { g_off[len] = off; off += g_hist[len]; }
        for (int t = 0; t <= Wc_; ++t) {
            int a = 0;
            for (int l = t + 1; l <= Wc_; ++l) a += g_hist[l];
            g_act[t] = a;
        }
    }
}
__global__ void scatter_k(const int* __restrict__ clens)
{
    const int i = blockIdx.x * blockDim.x + threadIdx.x;
    if (i < NW_) {
        const int len = clens[i];
        const int s = atomicAdd(&g_off[len], 1);
        g_perm[s] = i;
        g_iperm[i] = s;
        g_slen[s] = len;
    }
}

// generic fp32 -> fp16 copy
__global__ void half_k(const float* __restrict__ src, __half* __restrict__ dst, int total)
{
    const int i = blockIdx.x * blockDim.x + threadIdx.x;
    if (i < total) dst[i] = __float2half(src[i]);
}

// c_Whh -> fp16 with gate-interleaved row remap: src row r = g*CH+j -> dst row j*4+g
__global__ void half_remap_k(const float* __restrict__ src, __half* __restrict__ dst)
{
    const int i = blockIdx.x * blockDim.x + threadIdx.x;
    if (i >= CG_ * CH_) return;
    const int r = i / CH_, k = i % CH_;
    const int g = r / CH_, j = r % CH_;
    const int outr = j * 4 + g;
    dst[(size_t)outr * CH_ + k] = __float2half(src[i]);
}

// P reorder to interleaved + fold bias: Pp[tok][j*4+g] = P[tok][g*CH+j] + c_b[g*CH+j]
__global__ void reorderP_k(const float* __restrict__ cbias)
{
    const int i = blockIdx.x * blockDim.x + threadIdx.x;
    if (i >= 128 * CG_) return;
    const int tok = i / CG_, col = i % CG_;
    const int j = col >> 2, g = col & 3;
    const int src = g * CH_ + j;
    g_Pp[i] = g_P[(size_t)tok * CG_ + src] + cbias[src];
}

// ---------------- fp16 tensor-core GEMM: C[M,N] = A[M,K] @ B[N,K]^T (fp32 C) ----
// 128x128 tile, 8 warps (2x4), warp tile 64x32, BK=64, cp.async double buffer,
// mma.m16n8k16.f16, fp32 accumulate. Requires M%128==0, N%128==0, K%64==0.
__global__ __launch_bounds__(256)
void hgemm_f(const __half* __restrict__ A, const __half* __restrict__ Bm,
             float* __restrict__ C, int M, int N, int K)
{
    const int row0 = blockIdx.y * 128;
    const int col0 = blockIdx.x * 128;

    extern __shared__ __half smem_[];
    __half* const sA[2] = { smem_,                smem_ + 2*128*LDS_ };
    __half* const sB[2] = { smem_ + 128*LDS_,     smem_ + 3*128*LDS_ };

    const int tid  = threadIdx.x;
    const int lane = tid & 31;
    const int wid  = tid >> 5;
    const int wm   = (wid & 1) * 64;
    const int wn   = (wid >> 1) * 32;

    const int lr = tid >> 1;
    const int cb = (tid & 1) * 4;

    float acc[4][4][4];
#pragma unroll
    for (int mi = 0; mi < 4; ++mi)
#pragma unroll
        for (int ni = 0; ni < 4; ++ni)
#pragma unroll
            for (int f = 0; f < 4; ++f) acc[mi][ni][f] = 0.f;

    const int KT = K >> 6;

    {
        const __half* Ap = A  + (size_t)(row0 + lr) * K + cb * 8;
        const __half* Bp = Bm + (size_t)(col0 + lr) * K + cb * 8;
#pragma unroll
        for (int c = 0; c < 4; ++c) {
            cp16(&sA[0][lr * LDS_ + (cb + c) * 8], Ap + c * 8);
            cp16(&sB[0][lr * LDS_ + (cb + c) * 8], Bp + c * 8);
        }
        asm volatile("cp.async.commit_group;");
    }

    for (int kt = 0; kt < KT; ++kt) {
        const int buf = kt & 1;
        if (kt + 1 < KT) {
            const int k0 = (kt + 1) << 6;
            const __half* Ap = A  + (size_t)(row0 + lr) * K + k0 + cb * 8;
            const __half* Bp = Bm + (size_t)(col0 + lr) * K + k0 + cb * 8;
#pragma unroll
            for (int c = 0; c < 4; ++c) {
                cp16(&sA[buf ^ 1][lr * LDS_ + (cb + c) * 8], Ap + c * 8);
                cp16(&sB[buf ^ 1][lr * LDS_ + (cb + c) * 8], Bp + c * 8);
            }
            asm volatile("cp.async.commit_group;");
            asm volatile("cp.async.wait_group 1;");
        } else {
            asm volatile("cp.async.wait_group 0;");
        }
        __syncthreads();

        const __half* As = sA[buf];
        const __half* Bs = sB[buf];
#pragma unroll
        for (int ks = 0; ks < 4; ++ks) {
            uint32_t a[4][4], b[4][2];
#pragma unroll
            for (int mi = 0; mi < 4; ++mi) {
                uint32_t addr = (uint32_t)__cvta_generic_to_shared(
                    &As[(wm + mi*16 + (lane & 15)) * LDS_ + ks*16 + (lane >> 4) * 8]);
                asm volatile("ldmatrix.sync.aligned.m8n8.x4.shared.b16 {%0,%1,%2,%3}, [%4];"
                    : "=r"(a[mi][0]), "=r"(a[mi][1]), "=r"(a[mi][2]), "=r"(a[mi][3])
                    : "r"(addr));
            }
#pragma unroll
            for (int ni = 0; ni < 4; ++ni) {
                uint32_t addr = (uint32_t)__cvta_generic_to_shared(
                    &Bs[(wn + ni*8 + (lane & 7)) * LDS_ + ks*16 + ((lane >> 3) & 1) * 8]);
                asm volatile("ldmatrix.sync.aligned.m8n8.x2.shared.b16 {%0,%1}, [%2];"
                    : "=r"(b[ni][0]), "=r"(b[ni][1]) : "r"(addr));
            }
#pragma unroll
            for (int mi = 0; mi < 4; ++mi)
#pragma unroll
                for (int ni = 0; ni < 4; ++ni) {
                    asm volatile(
                        "mma.sync.aligned.m16n8k16.row.col.f32.f16.f16.f32 "
                        "{%0,%1,%2,%3}, {%4,%5,%6,%7}, {%8,%9}, {%0,%1,%2,%3};"
                        : "+f"(acc[mi][ni][0]), "+f"(acc[mi][ni][1]),
                          "+f"(acc[mi][ni][2]), "+f"(acc[mi][ni][3])
                        : "r"(a[mi][0]), "r"(a[mi][1]), "r"(a[mi][2]), "r"(a[mi][3]),
                          "r"(b[ni][0]), "r"(b[ni][1]));
                }
        }
        __syncthreads();
    }

#pragma unroll
    for (int mi = 0; mi < 4; ++mi)
#pragma unroll
        for (int ni = 0; ni < 4; ++ni) {
            const int r = row0 + wm + mi*16 + (lane >> 2);
            const int c = col0 + wn + ni*8 + (lane & 3) * 2;
            float2 v0 = make_float2(acc[mi][ni][0], acc[mi][ni][1]);
            float2 v1 = make_float2(acc[mi][ni][2], acc[mi][ni][3]);
            *(float2*)&C[(size_t)r * N + c]       = v0;
            *(float2*)&C[(size_t)(r + 8) * N + c] = v1;
        }
}

// ========== fused char-LSTM GEMM step: Z = h_{t-1} @ Wc2^T, then cell update ====
__global__ __launch_bounds__(256)
void hgemm_lstm(const __half* __restrict__ A,   // hsRead [8192,1024]
                const __half* __restrict__ Bm,  // g_Wc2 [4096,1024]
                __half* __restrict__ hsW,       // hsWrite
                const int* __restrict__ chars, int t)
{
    const int act_t = g_act[t];
    const int row0 = blockIdx.y * 128;
    if (row0 >= act_t) return;
    const int col0 = blockIdx.x * 128;
    const int K = CH_;                  // 1024

    extern __shared__ __half smem_[];
    __half* const sA[2] = { smem_,                smem_ + 2*128*LDS_ };
    __half* const sB[2] = { smem_ + 128*LDS_,     smem_ + 3*128*LDS_ };

    const int tid  = threadIdx.x;
    const int lane = tid & 31;
    const int wid  = tid >> 5;
    const int wm   = (wid & 1) * 64;
    const int wn   = (wid >> 1) * 32;

    const int lr = tid >> 1;
    const int cb = (tid & 1) * 4;

    float acc[4][4][4];
#pragma unroll
    for (int mi = 0; mi < 4; ++mi)
#pragma unroll
        for (int ni = 0; ni < 4; ++ni)
#pragma unroll
            for (int f = 0; f < 4; ++f) acc[mi][ni][f] = 0.f;

    const int KT = K >> 6;              // 16

    {
        const __half* Ap = A  + (size_t)(row0 + lr) * K + cb * 8;
        const __half* Bp = Bm + (size_t)(col0 + lr) * K + cb * 8;
#pragma unroll
        for (int c = 0; c < 4; ++c) {
            cp16(&sA[0][lr * LDS_ + (cb + c) * 8], Ap + c * 8);
            cp16(&sB[0][lr * LDS_ + (cb + c) * 8], Bp + c * 8);
        }
        asm volatile("cp.async.commit_group;");
    }

    for (int kt = 0; kt < KT; ++kt) {
        const int buf = kt & 1;
        if (kt + 1 < KT) {
            const int k0 = (kt + 1) << 6;
            const __half* Ap = A  + (size_t)(row0 + lr) * K + k0 + cb * 8;
            const __half* Bp = Bm + (size_t)(col0 + lr) * K + k0 + cb * 8;
#pragma unroll
            for (int c = 0; c < 4; ++c) {
                cp16(&sA[buf ^ 1][lr * LDS_ + (cb + c) * 8], Ap + c * 8);
                cp16(&sB[buf ^ 1][lr * LDS_ + (cb + c) * 8], Bp + c * 8);
            }
            asm volatile("cp.async.commit_group;");
            asm volatile("cp.async.wait_group 1;");
        } else {
            asm volatile("cp.async.wait_group 0;");
        }
        __syncthreads();

        const __half* As = sA[buf];
        const __half* Bs = sB[buf];
#pragma unroll
        for (int ks = 0; ks < 4; ++ks) {
            uint32_t a[4][4], b[4][2];
#pragma unroll
            for (int mi = 0; mi < 4; ++mi) {
                uint32_t addr = (uint32_t)__cvta_generic_to_shared(
                    &As[(wm + mi*16 + (lane & 15)) * LDS_ + ks*16 + (lane >> 4) * 8]);
                asm volatile("ldmatrix.sync.aligned.m8n8.x4.shared.b16 {%0,%1,%2,%3}, [%4];"
                    : "=r"(a[mi][0]), "=r"(a[mi][1]), "=r"(a[mi][2]), "=r"(a[mi][3])
                    : "r"(addr));
            }
#pragma unroll
            for (int ni = 0; ni < 4; ++ni) {
                uint32_t addr = (uint32_t)__cvta_generic_to_shared(
                    &Bs[(wn + ni*8 + (lane & 7)) * LDS_ + ks*16 + ((lane >> 3) & 1) * 8]);
                asm volatile("ldmatrix.sync.aligned.m8n8.x2.shared.b16 {%0,%1}, [%2];"
                    : "=r"(b[ni][0]), "=r"(b[ni][1]) : "r"(addr));
            }
#pragma unroll
            for (int mi = 0; mi < 4; ++mi)
#pragma unroll
                for (int ni = 0; ni < 4; ++ni) {
                    asm volatile(
                        "mma.sync.aligned.m16n8k16.row.col.f32.f16.f16.f32 "
                        "{%0,%1,%2,%3}, {%4,%5,%6,%7}, {%8,%9}, {%0,%1,%2,%3};"
                        : "+f"(acc[mi][ni][0]), "+f"(acc[mi][ni][1]),
                          "+f"(acc[mi][ni][2]), "+f"(acc[mi][ni][3])
                        : "r"(a[mi][0]), "r"(a[mi][1]), "r"(a[mi][2]), "r"(a[mi][3]),
                          "r"(b[ni][0]), "r"(b[ni][1]));
                }
        }
        __syncthreads();
    }

    // ---- fused LSTM cell epilogue ----
    float* Sg = (float*)smem_;          // 128 x 132 fp32
#pragma unroll
    for (int mi = 0; mi < 4; ++mi)
#pragma unroll
        for (int ni = 0; ni < 4; ++ni) {
            const int r = wm + mi*16 + (lane >> 2);
            const int c = wn + ni*8 + (lane & 3) * 2;
            Sg[r * 132 + c]           = acc[mi][ni][0];
            Sg[r * 132 + c + 1]       = acc[mi][ni][1];
            Sg[(r + 8) * 132 + c]     = acc[mi][ni][2];
            Sg[(r + 8) * 132 + c + 1] = acc[mi][ni][3];
        }
    __syncthreads();

    const int jb = col0 >> 2;           // 32 j per tile
#pragma unroll
    for (int q = 0; q < 16; ++q) {
        const int cid = tid + q * 256;
        const int nl = cid >> 5, jl = cid & 31;
        const int n = row0 + nl;
        if (n >= act_t) continue;
        const int j = jb + jl;
        float4 z = *(float4*)&Sg[nl * 132 + jl * 4];
        const int tok = chars[g_perm[n] * Wc_ + t];
        float4 p = *(const float4*)&g_Pp[(size_t)tok * CG_ + j * 4];
        const float zi = z.x + p.x, zf = z.y + p.y, zg = z.z + p.z, zo = z.w + p.w;
        const float c_old = g_cc[(size_t)n * CH_ + j];
        const float cn = sigf(zf) * c_old + sigf(zi) * tanhf(zg);
        const float hn = sigf(zo) * tanhf(cn);
        g_cc[(size_t)n * CH_ + j] = cn;
        g_ch[(size_t)n * CH_ + j] = hn;
        hsW[(size_t)n * CH_ + j] = __float2half(hn);
    }
}

// ---------------- char t=0 gate (all slots active; c_prev = 0) ----------------
__global__ void char_gate0(const int* __restrict__ chars, __half* __restrict__ hsW)
{
    const int n = blockIdx.y;
    const int j = blockIdx.x * blockDim.x + threadIdx.x;   // 0..1023
    const int tok = chars[g_perm[n] * Wc_ + 0];
    float4 p = *(const float4*)&g_Pp[(size_t)tok * CG_ + j * 4];
    const float cn = sigf(p.x) * tanhf(p.z);
    const float hn = sigf(p.w) * tanhf(cn);
    g_cc[(size_t)n * CH_ + j] = cn;
    g_ch[(size_t)n * CH_ + j] = hn;
    hsW[(size_t)n * CH_ + j] = __float2half(hn);
}

// ---------------- fp32 SGEMM (only for P = char_emb @ c_Wih.T, M=128) ----------
__global__ __launch_bounds__(256)
void sgemm128(const float* __restrict__ A, const float* __restrict__ Bm,
              float* __restrict__ C, int M, int N, int K)
{
    __shared__ float As[8][128];
    __shared__ float Bs[8][128];
    const int tid = threadIdx.x;
    const int tx  = tid & 15;
    const int ty  = tid >> 4;
    const int row0 = blockIdx.y * 128;
    const int col0 = blockIdx.x * 128;
    const int lr = tid >> 1;
    const int lk = (tid & 1) * 4;

    const float* Ap = A  + (size_t)(row0 + lr) * K + lk;
    const float* Bp = Bm + (size_t)(col0 + lr) * K + lk;

    float acc[8][8];
#pragma unroll
    for (int i = 0; i < 8; ++i)
#pragma unroll
        for (int j = 0; j < 8; ++j) acc[i][j] = 0.f;

    {
        float4 a = *(const float4*)Ap;
        float4 b = *(const float4*)Bp;
        As[lk+0][lr] = a.x; As[lk+1][lr] = a.y; As[lk+2][lr] = a.z; As[lk+3][lr] = a.w;
        Bs[lk+0][lr] = b.x; Bs[lk+1][lr] = b.y; Bs[lk+2][lr] = b.z; Bs[lk+3][lr] = b.w;
    }
    __syncthreads();

    int k0 = 0;
    while (true) {
        const int kn = k0 + 8;
        const bool more = kn < K;
        float4 an, bn;
        if (more) { an = *(const float4*)(Ap + kn); bn = *(const float4*)(Bp + kn); }
#pragma unroll
        for (int k = 0; k < 8; ++k) {
            float4 a0 = *(const float4*)&As[k][ty*8];
            float4 a1 = *(const float4*)&As[k][ty*8+4];
            float4 b0 = *(const float4*)&Bs[k][tx*8];
            float4 b1 = *(const float4*)&Bs[k][tx*8+4];
            float av[8] = {a0.x,a0.y,a0.z,a0.w,a1.x,a1.y,a1.z,a1.w};
            float bv[8] = {b0.x,b0.y,b0.z,b0.w,b1.x,b1.y,b1.z,b1.w};
#pragma unroll
            for (int i = 0; i < 8; ++i)
#pragma unroll
                for (int j = 0; j < 8; ++j)
                    acc[i][j] = fmaf(av[i], bv[j], acc[i][j]);
        }
        if (!more) break;
        __syncthreads();
        As[lk+0][lr] = an.x; As[lk+1][lr] = an.y; As[lk+2][lr] = an.z; As[lk+3][lr] = an.w;
        Bs[lk+0][lr] = bn.x; Bs[lk+1][lr] = bn.y; Bs[lk+2][lr] = bn.z; Bs[lk+3][lr] = bn.w;
        __syncthreads();
        k0 = kn;
    }

#pragma unroll
    for (int i = 0; i < 8; ++i) {
        const int r = row0 + ty*8 + i;
        float4 o0, o1;
        o0.x = acc[i][0]; o0.y = acc[i][1]; o0.z = acc[i][2]; o0.w = acc[i][3];
        o1.x = acc[i][4]; o1.y = acc[i][5]; o1.z = acc[i][6]; o1.w = acc[i][7];
        *(float4*)(C + (size_t)r*N + col0 + tx*8)     = o0;
        *(float4*)(C + (size_t)r*N + col0 + tx*8 + 4) = o1;
    }
}

// ---------------- persistent word BiLSTM layer (fp32 recurrence) ----------------
// HoutH (optional): fp16 copy of Hout for the next layer's fp16 x-projection.
__global__ __launch_bounds__(256)
void word_layer_persist(const float* __restrict__ Whh0, const float* __restrict__ Whh1,
                        const float* __restrict__ XGf, const float* __restrict__ XGb,
                        const int* __restrict__ lens, const float* __restrict__ bias,
                        float* __restrict__ Hout, __half* __restrict__ HoutH)
{
    __shared__ float hs[64][68];
    __shared__ float ws[32][68];

    const int tid = threadIdx.x;
    const int jj  = tid & 7;
    const int bb  = tid >> 3;             // 0..31
    const int dir = blockIdx.x >> 6;
    const int jt  = (blockIdx.x & 63) << 3;
    const int j   = jt + jj;

    const float* W  = dir ? Whh1 : Whh0;
    const float* XG = dir ? XGb : XGf;
    const float* bv = bias + (size_t)dir * G_;
    float bg[4];
#pragma unroll
    for (int g = 0; g < 4; ++g) bg[g] = bv[g * H_ + j];

    const int len0 = lens[bb];
    const int len1 = lens[bb + 32];

    float hreg0 = 0.f, creg0 = 0.f;
    float hreg1 = 0.f, creg1 = 0.f;

    for (int t = 0; t < S_; ++t) {
        const float* hcur = g_hpp + (size_t)(((t    ) & 1) * 2 + dir) * (B_*H_);
        float*       hnxt = g_hpp + (size_t)(((t + 1) & 1) * 2 + dir) * (B_*H_);

        float acc[2][4];
#pragma unroll
        for (int b2 = 0; b2 < 2; ++b2)
#pragma unroll
            for (int g = 0; g < 4; ++g) acc[b2][g] = 0.f;

        for (int k0 = 0; k0 < H_; k0 += 64) {
#pragma unroll
            for (int i = 0; i < 4; ++i) {
                const int idx = tid + i * 256;
                const int r = idx >> 4, c = idx & 15;
                float4 v = __ldcg((const float4*)(hcur + (size_t)r * H_ + k0 + c * 4));
                *(float4*)&hs[r][c * 4] = v;
            }
#pragma unroll
            for (int i = 0; i < 2; ++i) {
                const int idx = tid + i * 256;
                const int w = idx >> 4, c = idx & 15;
                const int g = w >> 3, jl = w & 7;
                float4 v = *(const float4*)(W + (size_t)(g * H_ + jt + jl) * H_ + k0 + c * 4);
                *(float4*)&ws[w][c * 4] = v;
            }
            __syncthreads();
#pragma unroll
            for (int k4 = 0; k4 < 16; ++k4) {
                float4 a0 = *(const float4*)&hs[bb][k4 * 4];
                float4 a1 = *(const float4*)&hs[bb + 32][k4 * 4];
#pragma unroll
                for (int g = 0; g < 4; ++g) {
                    float4 w4 = *(const float4*)&ws[g * 8 + jj][k4 * 4];
                    acc[0][g] = fmaf(a0.x, w4.x, acc[0][g]);
                    acc[0][g] = fmaf(a0.y, w4.y, acc[0][g]);
                    acc[0][g] = fmaf(a0.z, w4.z, acc[0][g]);
                    acc[0][g] = fmaf(a0.w, w4.w, acc[0][g]);
                    acc[1][g] = fmaf(a1.x, w4.x, acc[1][g]);
                    acc[1][g] = fmaf(a1.y, w4.y, acc[1][g]);
                    acc[1][g] = fmaf(a1.z, w4.z, acc[1][g]);
                    acc[1][g] = fmaf(a1.w, w4.w, acc[1][g]);
                }
            }
            __syncthreads();
        }

#pragma unroll
        for (int b2 = 0; b2 < 2; ++b2) {
            const int b = bb + b2 * 32;
            const int len = b2 ? len1 : len0;
            const bool valid = t < len;
            const int src = (dir == 0) ? t : (valid ? (len - 1 - t) : t);
            const float* xg = XG + (size_t)(b * S_ + src) * G_ + jt + jj;
            float zi = acc[b2][0] + xg[0]      + bg[0];
            float zf = acc[b2][1] + xg[H_]     + bg[1];
            float zg = acc[b2][2] + xg[2*H_]   + bg[2];
            float zo = acc[b2][3] + xg[3*H_]   + bg[3];
            float c_old = b2 ? creg1 : creg0;
            float cn = sigf(zf) * c_old + sigf(zi) * tanhf(zg);
            float hn = sigf(zo) * tanhf(cn);
            float h_old = b2 ? hreg1 : hreg0;
            float h_out = valid ? hn : h_old;
            float c_out = valid ? cn : c_old;
            if (b2) { hreg1 = h_out; creg1 = c_out; }
            else    { hreg0 = h_out; creg0 = c_out; }
            __stcg(hnxt + (size_t)b * H_ + j, h_out);
            if (dir == 0) {
                const float v = valid ? hn : 0.f;
                Hout[(size_t)(b * S_ + t) * CH_ + j] = v;
                if (HoutH) HoutH[(size_t)(b * S_ + t) * CH_ + j] = __float2half(v);
            } else if (valid) {
                Hout[(size_t)(b * S_ + src) * CH_ + H_ + j] = hn;
                if (HoutH) HoutH[(size_t)(b * S_ + src) * CH_ + H_ + j] = __float2half(hn);
            }
        }

        if (t < S_ - 1) {
            __syncthreads();
            if (tid == 0) {
                __threadfence();
                atomicAdd(&g_bar, 1u);
                const unsigned tgt = (unsigned)(t + 1) * (unsigned)NBLK_;
                volatile unsigned* p = &g_bar;
                while (*p < tgt) __nanosleep(64);
            }
            __syncthreads();
        }
    }
}

// ---------------- word embedding gather (fp16) ----------------
__global__ void embed_words(const int* __restrict__ words, const float* __restrict__ emb)
{
    const int m = blockIdx.x;
    const int e = threadIdx.x;
    g_XembH[(size_t)m*E_ + e] = __float2half(emb[(size_t)words[m] * E_ + e]);
}

// ---------------- final head ----------------
__global__ __launch_bounds__(256)
void final_linear(const int* __restrict__ wnum, const float* __restrict__ W,
                  const float* __restrict__ bias, float* __restrict__ out)
{
    const int row = blockIdx.x;         // 0..8191
    const int b = row >> 7;
    const int s = row & (S_ - 1);
    const bool valid = s < wnum[b];
    const int slot = g_iperm[row];
    __shared__ float v[CH_];
    __shared__ float sred[8*NC_];
    const int tid = threadIdx.x;
    for (int j = tid; j < CH_; j += 256) {
        float x = g_H1[(size_t)row*CH_ + j];
        if (valid) x += g_ch[(size_t)slot*CH_ + j];
        v[j] = x;
    }
    __syncthreads();
    float acc[NC_];
#pragma unroll
    for (int c2 = 0; c2 < NC_; ++c2) acc[c2] = 0.f;
    for (int j = tid; j < CH_; j += 256) {
        float x = v[j];
#pragma unroll
        for (int c2 = 0; c2 < NC_; ++c2)
            acc[c2] = fmaf(x, W[c2*CH_ + j], acc[c2]);
    }
#pragma unroll
    for (int c2 = 0; c2 < NC_; ++c2)
#pragma unroll
        for (int off = 16; off > 0; off >>= 1)
            acc[c2] += __shfl_down_sync(0xffffffffu, acc[c2], off);
    const int lane = tid & 31, w = tid >> 5;
    if (lane == 0)
#pragma unroll
        for (int c2 = 0; c2 < NC_; ++c2) sred[w*NC_ + c2] = acc[c2];
    __syncthreads();
    if (tid < NC_) {
        float sum = bias[tid];
#pragma unroll
        for (int w2 = 0; w2 < 8; ++w2) sum += sred[w2*NC_ + tid];
        out[(size_t)row*NC_ + tid] = sum;
    }
}

// ================================================================================
extern "C" void kernel_launch(void* const* d_in, const int* in_sizes, int n_in,
                              void* d_out, int out_size)
{
    (void)in_sizes; (void)n_in; (void)out_size;
    const int*   words     = (const int*)  d_in[0];
    const int*   words_num = (const int*)  d_in[1];
    const int*   chars     = (const int*)  d_in[2];
    const int*   char_lens = (const int*)  d_in[3];
    const float* word_emb  = (const float*)d_in[4];
    const float* char_emb  = (const float*)d_in[5];
    const float* l0_Wih    = (const float*)d_in[6];
    const float* l0_Whh    = (const float*)d_in[7];
    const float* l0_b      = (const float*)d_in[8];
    const float* l1_Wih    = (const float*)d_in[9];
    const float* l1_Whh    = (const float*)d_in[10];
    const float* l1_b      = (const float*)d_in[11];
    const float* c_Wih     = (const float*)d_in[12];
    const float* c_Whh     = (const float*)d_in[13];
    const float* c_b       = (const float*)d_in[14];
    const float* lin_W     = (const float*)d_in[15];
    const float* lin_b     = (const float*)d_in[16];
    float* out = (float*)d_out;

    float *XGf, *XGb, *H0, *H1, *hpp, *P;
    __half *XembH, *Wih0H, *Wih1H, *H0h, *hsA, *hsB, *Wc2;
    unsigned* bar;
    int *hist;
    cudaGetSymbolAddress((void**)&XembH, g_XembH);
    cudaGetSymbolAddress((void**)&Wih0H, g_Wih0H);
    cudaGetSymbolAddress((void**)&Wih1H, g_Wih1H);
    cudaGetSymbolAddress((void**)&XGf,  g_XGf);
    cudaGetSymbolAddress((void**)&XGb,  g_XGb);
    cudaGetSymbolAddress((void**)&H0,   g_H0);
    cudaGetSymbolAddress((void**)&H0h,  g_H0h);
    cudaGetSymbolAddress((void**)&H1,   g_H1);
    cudaGetSymbolAddress((void**)&hpp,  g_hpp);
    cudaGetSymbolAddress((void**)&bar,  g_bar);
    cudaGetSymbolAddress((void**)&P,    g_P);
    cudaGetSymbolAddress((void**)&hsA,  g_hsA);
    cudaGetSymbolAddress((void**)&hsB,  g_hsB);
    cudaGetSymbolAddress((void**)&Wc2,  g_Wc2);
    cudaGetSymbolAddress((void**)&hist, g_hist);

    cudaFuncSetAttribute(hgemm_lstm, cudaFuncAttributeMaxDynamicSharedMemorySize, (int)HS_BYTES);
    cudaFuncSetAttribute(hgemm_f,    cudaFuncAttributeMaxDynamicSharedMemorySize, (int)HS_BYTES);

    // ---- fork-join streams ----
    static cudaStream_t s_char = nullptr;
    static cudaEvent_t ev_fork = nullptr, ev_join = nullptr;
    if (!s_char) {
        cudaStreamCreateWithFlags(&s_char, cudaStreamNonBlocking);
        cudaEventCreateWithFlags(&ev_fork, cudaEventDisableTiming);
        cudaEventCreateWithFlags(&ev_join, cudaEventDisableTiming);
    }
    cudaEventRecord(ev_fork, 0);
    cudaStreamWaitEvent(s_char, ev_fork, 0);

    // ======================= char path (stream s_char) ==========================
    cudaMemsetAsync(hist, 0, (Wc_ + 1) * sizeof(int), s_char);
    hist_k<<<NW_/256, 256, 0, s_char>>>(char_lens);
    scan_k<<<1, 32, 0, s_char>>>();
    scatter_k<<<NW_/256, 256, 0, s_char>>>(char_lens);
    half_remap_k<<<(CG_*CH_ + 255)/256, 256, 0, s_char>>>(c_Whh, Wc2);
    sgemm128<<<dim3(CG_/128, 1), 256, 0, s_char>>>(char_emb, c_Wih, P, 128, CG_, E_);
    reorderP_k<<<(128*CG_ + 255)/256, 256, 0, s_char>>>(c_b);
    char_gate0<<<dim3(CH_/256, NW_), 256, 0, s_char>>>(chars, hsA);
    for (int t = 1; t < Wc_; ++t) {
        const __half* rd = ((t - 1) & 1) ? hsB : hsA;
        __half*       wr = (t & 1)       ? hsB : hsA;
        hgemm_lstm<<<dim3(CG_/128, NW_/128), 256, HS_BYTES, s_char>>>(rd, Wc2, wr, chars, t);
    }
    cudaEventRecord(ev_join, s_char);

    // ======================= word path (capture stream) =========================
    half_k<<<(2*G_*E_ + 255)/256, 256>>>(l0_Wih, Wih0H, 2*G_*E_);
    half_k<<<(2*G_*CH_ + 255)/256, 256>>>(l1_Wih, Wih1H, 2*G_*CH_);
    embed_words<<<NW_, E_>>>(words, word_emb);

    {   // layer 0 (K=256, fp16 x-proj)
        const float* Whh0 = l0_Whh;
        const float* Whh1 = l0_Whh + (size_t)G_ * H_;
        hgemm_f<<<dim3(G_/128, NW_/128), 256, HS_BYTES>>>(XembH, Wih0H,                  XGf, NW_, G_, E_);
        hgemm_f<<<dim3(G_/128, NW_/128), 256, HS_BYTES>>>(XembH, Wih0H + (size_t)G_*E_,  XGb, NW_, G_, E_);
        cudaMemsetAsync(H0,  0, (size_t)NW_*CH_*sizeof(float), 0);
        cudaMemsetAsync(H0h, 0, (size_t)NW_*CH_*sizeof(__half), 0);
        cudaMemsetAsync(hpp, 0, (size_t)2*2*B_*H_*sizeof(float), 0);
        cudaMemsetAsync(bar, 0, sizeof(unsigned), 0);
        word_layer_persist<<<NBLK_, 256>>>(Whh0, Whh1, XGf, XGb, words_num, l0_b, H0, H0h);
    }
    {   // layer 1 (K=1024, fp16 x-proj)
        const float* Whh0 = l1_Whh;
        const float* Whh1 = l1_Whh + (size_t)G_ * H_;
        hgemm_f<<<dim3(G_/128, NW_/128), 256, HS_BYTES>>>(H0h, Wih1H,                   XGf, NW_, G_, CH_);
        hgemm_f<<<dim3(G_/128, NW_/128), 256, HS_BYTES>>>(H0h, Wih1H + (size_t)G_*CH_,  XGb, NW_, G_, CH_);
        cudaMemsetAsync(H1,  0, (size_t)NW_*CH_*sizeof(float), 0);
        cudaMemsetAsync(hpp, 0, (size_t)2*2*B_*H_*sizeof(float), 0);
        cudaMemsetAsync(bar, 0, sizeof(unsigned), 0);
        word_layer_persist<<<NBLK_, 256>>>(Whh0, Whh1, XGf, XGb, words_num, l1_b, H1, nullptr);
    }

    // ======================= join + head =========================
    cudaStreamWaitEvent(0, ev_join, 0);
    final_linear<<<NW_, 256>>>(words_num, lin_W, lin_b, out);
}

// round 12
// speedup vs baseline: 1.7854x; 1.0467x over previous
#include <cuda_runtime.h>
#include <cuda_fp16.h>
#include <cstdint>
#include <cstddef>

// Problem constants
#define B_   64
#define S_   128
#define Wc_  16
#define E_   256
#define H_   512
#define NC_  20
#define NW_  (B_*S_)        // 8192 words total
#define G_   (4*H_)         // 2048 word-LSTM gate width
#define CH_  (2*H_)         // 1024 char-LSTM hidden
#define CG_  (4*CH_)        // 4096 char-LSTM gate width

#define NBLK_ 128           // persistent word-layer blocks
#define LDS_  72            // hgemm smem halfword stride (64 + 8 pad)
#define HS_BYTES ((size_t)4 * 128 * LDS_ * sizeof(__half))   // 73728

// ---------------- scratch (static device globals; no allocation) ----------------
__device__ __half g_XembH[(size_t)NW_*E_];             // word embeddings fp16
__device__ __half g_Wih0H[(size_t)2*G_*E_];            // l0_Wih fp16 [2][2048,256]
__device__ __half g_Wih1H[(size_t)2*G_*CH_];           // l1_Wih fp16 [2][2048,1024]
__device__ float g_XGf [(size_t)NW_*G_];               // fwd x-gates      [8192,2048]
__device__ float g_XGb [(size_t)NW_*G_];               // bwd x-gates      [8192,2048]
__device__ float g_H0  [(size_t)NW_*CH_];              // layer0 out fp32
__device__ __half g_H0h[(size_t)NW_*CH_];              // layer0 out fp16
__device__ float g_H1  [(size_t)NW_*CH_];              // layer1 output    [8192,1024]
__device__ float g_hpp[(size_t)2*2*B_*H_];             // h ping-pong
__device__ unsigned g_bar;                             // grid barrier counter
__device__ float g_P  [(size_t)128*CG_];               // char_emb @ c_Wih.T (gate-major)
__device__ float g_Pp [(size_t)128*CG_];               // P interleaved j*4+g, + bias
__device__ float g_ch [(size_t)NW_*CH_];               // char h fp32 (sorted slots)
__device__ float g_cc [(size_t)NW_*CH_];               // char c state (sorted)
__device__ __half g_hsA[(size_t)NW_*CH_];              // char h fp16 buf A
__device__ __half g_hsB[(size_t)NW_*CH_];              // char h fp16 buf B
__device__ __half g_Wc2[(size_t)CG_*CH_];              // c_Whh fp16, rows j*4+g

// ---- length-sort bookkeeping ----
__device__ int g_hist[Wc_ + 1];
__device__ int g_off [Wc_ + 1];
__device__ int g_act [Wc_ + 1];
__device__ int g_perm [NW_];
__device__ int g_iperm[NW_];
__device__ int g_slen [NW_];

// ---- transcendentals ----
// word path (128 compounding steps): expf-based, rel err ~1e-7
__device__ __forceinline__ float sigf(float x)
{
    return __fdividef(1.f, 1.f + __expf(-x));
}
__device__ __forceinline__ float tanhf_fast(float x)
{
    return __fdividef(2.f, 1.f + __expf(-2.f * x)) - 1.f;
}
// char path (15 steps): HW tanh.approx, 1 MUFU per transcendental
__device__ __forceinline__ float tanh_ap(float x)
{
    float y;
    asm("tanh.approx.f32 %0, %1;" : "=f"(y) : "f"(x));
    return y;
}
__device__ __forceinline__ float sig_ap(float x)
{
    return fmaf(tanh_ap(0.5f * x), 0.5f, 0.5f);
}

__device__ __forceinline__ void cp16(void* dst, const void* src)
{
    uint32_t d = (uint32_t)__cvta_generic_to_shared(dst);
    asm volatile("cp.async.cg.shared.global [%0], [%1], 16;" :: "r"(d), "l"(src));
}

// ---------------- counting sort by char_lens (descending) ----------------
__global__ void hist_k(const int* __restrict__ clens)
{
    const int i = blockIdx.x * blockDim.x + threadIdx.x;
    if (i < NW_) atomicAdd(&g_hist[clens[i]], 1);
}
__global__ void scan_k()
{
    if (threadIdx.x == 0) {
        int off = 0;
        for (int len = Wc_; len >= 1; --len) { g_off[len] = off; off += g_hist[len]; }
        for (int t = 0; t <= Wc_; ++t) {
            int a = 0;
            for (int l = t + 1; l <= Wc_; ++l) a += g_hist[l];
            g_act[t] = a;
        }
    }
}
__global__ void scatter_k(const int* __restrict__ clens)
{
    const int i = blockIdx.x * blockDim.x + threadIdx.x;
    if (i < NW_) {
        const int len = clens[i];
        const int s = atomicAdd(&g_off[len], 1);
        g_perm[s] = i;
        g_iperm[i] = s;
        g_slen[s] = len;
    }
}

// generic fp32 -> fp16 copy
__global__ void half_k(const float* __restrict__ src, __half* __restrict__ dst, int total)
{
    const int i = blockIdx.x * blockDim.x + threadIdx.x;
    if (i < total) dst[i] = __float2half(src[i]);
}

// c_Whh -> fp16 with gate-interleaved row remap: src row r = g*CH+j -> dst row j*4+g
__global__ void half_remap_k(const float* __restrict__ src, __half* __restrict__ dst)
{
    const int i = blockIdx.x * blockDim.x + threadIdx.x;
    if (i >= CG_ * CH_) return;
    const int r = i / CH_, k = i % CH_;
    const int g = r / CH_, j = r % CH_;
    const int outr = j * 4 + g;
    dst[(size_t)outr * CH_ + k] = __float2half(src[i]);
}

// P reorder to interleaved + fold bias: Pp[tok][j*4+g] = P[tok][g*CH+j] + c_b[g*CH+j]
__global__ void reorderP_k(const float* __restrict__ cbias)
{
    const int i = blockIdx.x * blockDim.x + threadIdx.x;
    if (i >= 128 * CG_) return;
    const int tok = i / CG_, col = i % CG_;
    const int j = col >> 2, g = col & 3;
    const int src = g * CH_ + j;
    g_Pp[i] = g_P[(size_t)tok * CG_ + src] + cbias[src];
}

// ---------------- fp16 tensor-core GEMM: C[M,N] = A[M,K] @ B[N,K]^T (fp32 C) ----
__global__ __launch_bounds__(256)
void hgemm_f(const __half* __restrict__ A, const __half* __restrict__ Bm,
             float* __restrict__ C, int M, int N, int K)
{
    const int row0 = blockIdx.y * 128;
    const int col0 = blockIdx.x * 128;

    extern __shared__ __half smem_[];
    __half* const sA[2] = { smem_,                smem_ + 2*128*LDS_ };
    __half* const sB[2] = { smem_ + 128*LDS_,     smem_ + 3*128*LDS_ };

    const int tid  = threadIdx.x;
    const int lane = tid & 31;
    const int wid  = tid >> 5;
    const int wm   = (wid & 1) * 64;
    const int wn   = (wid >> 1) * 32;

    const int lr = tid >> 1;
    const int cb = (tid & 1) * 4;

    float acc[4][4][4];
#pragma unroll
    for (int mi = 0; mi < 4; ++mi)
#pragma unroll
        for (int ni = 0; ni < 4; ++ni)
#pragma unroll
            for (int f = 0; f < 4; ++f) acc[mi][ni][f] = 0.f;

    const int KT = K >> 6;

    {
        const __half* Ap = A  + (size_t)(row0 + lr) * K + cb * 8;
        const __half* Bp = Bm + (size_t)(col0 + lr) * K + cb * 8;
#pragma unroll
        for (int c = 0; c < 4; ++c) {
            cp16(&sA[0][lr * LDS_ + (cb + c) * 8], Ap + c * 8);
            cp16(&sB[0][lr * LDS_ + (cb + c) * 8], Bp + c * 8);
        }
        asm volatile("cp.async.commit_group;");
    }

    for (int kt = 0; kt < KT; ++kt) {
        const int buf = kt & 1;
        if (kt + 1 < KT) {
            const int k0 = (kt + 1) << 6;
            const __half* Ap = A  + (size_t)(row0 + lr) * K + k0 + cb * 8;
            const __half* Bp = Bm + (size_t)(col0 + lr) * K + k0 + cb * 8;
#pragma unroll
            for (int c = 0; c < 4; ++c) {
                cp16(&sA[buf ^ 1][lr * LDS_ + (cb + c) * 8], Ap + c * 8);
                cp16(&sB[buf ^ 1][lr * LDS_ + (cb + c) * 8], Bp + c * 8);
            }
            asm volatile("cp.async.commit_group;");
            asm volatile("cp.async.wait_group 1;");
        } else {
            asm volatile("cp.async.wait_group 0;");
        }
        __syncthreads();

        const __half* As = sA[buf];
        const __half* Bs = sB[buf];
#pragma unroll
        for (int ks = 0; ks < 4; ++ks) {
            uint32_t a[4][4], b[4][2];
#pragma unroll
            for (int mi = 0; mi < 4; ++mi) {
                uint32_t addr = (uint32_t)__cvta_generic_to_shared(
                    &As[(wm + mi*16 + (lane & 15)) * LDS_ + ks*16 + (lane >> 4) * 8]);
                asm volatile("ldmatrix.sync.aligned.m8n8.x4.shared.b16 {%0,%1,%2,%3}, [%4];"
                    : "=r"(a[mi][0]), "=r"(a[mi][1]), "=r"(a[mi][2]), "=r"(a[mi][3])
                    : "r"(addr));
            }
#pragma unroll
            for (int ni = 0; ni < 4; ++ni) {
                uint32_t addr = (uint32_t)__cvta_generic_to_shared(
                    &Bs[(wn + ni*8 + (lane & 7)) * LDS_ + ks*16 + ((lane >> 3) & 1) * 8]);
                asm volatile("ldmatrix.sync.aligned.m8n8.x2.shared.b16 {%0,%1}, [%2];"
                    : "=r"(b[ni][0]), "=r"(b[ni][1]) : "r"(addr));
            }
#pragma unroll
            for (int mi = 0; mi < 4; ++mi)
#pragma unroll
                for (int ni = 0; ni < 4; ++ni) {
                    asm volatile(
                        "mma.sync.aligned.m16n8k16.row.col.f32.f16.f16.f32 "
                        "{%0,%1,%2,%3}, {%4,%5,%6,%7}, {%8,%9}, {%0,%1,%2,%3};"
                        : "+f"(acc[mi][ni][0]), "+f"(acc[mi][ni][1]),
                          "+f"(acc[mi][ni][2]), "+f"(acc[mi][ni][3])
                        : "r"(a[mi][0]), "r"(a[mi][1]), "r"(a[mi][2]), "r"(a[mi][3]),
                          "r"(b[ni][0]), "r"(b[ni][1]));
                }
        }
        __syncthreads();
    }

#pragma unroll
    for (int mi = 0; mi < 4; ++mi)
#pragma unroll
        for (int ni = 0; ni < 4; ++ni) {
            const int r = row0 + wm + mi*16 + (lane >> 2);
            const int c = col0 + wn + ni*8 + (lane & 3) * 2;
            float2 v0 = make_float2(acc[mi][ni][0], acc[mi][ni][1]);
            float2 v1 = make_float2(acc[mi][ni][2], acc[mi][ni][3]);
            *(float2*)&C[(size_t)r * N + c]       = v0;
            *(float2*)&C[(size_t)(r + 8) * N + c] = v1;
        }
}

// ========== fused char-LSTM GEMM step: Z = h_{t-1} @ Wc2^T, then cell update ====
__global__ __launch_bounds__(256)
void hgemm_lstm(const __half* __restrict__ A,   // hsRead [8192,1024]
                const __half* __restrict__ Bm,  // g_Wc2 [4096,1024]
                __half* __restrict__ hsW,       // hsWrite
                const int* __restrict__ chars, int t)
{
    const int act_t = g_act[t];
    const int row0 = blockIdx.y * 128;
    if (row0 >= act_t) return;
    const int col0 = blockIdx.x * 128;
    const int K = CH_;                  // 1024

    extern __shared__ __half smem_[];
    __half* const sA[2] = { smem_,                smem_ + 2*128*LDS_ };
    __half* const sB[2] = { smem_ + 128*LDS_,     smem_ + 3*128*LDS_ };

    const int tid  = threadIdx.x;
    const int lane = tid & 31;
    const int wid  = tid >> 5;
    const int wm   = (wid & 1) * 64;
    const int wn   = (wid >> 1) * 32;

    const int lr = tid >> 1;
    const int cb = (tid & 1) * 4;

    float acc[4][4][4];
#pragma unroll
    for (int mi = 0; mi < 4; ++mi)
#pragma unroll
        for (int ni = 0; ni < 4; ++ni)
#pragma unroll
            for (int f = 0; f < 4; ++f) acc[mi][ni][f] = 0.f;

    const int KT = K >> 6;              // 16

    {
        const __half* Ap = A  + (size_t)(row0 + lr) * K + cb * 8;
        const __half* Bp = Bm + (size_t)(col0 + lr) * K + cb * 8;
#pragma unroll
        for (int c = 0; c < 4; ++c) {
            cp16(&sA[0][lr * LDS_ + (cb + c) * 8], Ap + c * 8);
            cp16(&sB[0][lr * LDS_ + (cb + c) * 8], Bp + c * 8);
        }
        asm volatile("cp.async.commit_group;");
    }

    for (int kt = 0; kt < KT; ++kt) {
        const int buf = kt & 1;
        if (kt + 1 < KT) {
            const int k0 = (kt + 1) << 6;
            const __half* Ap = A  + (size_t)(row0 + lr) * K + k0 + cb * 8;
            const __half* Bp = Bm + (size_t)(col0 + lr) * K + k0 + cb * 8;
#pragma unroll
            for (int c = 0; c < 4; ++c) {
                cp16(&sA[buf ^ 1][lr * LDS_ + (cb + c) * 8], Ap + c * 8);
                cp16(&sB[buf ^ 1][lr * LDS_ + (cb + c) * 8], Bp + c * 8);
            }
            asm volatile("cp.async.commit_group;");
            asm volatile("cp.async.wait_group 1;");
        } else {
            asm volatile("cp.async.wait_group 0;");
        }
        __syncthreads();

        const __half* As = sA[buf];
        const __half* Bs = sB[buf];
#pragma unroll
        for (int ks = 0; ks < 4; ++ks) {
            uint32_t a[4][4], b[4][2];
#pragma unroll
            for (int mi = 0; mi < 4; ++mi) {
                uint32_t addr = (uint32_t)__cvta_generic_to_shared(
                    &As[(wm + mi*16 + (lane & 15)) * LDS_ + ks*16 + (lane >> 4) * 8]);
                asm volatile("ldmatrix.sync.aligned.m8n8.x4.shared.b16 {%0,%1,%2,%3}, [%4];"
                    : "=r"(a[mi][0]), "=r"(a[mi][1]), "=r"(a[mi][2]), "=r"(a[mi][3])
                    : "r"(addr));
            }
#pragma unroll
            for (int ni = 0; ni < 4; ++ni) {
                uint32_t addr = (uint32_t)__cvta_generic_to_shared(
                    &Bs[(wn + ni*8 + (lane & 7)) * LDS_ + ks*16 + ((lane >> 3) & 1) * 8]);
                asm volatile("ldmatrix.sync.aligned.m8n8.x2.shared.b16 {%0,%1}, [%2];"
                    : "=r"(b[ni][0]), "=r"(b[ni][1]) : "r"(addr));
            }
#pragma unroll
            for (int mi = 0; mi < 4; ++mi)
#pragma unroll
                for (int ni = 0; ni < 4; ++ni) {
                    asm volatile(
                        "mma.sync.aligned.m16n8k16.row.col.f32.f16.f16.f32 "
                        "{%0,%1,%2,%3}, {%4,%5,%6,%7}, {%8,%9}, {%0,%1,%2,%3};"
                        : "+f"(acc[mi][ni][0]), "+f"(acc[mi][ni][1]),
                          "+f"(acc[mi][ni][2]), "+f"(acc[mi][ni][3])
                        : "r"(a[mi][0]), "r"(a[mi][1]), "r"(a[mi][2]), "r"(a[mi][3]),
                          "r"(b[ni][0]), "r"(b[ni][1]));
                }
        }
        __syncthreads();
    }

    // ---- fused LSTM cell epilogue (tanh.approx: 5 MUFU/cell) ----
    float* Sg = (float*)smem_;          // 128 x 132 fp32
#pragma unroll
    for (int mi = 0; mi < 4; ++mi)
#pragma unroll
        for (int ni = 0; ni < 4; ++ni) {
            const int r = wm + mi*16 + (lane >> 2);
            const int c = wn + ni*8 + (lane & 3) * 2;
            Sg[r * 132 + c]           = acc[mi][ni][0];
            Sg[r * 132 + c + 1]       = acc[mi][ni][1];
            Sg[(r + 8) * 132 + c]     = acc[mi][ni][2];
            Sg[(r + 8) * 132 + c + 1] = acc[mi][ni][3];
        }
    __syncthreads();

    const int jb = col0 >> 2;           // 32 j per tile
#pragma unroll
    for (int q = 0; q < 16; ++q) {
        const int cid = tid + q * 256;
        const int nl = cid >> 5, jl = cid & 31;
        const int n = row0 + nl;
        if (n >= act_t) continue;
        const int j = jb + jl;
        float4 z = *(float4*)&Sg[nl * 132 + jl * 4];
        const int tok = chars[g_perm[n] * Wc_ + t];
        float4 p = *(const float4*)&g_Pp[(size_t)tok * CG_ + j * 4];
        const float zi = z.x + p.x, zf = z.y + p.y, zg = z.z + p.z, zo = z.w + p.w;
        const float c_old = g_cc[(size_t)n * CH_ + j];
        const float cn = sig_ap(zf) * c_old + sig_ap(zi) * tanh_ap(zg);
        const float hn = sig_ap(zo) * tanh_ap(cn);
        g_cc[(size_t)n * CH_ + j] = cn;
        g_ch[(size_t)n * CH_ + j] = hn;
        hsW[(size_t)n * CH_ + j] = __float2half(hn);
    }
}

// ---------------- char t=0 gate (all slots active; c_prev = 0) ----------------
__global__ void char_gate0(const int* __restrict__ chars, __half* __restrict__ hsW)
{
    const int n = blockIdx.y;
    const int j = blockIdx.x * blockDim.x + threadIdx.x;   // 0..1023
    const int tok = chars[g_perm[n] * Wc_ + 0];
    float4 p = *(const float4*)&g_Pp[(size_t)tok * CG_ + j * 4];
    const float cn = sig_ap(p.x) * tanh_ap(p.z);
    const float hn = sig_ap(p.w) * tanh_ap(cn);
    g_cc[(size_t)n * CH_ + j] = cn;
    g_ch[(size_t)n * CH_ + j] = hn;
    hsW[(size_t)n * CH_ + j] = __float2half(hn);
}

// ---------------- fp32 SGEMM (only for P = char_emb @ c_Wih.T, M=128) ----------
__global__ __launch_bounds__(256)
void sgemm128(const float* __restrict__ A, const float* __restrict__ Bm,
              float* __restrict__ C, int M, int N, int K)
{
    __shared__ float As[8][128];
    __shared__ float Bs[8][128];
    const int tid = threadIdx.x;
    const int tx  = tid & 15;
    const int ty  = tid >> 4;
    const int row0 = blockIdx.y * 128;
    const int col0 = blockIdx.x * 128;
    const int lr = tid >> 1;
    const int lk = (tid & 1) * 4;

    const float* Ap = A  + (size_t)(row0 + lr) * K + lk;
    const float* Bp = Bm + (size_t)(col0 + lr) * K + lk;

    float acc[8][8];
#pragma unroll
    for (int i = 0; i < 8; ++i)
#pragma unroll
        for (int j = 0; j < 8; ++j) acc[i][j] = 0.f;

    {
        float4 a = *(const float4*)Ap;
        float4 b = *(const float4*)Bp;
        As[lk+0][lr] = a.x; As[lk+1][lr] = a.y; As[lk+2][lr] = a.z; As[lk+3][lr] = a.w;
        Bs[lk+0][lr] = b.x; Bs[lk+1][lr] = b.y; Bs[lk+2][lr] = b.z; Bs[lk+3][lr] = b.w;
    }
    __syncthreads();

    int k0 = 0;
    while (true) {
        const int kn = k0 + 8;
        const bool more = kn < K;
        float4 an, bn;
        if (more) { an = *(const float4*)(Ap + kn); bn = *(const float4*)(Bp + kn); }
#pragma unroll
        for (int k = 0; k < 8; ++k) {
            float4 a0 = *(const float4*)&As[k][ty*8];
            float4 a1 = *(const float4*)&As[k][ty*8+4];
            float4 b0 = *(const float4*)&Bs[k][tx*8];
            float4 b1 = *(const float4*)&Bs[k][tx*8+4];
            float av[8] = {a0.x,a0.y,a0.z,a0.w,a1.x,a1.y,a1.z,a1.w};
            float bv[8] = {b0.x,b0.y,b0.z,b0.w,b1.x,b1.y,b1.z,b1.w};
#pragma unroll
            for (int i = 0; i < 8; ++i)
#pragma unroll
                for (int j = 0; j < 8; ++j)
                    acc[i][j] = fmaf(av[i], bv[j], acc[i][j]);
        }
        if (!more) break;
        __syncthreads();
        As[lk+0][lr] = an.x; As[lk+1][lr] = an.y; As[lk+2][lr] = an.z; As[lk+3][lr] = an.w;
        Bs[lk+0][lr] = bn.x; Bs[lk+1][lr] = bn.y; Bs[lk+2][lr] = bn.z; Bs[lk+3][lr] = bn.w;
        __syncthreads();
        k0 = kn;
    }

#pragma unroll
    for (int i = 0; i < 8; ++i) {
        const int r = row0 + ty*8 + i;
        float4 o0, o1;
        o0.x = acc[i][0]; o0.y = acc[i][1]; o0.z = acc[i][2]; o0.w = acc[i][3];
        o1.x = acc[i][4]; o1.y = acc[i][5]; o1.z = acc[i][6]; o1.w = acc[i][7];
        *(float4*)(C + (size_t)r*N + col0 + tx*8)     = o0;
        *(float4*)(C + (size_t)r*N + col0 + tx*8 + 4) = o1;
    }
}

// ---------------- persistent word BiLSTM layer (fp32 recurrence) ----------------
__global__ __launch_bounds__(256)
void word_layer_persist(const float* __restrict__ Whh0, const float* __restrict__ Whh1,
                        const float* __restrict__ XGf, const float* __restrict__ XGb,
                        const int* __restrict__ lens, const float* __restrict__ bias,
                        float* __restrict__ Hout, __half* __restrict__ HoutH)
{
    __shared__ float hs[64][68];
    __shared__ float ws[32][68];

    const int tid = threadIdx.x;
    const int jj  = tid & 7;
    const int bb  = tid >> 3;             // 0..31
    const int dir = blockIdx.x >> 6;
    const int jt  = (blockIdx.x & 63) << 3;
    const int j   = jt + jj;

    const float* W  = dir ? Whh1 : Whh0;
    const float* XG = dir ? XGb : XGf;
    const float* bv = bias + (size_t)dir * G_;
    float bg[4];
#pragma unroll
    for (int g = 0; g < 4; ++g) bg[g] = bv[g * H_ + j];

    const int len0 = lens[bb];
    const int len1 = lens[bb + 32];

    float hreg0 = 0.f, creg0 = 0.f;
    float hreg1 = 0.f, creg1 = 0.f;

    for (int t = 0; t < S_; ++t) {
        const float* hcur = g_hpp + (size_t)(((t    ) & 1) * 2 + dir) * (B_*H_);
        float*       hnxt = g_hpp + (size_t)(((t + 1) & 1) * 2 + dir) * (B_*H_);

        float acc[2][4];
#pragma unroll
        for (int b2 = 0; b2 < 2; ++b2)
#pragma unroll
            for (int g = 0; g < 4; ++g) acc[b2][g] = 0.f;

        for (int k0 = 0; k0 < H_; k0 += 64) {
#pragma unroll
            for (int i = 0; i < 4; ++i) {
                const int idx = tid + i * 256;
                const int r = idx >> 4, c = idx & 15;
                float4 v = __ldcg((const float4*)(hcur + (size_t)r * H_ + k0 + c * 4));
                *(float4*)&hs[r][c * 4] = v;
            }
#pragma unroll
            for (int i = 0; i < 2; ++i) {
                const int idx = tid + i * 256;
                const int w = idx >> 4, c = idx & 15;
                const int g = w >> 3, jl = w & 7;
                float4 v = *(const float4*)(W + (size_t)(g * H_ + jt + jl) * H_ + k0 + c * 4);
                *(float4*)&ws[w][c * 4] = v;
            }
            __syncthreads();
#pragma unroll
            for (int k4 = 0; k4 < 16; ++k4) {
                float4 a0 = *(const float4*)&hs[bb][k4 * 4];
                float4 a1 = *(const float4*)&hs[bb + 32][k4 * 4];
#pragma unroll
                for (int g = 0; g < 4; ++g) {
                    float4 w4 = *(const float4*)&ws[g * 8 + jj][k4 * 4];
                    acc[0][g] = fmaf(a0.x, w4.x, acc[0][g]);
                    acc[0][g] = fmaf(a0.y, w4.y, acc[0][g]);
                    acc[0][g] = fmaf(a0.z, w4.z, acc[0][g]);
                    acc[0][g] = fmaf(a0.w, w4.w, acc[0][g]);
                    acc[1][g] = fmaf(a1.x, w4.x, acc[1][g]);
                    acc[1][g] = fmaf(a1.y, w4.y, acc[1][g]);
                    acc[1][g] = fmaf(a1.z, w4.z, acc[1][g]);
                    acc[1][g] = fmaf(a1.w, w4.w, acc[1][g]);
                }
            }
            __syncthreads();
        }

#pragma unroll
        for (int b2 = 0; b2 < 2; ++b2) {
            const int b = bb + b2 * 32;
            const int len = b2 ? len1 : len0;
            const bool valid = t < len;
            const int src = (dir == 0) ? t : (valid ? (len - 1 - t) : t);
            const float* xg = XG + (size_t)(b * S_ + src) * G_ + jt + jj;
            float zi = acc[b2][0] + xg[0]      + bg[0];
            float zf = acc[b2][1] + xg[H_]     + bg[1];
            float zg = acc[b2][2] + xg[2*H_]   + bg[2];
            float zo = acc[b2][3] + xg[3*H_]   + bg[3];
            float c_old = b2 ? creg1 : creg0;
            float cn = sigf(zf) * c_old + sigf(zi) * tanhf_fast(zg);
            float hn = sigf(zo) * tanhf_fast(cn);
            float h_old = b2 ? hreg1 : hreg0;
            float h_out = valid ? hn : h_old;
            float c_out = valid ? cn : c_old;
            if (b2) { hreg1 = h_out; creg1 = c_out; }
            else    { hreg0 = h_out; creg0 = c_out; }
            __stcg(hnxt + (size_t)b * H_ + j, h_out);
            if (dir == 0) {
                const float v = valid ? hn : 0.f;
                Hout[(size_t)(b * S_ + t) * CH_ + j] = v;
                if (HoutH) HoutH[(size_t)(b * S_ + t) * CH_ + j] = __float2half(v);
            } else if (valid) {
                Hout[(size_t)(b * S_ + src) * CH_ + H_ + j] = hn;
                if (HoutH) HoutH[(size_t)(b * S_ + src) * CH_ + H_ + j] = __float2half(hn);
            }
        }

        if (t < S_ - 1) {
            __syncthreads();
            if (tid == 0) {
                __threadfence();
                atomicAdd(&g_bar, 1u);
                const unsigned tgt = (unsigned)(t + 1) * (unsigned)NBLK_;
                volatile unsigned* p = &g_bar;
                while (*p < tgt) __nanosleep(64);
            }
            __syncthreads();
        }
    }
}

// ---------------- word embedding gather (fp16) ----------------
__global__ void embed_words(const int* __restrict__ words, const float* __restrict__ emb)
{
    const int m = blockIdx.x;
    const int e = threadIdx.x;
    g_XembH[(size_t)m*E_ + e] = __float2half(emb[(size_t)words[m] * E_ + e]);
}

// ---------------- final head ----------------
__global__ __launch_bounds__(256)
void final_linear(const int* __restrict__ wnum, const float* __restrict__ W,
                  const float* __restrict__ bias, float* __restrict__ out)
{
    const int row = blockIdx.x;         // 0..8191
    const int b = row >> 7;
    const int s = row & (S_ - 1);
    const bool valid = s < wnum[b];
    const int slot = g_iperm[row];
    __shared__ float v[CH_];
    __shared__ float sred[8*NC_];
    const int tid = threadIdx.x;
    for (int j = tid; j < CH_; j += 256) {
        float x = g_H1[(size_t)row*CH_ + j];
        if (valid) x += g_ch[(size_t)slot*CH_ + j];
        v[j] = x;
    }
    __syncthreads();
    float acc[NC_];
#pragma unroll
    for (int c2 = 0; c2 < NC_; ++c2) acc[c2] = 0.f;
    for (int j = tid; j < CH_; j += 256) {
        float x = v[j];
#pragma unroll
        for (int c2 = 0; c2 < NC_; ++c2)
            acc[c2] = fmaf(x, W[c2*CH_ + j], acc[c2]);
    }
#pragma unroll
    for (int c2 = 0; c2 < NC_; ++c2)
#pragma unroll
        for (int off = 16; off > 0; off >>= 1)
            acc[c2] += __shfl_down_sync(0xffffffffu, acc[c2], off);
    const int lane = tid & 31, w = tid >> 5;
    if (lane == 0)
#pragma unroll
        for (int c2 = 0; c2 < NC_; ++c2) sred[w*NC_ + c2] = acc[c2];
    __syncthreads();
    if (tid < NC_) {
        float sum = bias[tid];
#pragma unroll
        for (int w2 = 0; w2 < 8; ++w2) sum += sred[w2*NC_ + tid];
        out[(size_t)row*NC_ + tid] = sum;
    }
}

// ================================================================================
extern "C" void kernel_launch(void* const* d_in, const int* in_sizes, int n_in,
                              void* d_out, int out_size)
{
    (void)in_sizes; (void)n_in; (void)out_size;
    const int*   words     = (const int*)  d_in[0];
    const int*   words_num = (const int*)  d_in[1];
    const int*   chars     = (const int*)  d_in[2];
    const int*   char_lens = (const int*)  d_in[3];
    const float* word_emb  = (const float*)d_in[4];
    const float* char_emb  = (const float*)d_in[5];
    const float* l0_Wih    = (const float*)d_in[6];
    const float* l0_Whh    = (const float*)d_in[7];
    const float* l0_b      = (const float*)d_in[8];
    const float* l1_Wih    = (const float*)d_in[9];
    const float* l1_Whh    = (const float*)d_in[10];
    const float* l1_b      = (const float*)d_in[11];
    const float* c_Wih     = (const float*)d_in[12];
    const float* c_Whh     = (const float*)d_in[13];
    const float* c_b       = (const float*)d_in[14];
    const float* lin_W     = (const float*)d_in[15];
    const float* lin_b     = (const float*)d_in[16];
    float* out = (float*)d_out;

    float *XGf, *XGb, *H0, *H1, *hpp, *P;
    __half *XembH, *Wih0H, *Wih1H, *H0h, *hsA, *hsB, *Wc2;
    unsigned* bar;
    int *hist;
    cudaGetSymbolAddress((void**)&XembH, g_XembH);
    cudaGetSymbolAddress((void**)&Wih0H, g_Wih0H);
    cudaGetSymbolAddress((void**)&Wih1H, g_Wih1H);
    cudaGetSymbolAddress((void**)&XGf,  g_XGf);
    cudaGetSymbolAddress((void**)&XGb,  g_XGb);
    cudaGetSymbolAddress((void**)&H0,   g_H0);
    cudaGetSymbolAddress((void**)&H0h,  g_H0h);
    cudaGetSymbolAddress((void**)&H1,   g_H1);
    cudaGetSymbolAddress((void**)&hpp,  g_hpp);
    cudaGetSymbolAddress((void**)&bar,  g_bar);
    cudaGetSymbolAddress((void**)&P,    g_P);
    cudaGetSymbolAddress((void**)&hsA,  g_hsA);
    cudaGetSymbolAddress((void**)&hsB,  g_hsB);
    cudaGetSymbolAddress((void**)&Wc2,  g_Wc2);
    cudaGetSymbolAddress((void**)&hist, g_hist);

    cudaFuncSetAttribute(hgemm_lstm, cudaFuncAttributeMaxDynamicSharedMemorySize, (int)HS_BYTES);
    cudaFuncSetAttribute(hgemm_f,    cudaFuncAttributeMaxDynamicSharedMemorySize, (int)HS_BYTES);

    // ---- fork-join streams ----
    static cudaStream_t s_char = nullptr;
    static cudaEvent_t ev_fork = nullptr, ev_join = nullptr;
    if (!s_char) {
        cudaStreamCreateWithFlags(&s_char, cudaStreamNonBlocking);
        cudaEventCreateWithFlags(&ev_fork, cudaEventDisableTiming);
        cudaEventCreateWithFlags(&ev_join, cudaEventDisableTiming);
    }
    cudaEventRecord(ev_fork, 0);
    cudaStreamWaitEvent(s_char, ev_fork, 0);

    // ======================= char path (stream s_char) ==========================
    cudaMemsetAsync(hist, 0, (Wc_ + 1) * sizeof(int), s_char);
    hist_k<<<NW_/256, 256, 0, s_char>>>(char_lens);
    scan_k<<<1, 32, 0, s_char>>>();
    scatter_k<<<NW_/256, 256, 0, s_char>>>(char_lens);
    half_remap_k<<<(CG_*CH_ + 255)/256, 256, 0, s_char>>>(c_Whh, Wc2);
    sgemm128<<<dim3(CG_/128, 1), 256, 0, s_char>>>(char_emb, c_Wih, P, 128, CG_, E_);
    reorderP_k<<<(128*CG_ + 255)/256, 256, 0, s_char>>>(c_b);
    char_gate0<<<dim3(CH_/256, NW_), 256, 0, s_char>>>(chars, hsA);
    for (int t = 1; t < Wc_; ++t) {
        const __half* rd = ((t - 1) & 1) ? hsB : hsA;
        __half*       wr = (t & 1)       ? hsB : hsA;
        hgemm_lstm<<<dim3(CG_/128, NW_/128), 256, HS_BYTES, s_char>>>(rd, Wc2, wr, chars, t);
    }
    cudaEventRecord(ev_join, s_char);

    // ======================= word path (capture stream) =========================
    half_k<<<(2*G_*E_ + 255)/256, 256>>>(l0_Wih, Wih0H, 2*G_*E_);
    half_k<<<(2*G_*CH_ + 255)/256, 256>>>(l1_Wih, Wih1H, 2*G_*CH_);
    embed_words<<<NW_, E_>>>(words, word_emb);

    {   // layer 0 (K=256, fp16 x-proj)
        const float* Whh0 = l0_Whh;
        const float* Whh1 = l0_Whh + (size_t)G_ * H_;
        hgemm_f<<<dim3(G_/128, NW_/128), 256, HS_BYTES>>>(XembH, Wih0H,                  XGf, NW_, G_, E_);
        hgemm_f<<<dim3(G_/128, NW_/128), 256, HS_BYTES>>>(XembH, Wih0H + (size_t)G_*E_,  XGb, NW_, G_, E_);
        cudaMemsetAsync(H0,  0, (size_t)NW_*CH_*sizeof(float), 0);
        cudaMemsetAsync(H0h, 0, (size_t)NW_*CH_*sizeof(__half), 0);
        cudaMemsetAsync(hpp, 0, (size_t)2*2*B_*H_*sizeof(float), 0);
        cudaMemsetAsync(bar, 0, sizeof(unsigned), 0);
        word_layer_persist<<<NBLK_, 256>>>(Whh0, Whh1, XGf, XGb, words_num, l0_b, H0, H0h);
    }
    {   // layer 1 (K=1024, fp16 x-proj)
        const float* Whh0 = l1_Whh;
        const float* Whh1 = l1_Whh + (size_t)G_ * H_;
        hgemm_f<<<dim3(G_/128, NW_/128), 256, HS_BYTES>>>(H0h, Wih1H,                   XGf, NW_, G_, CH_);
        hgemm_f<<<dim3(G_/128, NW_/128), 256, HS_BYTES>>>(H0h, Wih1H + (size_t)G_*CH_,  XGb, NW_, G_, CH_);
        cudaMemsetAsync(H1,  0, (size_t)NW_*CH_*sizeof(float), 0);
        cudaMemsetAsync(hpp, 0, (size_t)2*2*B_*H_*sizeof(float), 0);
        cudaMemsetAsync(bar, 0, sizeof(unsigned), 0);
        word_layer_persist<<<NBLK_, 256>>>(Whh0, Whh1, XGf, XGb, words_num, l1_b, H1, nullptr);
    }

    // ======================= join + head =========================
    cudaStreamWaitEvent(0, ev_join, 0);
    final_linear<<<NW_, 256>>>(words_num, lin_W, lin_b, out);
}

// round 13
// speedup vs baseline: 2.3535x; 1.3182x over previous
#include <cuda_runtime.h>
#include <cuda_fp16.h>
#include <cstdint>
#include <cstddef>

// Problem constants
#define B_   64
#define S_   128
#define Wc_  16
#define E_   256
#define H_   512
#define NC_  20
#define NW_  (B_*S_)        // 8192 words total
#define G_   (4*H_)         // 2048 word-LSTM gate width
#define CH_  (2*H_)         // 1024 char-LSTM hidden
#define CG_  (4*CH_)        // 4096 char-LSTM gate width
#define KW_  (3*H_)         // 1536: fp16x3-split K for word recurrence

#define NBLK_ 128           // persistent word-layer blocks
#define LDS_  72            // GEMM smem halfword stride (64 + 8 pad)
#define WST_  1544          // resident-W smem halfword stride (1536 + 8)
#define HS_BYTES ((size_t)4 * 128 * LDS_ * sizeof(__half))   // 73728
// word persist smem: A stages 2*64*72*2 + W 32*1544*2 + Zs 64*36*4
#define WP_SMEM (18432 + 98816 + 9216)                       // 126464

// ---------------- scratch (static device globals; no allocation) ----------------
__device__ __half g_XembH[(size_t)NW_*E_];             // word embeddings fp16
__device__ __half g_Wih0H[(size_t)2*G_*E_];            // l0_Wih fp16
__device__ __half g_Wih1H[(size_t)2*G_*CH_];           // l1_Wih fp16
__device__ __half g_WhhS0[(size_t)2*G_*KW_];           // l0_Whh split+remap [2dir][2048][1536]
__device__ __half g_WhhS1[(size_t)2*G_*KW_];           // l1_Whh split+remap
__device__ float g_XGf [(size_t)NW_*G_];               // fwd x-gates
__device__ float g_XGb [(size_t)NW_*G_];               // bwd x-gates
__device__ __half g_H0h[(size_t)NW_*CH_];              // layer0 out fp16
__device__ float g_H1  [(size_t)NW_*CH_];              // layer1 output fp32
__device__ __half g_hppS[(size_t)2*2*B_*KW_];          // h ping-pong split [buf][dir][64][1536]
__device__ unsigned g_bar;                             // grid barrier counter
__device__ float g_P  [(size_t)128*CG_];               // char_emb @ c_Wih.T (gate-major)
__device__ float g_Pp [(size_t)128*CG_];               // P interleaved j*4+g, + bias
__device__ float g_ch [(size_t)NW_*CH_];               // char h fp32 (sorted slots)
__device__ float g_cc [(size_t)NW_*CH_];               // char c state (sorted)
__device__ __half g_hsA[(size_t)NW_*CH_];              // char h fp16 buf A
__device__ __half g_hsB[(size_t)NW_*CH_];              // char h fp16 buf B
__device__ __half g_Wc2[(size_t)CG_*CH_];              // c_Whh fp16, rows j*4+g

// ---- length-sort bookkeeping ----
__device__ int g_hist[Wc_ + 1];
__device__ int g_off [Wc_ + 1];
__device__ int g_act [Wc_ + 1];
__device__ int g_perm [NW_];
__device__ int g_iperm[NW_];
__device__ int g_slen [NW_];

// ---- transcendentals ----
__device__ __forceinline__ float sigf(float x)
{
    return __fdividef(1.f, 1.f + __expf(-x));
}
__device__ __forceinline__ float tanhf_fast(float x)
{
    return __fdividef(2.f, 1.f + __expf(-2.f * x)) - 1.f;
}
__device__ __forceinline__ float tanh_ap(float x)
{
    float y;
    asm("tanh.approx.f32 %0, %1;" : "=f"(y) : "f"(x));
    return y;
}
__device__ __forceinline__ float sig_ap(float x)
{
    return fmaf(tanh_ap(0.5f * x), 0.5f, 0.5f);
}

__device__ __forceinline__ void cp16(void* dst, const void* src)
{
    uint32_t d = (uint32_t)__cvta_generic_to_shared(dst);
    asm volatile("cp.async.cg.shared.global [%0], [%1], 16;" :: "r"(d), "l"(src));
}
__device__ __forceinline__ void h16split(float x, __half& hi, __half& lo)
{
    hi = __float2half(x);
    lo = __float2half(x - __half2float(hi));
}

// ---------------- counting sort by char_lens (descending) ----------------
__global__ void hist_k(const int* __restrict__ clens)
{
    const int i = blockIdx.x * blockDim.x + threadIdx.x;
    if (i < NW_) atomicAdd(&g_hist[clens[i]], 1);
}
__global__ void scan_k()
{
    if (threadIdx.x == 0) {
        int off = 0;
        for (int len = Wc_; len >= 1; --len) { g_off[len] = off; off += g_hist[len]; }
        for (int t = 0; t <= Wc_; ++t) {
            int a = 0;
            for (int l = t + 1; l <= Wc_; ++l) a += g_hist[l];
            g_act[t] = a;
        }
    }
}
__global__ void scatter_k(const int* __restrict__ clens)
{
    const int i = blockIdx.x * blockDim.x + threadIdx.x;
    if (i < NW_) {
        const int len = clens[i];
        const int s = atomicAdd(&g_off[len], 1);
        g_perm[s] = i;
        g_iperm[i] = s;
        g_slen[s] = len;
    }
}

// generic fp32 -> fp16 copy
__global__ void half_k(const float* __restrict__ src, __half* __restrict__ dst, int total)
{
    const int i = blockIdx.x * blockDim.x + threadIdx.x;
    if (i < total) dst[i] = __float2half(src[i]);
}

// c_Whh -> fp16, gate-interleaved row remap (src r = g*CH+j -> dst j*4+g)
__global__ void half_remap_k(const float* __restrict__ src, __half* __restrict__ dst)
{
    const int i = blockIdx.x * blockDim.x + threadIdx.x;
    if (i >= CG_ * CH_) return;
    const int r = i / CH_, k = i % CH_;
    const int g = r / CH_, j = r % CH_;
    const int outr = j * 4 + g;
    dst[(size_t)outr * CH_ + k] = __float2half(src[i]);
}

// word Whh -> fp16x3 split (B-side [hi|lo|hi]) + gate-interleave per dir.
// src: [2][2048][512], src row r = g*H+j ; dst: [2][2048][1536], dst row j*4+g
__global__ void whh_split_k(const float* __restrict__ src, __half* __restrict__ dst)
{
    const int i = blockIdx.x * blockDim.x + threadIdx.x;
    if (i >= 2 * G_ * H_) return;
    const int d = i / (G_ * H_);
    const int rem = i - d * (G_ * H_);
    const int r = rem / H_, k = rem % H_;
    const int g = r >> 9, j = r & (H_ - 1);
    const int outr = j * 4 + g;
    __half hi, lo; h16split(src[i], hi, lo);
    const size_t base = ((size_t)d * G_ + outr) * KW_;
    dst[base + k] = hi; dst[base + H_ + k] = lo; dst[base + 2*H_ + k] = hi;
}

// P reorder to interleaved + fold bias
__global__ void reorderP_k(const float* __restrict__ cbias)
{
    const int i = blockIdx.x * blockDim.x + threadIdx.x;
    if (i >= 128 * CG_) return;
    const int tok = i / CG_, col = i % CG_;
    const int j = col >> 2, g = col & 3;
    const int src = g * CH_ + j;
    g_Pp[i] = g_P[(size_t)tok * CG_ + src] + cbias[src];
}

// ---------------- fp16 tensor-core GEMM: C[M,N] = A[M,K] @ B[N,K]^T (fp32 C) ----
__global__ __launch_bounds__(256)
void hgemm_f(const __half* __restrict__ A, const __half* __restrict__ Bm,
             float* __restrict__ C, int M, int N, int K)
{
    const int row0 = blockIdx.y * 128;
    const int col0 = blockIdx.x * 128;

    extern __shared__ __half smem_[];
    __half* const sA[2] = { smem_,                smem_ + 2*128*LDS_ };
    __half* const sB[2] = { smem_ + 128*LDS_,     smem_ + 3*128*LDS_ };

    const int tid  = threadIdx.x;
    const int lane = tid & 31;
    const int wid  = tid >> 5;
    const int wm   = (wid & 1) * 64;
    const int wn   = (wid >> 1) * 32;

    const int lr = tid >> 1;
    const int cb = (tid & 1) * 4;

    float acc[4][4][4];
#pragma unroll
    for (int mi = 0; mi < 4; ++mi)
#pragma unroll
        for (int ni = 0; ni < 4; ++ni)
#pragma unroll
            for (int f = 0; f < 4; ++f) acc[mi][ni][f] = 0.f;

    const int KT = K >> 6;

    {
        const __half* Ap = A  + (size_t)(row0 + lr) * K + cb * 8;
        const __half* Bp = Bm + (size_t)(col0 + lr) * K + cb * 8;
#pragma unroll
        for (int c = 0; c < 4; ++c) {
            cp16(&sA[0][lr * LDS_ + (cb + c) * 8], Ap + c * 8);
            cp16(&sB[0][lr * LDS_ + (cb + c) * 8], Bp + c * 8);
        }
        asm volatile("cp.async.commit_group;");
    }

    for (int kt = 0; kt < KT; ++kt) {
        const int buf = kt & 1;
        if (kt + 1 < KT) {
            const int k0 = (kt + 1) << 6;
            const __half* Ap = A  + (size_t)(row0 + lr) * K + k0 + cb * 8;
            const __half* Bp = Bm + (size_t)(col0 + lr) * K + k0 + cb * 8;
#pragma unroll
            for (int c = 0; c < 4; ++c) {
                cp16(&sA[buf ^ 1][lr * LDS_ + (cb + c) * 8], Ap + c * 8);
                cp16(&sB[buf ^ 1][lr * LDS_ + (cb + c) * 8], Bp + c * 8);
            }
            asm volatile("cp.async.commit_group;");
            asm volatile("cp.async.wait_group 1;");
        } else {
            asm volatile("cp.async.wait_group 0;");
        }
        __syncthreads();

        const __half* As = sA[buf];
        const __half* Bs = sB[buf];
#pragma unroll
        for (int ks = 0; ks < 4; ++ks) {
            uint32_t a[4][4], b[4][2];
#pragma unroll
            for (int mi = 0; mi < 4; ++mi) {
                uint32_t addr = (uint32_t)__cvta_generic_to_shared(
                    &As[(wm + mi*16 + (lane & 15)) * LDS_ + ks*16 + (lane >> 4) * 8]);
                asm volatile("ldmatrix.sync.aligned.m8n8.x4.shared.b16 {%0,%1,%2,%3}, [%4];"
                    : "=r"(a[mi][0]), "=r"(a[mi][1]), "=r"(a[mi][2]), "=r"(a[mi][3])
                    : "r"(addr));
            }
#pragma unroll
            for (int ni = 0; ni < 4; ++ni) {
                uint32_t addr = (uint32_t)__cvta_generic_to_shared(
                    &Bs[(wn + ni*8 + (lane & 7)) * LDS_ + ks*16 + ((lane >> 3) & 1) * 8]);
                asm volatile("ldmatrix.sync.aligned.m8n8.x2.shared.b16 {%0,%1}, [%2];"
                    : "=r"(b[ni][0]), "=r"(b[ni][1]) : "r"(addr));
            }
#pragma unroll
            for (int mi = 0; mi < 4; ++mi)
#pragma unroll
                for (int ni = 0; ni < 4; ++ni) {
                    asm volatile(
                        "mma.sync.aligned.m16n8k16.row.col.f32.f16.f16.f32 "
                        "{%0,%1,%2,%3}, {%4,%5,%6,%7}, {%8,%9}, {%0,%1,%2,%3};"
                        : "+f"(acc[mi][ni][0]), "+f"(acc[mi][ni][1]),
                          "+f"(acc[mi][ni][2]), "+f"(acc[mi][ni][3])
                        : "r"(a[mi][0]), "r"(a[mi][1]), "r"(a[mi][2]), "r"(a[mi][3]),
                          "r"(b[ni][0]), "r"(b[ni][1]));
                }
        }
        __syncthreads();
    }

#pragma unroll
    for (int mi = 0; mi < 4; ++mi)
#pragma unroll
        for (int ni = 0; ni < 4; ++ni) {
            const int r = row0 + wm + mi*16 + (lane >> 2);
            const int c = col0 + wn + ni*8 + (lane & 3) * 2;
            float2 v0 = make_float2(acc[mi][ni][0], acc[mi][ni][1]);
            float2 v1 = make_float2(acc[mi][ni][2], acc[mi][ni][3]);
            *(float2*)&C[(size_t)r * N + c]       = v0;
            *(float2*)&C[(size_t)(r + 8) * N + c] = v1;
        }
}

// ========== fused char-LSTM GEMM step ====
__global__ __launch_bounds__(256)
void hgemm_lstm(const __half* __restrict__ A, const __half* __restrict__ Bm,
                __half* __restrict__ hsW, const int* __restrict__ chars, int t)
{
    const int act_t = g_act[t];
    const int row0 = blockIdx.y * 128;
    if (row0 >= act_t) return;
    const int col0 = blockIdx.x * 128;
    const int K = CH_;

    extern __shared__ __half smem_[];
    __half* const sA[2] = { smem_,                smem_ + 2*128*LDS_ };
    __half* const sB[2] = { smem_ + 128*LDS_,     smem_ + 3*128*LDS_ };

    const int tid  = threadIdx.x;
    const int lane = tid & 31;
    const int wid  = tid >> 5;
    const int wm   = (wid & 1) * 64;
    const int wn   = (wid >> 1) * 32;

    const int lr = tid >> 1;
    const int cb = (tid & 1) * 4;

    float acc[4][4][4];
#pragma unroll
    for (int mi = 0; mi < 4; ++mi)
#pragma unroll
        for (int ni = 0; ni < 4; ++ni)
#pragma unroll
            for (int f = 0; f < 4; ++f) acc[mi][ni][f] = 0.f;

    const int KT = K >> 6;

    {
        const __half* Ap = A  + (size_t)(row0 + lr) * K + cb * 8;
        const __half* Bp = Bm + (size_t)(col0 + lr) * K + cb * 8;
#pragma unroll
        for (int c = 0; c < 4; ++c) {
            cp16(&sA[0][lr * LDS_ + (cb + c) * 8], Ap + c * 8);
            cp16(&sB[0][lr * LDS_ + (cb + c) * 8], Bp + c * 8);
        }
        asm volatile("cp.async.commit_group;");
    }

    for (int kt = 0; kt < KT; ++kt) {
        const int buf = kt & 1;
        if (kt + 1 < KT) {
            const int k0 = (kt + 1) << 6;
            const __half* Ap = A  + (size_t)(row0 + lr) * K + k0 + cb * 8;
            const __half* Bp = Bm + (size_t)(col0 + lr) * K + k0 + cb * 8;
#pragma unroll
            for (int c = 0; c < 4; ++c) {
                cp16(&sA[buf ^ 1][lr * LDS_ + (cb + c) * 8], Ap + c * 8);
                cp16(&sB[buf ^ 1][lr * LDS_ + (cb + c) * 8], Bp + c * 8);
            }
            asm volatile("cp.async.commit_group;");
            asm volatile("cp.async.wait_group 1;");
        } else {
            asm volatile("cp.async.wait_group 0;");
        }
        __syncthreads();

        const __half* As = sA[buf];
        const __half* Bs = sB[buf];
#pragma unroll
        for (int ks = 0; ks < 4; ++ks) {
            uint32_t a[4][4], b[4][2];
#pragma unroll
            for (int mi = 0; mi < 4; ++mi) {
                uint32_t addr = (uint32_t)__cvta_generic_to_shared(
                    &As[(wm + mi*16 + (lane & 15)) * LDS_ + ks*16 + (lane >> 4) * 8]);
                asm volatile("ldmatrix.sync.aligned.m8n8.x4.shared.b16 {%0,%1,%2,%3}, [%4];"
                    : "=r"(a[mi][0]), "=r"(a[mi][1]), "=r"(a[mi][2]), "=r"(a[mi][3])
                    : "r"(addr));
            }
#pragma unroll
            for (int ni = 0; ni < 4; ++ni) {
                uint32_t addr = (uint32_t)__cvta_generic_to_shared(
                    &Bs[(wn + ni*8 + (lane & 7)) * LDS_ + ks*16 + ((lane >> 3) & 1) * 8]);
                asm volatile("ldmatrix.sync.aligned.m8n8.x2.shared.b16 {%0,%1}, [%2];"
                    : "=r"(b[ni][0]), "=r"(b[ni][1]) : "r"(addr));
            }
#pragma unroll
            for (int mi = 0; mi < 4; ++mi)
#pragma unroll
                for (int ni = 0; ni < 4; ++ni) {
                    asm volatile(
                        "mma.sync.aligned.m16n8k16.row.col.f32.f16.f16.f32 "
                        "{%0,%1,%2,%3}, {%4,%5,%6,%7}, {%8,%9}, {%0,%1,%2,%3};"
                        : "+f"(acc[mi][ni][0]), "+f"(acc[mi][ni][1]),
                          "+f"(acc[mi][ni][2]), "+f"(acc[mi][ni][3])
                        : "r"(a[mi][0]), "r"(a[mi][1]), "r"(a[mi][2]), "r"(a[mi][3]),
                          "r"(b[ni][0]), "r"(b[ni][1]));
                }
        }
        __syncthreads();
    }

    float* Sg = (float*)smem_;
#pragma unroll
    for (int mi = 0; mi < 4; ++mi)
#pragma unroll
        for (int ni = 0; ni < 4; ++ni) {
            const int r = wm + mi*16 + (lane >> 2);
            const int c = wn + ni*8 + (lane & 3) * 2;
            Sg[r * 132 + c]           = acc[mi][ni][0];
            Sg[r * 132 + c + 1]       = acc[mi][ni][1];
            Sg[(r + 8) * 132 + c]     = acc[mi][ni][2];
            Sg[(r + 8) * 132 + c + 1] = acc[mi][ni][3];
        }
    __syncthreads();

    const int jb = col0 >> 2;
#pragma unroll
    for (int q = 0; q < 16; ++q) {
        const int cid = tid + q * 256;
        const int nl = cid >> 5, jl = cid & 31;
        const int n = row0 + nl;
        if (n >= act_t) continue;
        const int j = jb + jl;
        float4 z = *(float4*)&Sg[nl * 132 + jl * 4];
        const int tok = chars[g_perm[n] * Wc_ + t];
        float4 p = *(const float4*)&g_Pp[(size_t)tok * CG_ + j * 4];
        const float zi = z.x + p.x, zf = z.y + p.y, zg = z.z + p.z, zo = z.w + p.w;
        const float c_old = g_cc[(size_t)n * CH_ + j];
        const float cn = sig_ap(zf) * c_old + sig_ap(zi) * tanh_ap(zg);
        const float hn = sig_ap(zo) * tanh_ap(cn);
        g_cc[(size_t)n * CH_ + j] = cn;
        g_ch[(size_t)n * CH_ + j] = hn;
        hsW[(size_t)n * CH_ + j] = __float2half(hn);
    }
}

// ---------------- char t=0 gate ----------------
__global__ void char_gate0(const int* __restrict__ chars, __half* __restrict__ hsW)
{
    const int n = blockIdx.y;
    const int j = blockIdx.x * blockDim.x + threadIdx.x;
    const int tok = chars[g_perm[n] * Wc_ + 0];
    float4 p = *(const float4*)&g_Pp[(size_t)tok * CG_ + j * 4];
    const float cn = sig_ap(p.x) * tanh_ap(p.z);
    const float hn = sig_ap(p.w) * tanh_ap(cn);
    g_cc[(size_t)n * CH_ + j] = cn;
    g_ch[(size_t)n * CH_ + j] = hn;
    hsW[(size_t)n * CH_ + j] = __float2half(hn);
}

// ---------------- fp32 SGEMM (only for P = char_emb @ c_Wih.T, M=128) ----------
__global__ __launch_bounds__(256)
void sgemm128(const float* __restrict__ A, const float* __restrict__ Bm,
              float* __restrict__ C, int M, int N, int K)
{
    __shared__ float As[8][128];
    __shared__ float Bs[8][128];
    const int tid = threadIdx.x;
    const int tx  = tid & 15;
    const int ty  = tid >> 4;
    const int row0 = blockIdx.y * 128;
    const int col0 = blockIdx.x * 128;
    const int lr = tid >> 1;
    const int lk = (tid & 1) * 4;

    const float* Ap = A  + (size_t)(row0 + lr) * K + lk;
    const float* Bp = Bm + (size_t)(col0 + lr) * K + lk;

    float acc[8][8];
#pragma unroll
    for (int i = 0; i < 8; ++i)
#pragma unroll
        for (int j = 0; j < 8; ++j) acc[i][j] = 0.f;

    {
        float4 a = *(const float4*)Ap;
        float4 b = *(const float4*)Bp;
        As[lk+0][lr] = a.x; As[lk+1][lr] = a.y; As[lk+2][lr] = a.z; As[lk+3][lr] = a.w;
        Bs[lk+0][lr] = b.x; Bs[lk+1][lr] = b.y; Bs[lk+2][lr] = b.z; Bs[lk+3][lr] = b.w;
    }
    __syncthreads();

    int k0 = 0;
    while (true) {
        const int kn = k0 + 8;
        const bool more = kn < K;
        float4 an, bn;
        if (more) { an = *(const float4*)(Ap + kn); bn = *(const float4*)(Bp + kn); }
#pragma unroll
        for (int k = 0; k < 8; ++k) {
            float4 a0 = *(const float4*)&As[k][ty*8];
            float4 a1 = *(const float4*)&As[k][ty*8+4];
            float4 b0 = *(const float4*)&Bs[k][tx*8];
            float4 b1 = *(const float4*)&Bs[k][tx*8+4];
            float av[8] = {a0.x,a0.y,a0.z,a0.w,a1.x,a1.y,a1.z,a1.w};
            float bv[8] = {b0.x,b0.y,b0.z,b0.w,b1.x,b1.y,b1.z,b1.w};
#pragma unroll
            for (int i = 0; i < 8; ++i)
#pragma unroll
                for (int j = 0; j < 8; ++j)
                    acc[i][j] = fmaf(av[i], bv[j], acc[i][j]);
        }
        if (!more) break;
        __syncthreads();
        As[lk+0][lr] = an.x; As[lk+1][lr] = an.y; As[lk+2][lr] = an.z; As[lk+3][lr] = an.w;
        Bs[lk+0][lr] = bn.x; Bs[lk+1][lr] = bn.y; Bs[lk+2][lr] = bn.z; Bs[lk+3][lr] = bn.w;
        __syncthreads();
        k0 = kn;
    }

#pragma unroll
    for (int i = 0; i < 8; ++i) {
        const int r = row0 + ty*8 + i;
        float4 o0, o1;
        o0.x = acc[i][0]; o0.y = acc[i][1]; o0.z = acc[i][2]; o0.w = acc[i][3];
        o1.x = acc[i][4]; o1.y = acc[i][5]; o1.z = acc[i][6]; o1.w = acc[i][7];
        *(float4*)(C + (size_t)r*N + col0 + tx*8)     = o0;
        *(float4*)(C + (size_t)r*N + col0 + tx*8 + 4) = o1;
    }
}

// ============ persistent word BiLSTM layer on tensor cores (fp16x3 split) =======
// 128 blocks: dir = blk>>6, j-tile of 8 = blk&63. Per step: Z[64x32] =
// h_split[64x1536] @ W_split[32x1536]^T via HMMA (W resident in smem), then
// fused LSTM cell (c/h in regs), h re-split into global ping-pong.
__global__ __launch_bounds__(256)
void word_layer_mma(const __half* __restrict__ WhhS,
                    const float* __restrict__ XGf, const float* __restrict__ XGb,
                    const int* __restrict__ lens, const float* __restrict__ bias,
                    float* __restrict__ Hout, __half* __restrict__ HoutH)
{
    extern __shared__ char sm_[];
    __half* const sA0 = (__half*)sm_;                       // [2][64][72]
    __half* const sA1 = sA0 + 64 * LDS_;
    __half* const sW  = (__half*)(sm_ + 18432);             // [32][1544]
    float*  const Zs  = (float*)(sm_ + 18432 + 98816);      // [64][36]

    const int tid  = threadIdx.x;
    const int lane = tid & 31;
    const int wid  = tid >> 5;
    const int dir  = blockIdx.x >> 6;
    const int jt   = (blockIdx.x & 63) << 3;                // 8 j per block
    const int m0   = (wid >> 1) * 16;                       // warp m row
    const int n0   = (wid & 1) * 16;                        // warp n row

    // ---- load resident W slice: rows jt*4 .. jt*4+32 of [2048][1536] ----
    {
        const __half* Wg = WhhS + ((size_t)dir * G_ + (size_t)jt * 4) * KW_;
#pragma unroll
        for (int i = 0; i < 24; ++i) {
            const int chunk = tid + i * 256;                // 0..6143
            const int row = chunk / 192, c8 = chunk % 192;
            cp16(&sW[row * WST_ + c8 * 8], Wg + (size_t)row * KW_ + c8 * 8);
        }
        asm volatile("cp.async.commit_group;");
        asm volatile("cp.async.wait_group 0;");
    }
    __syncthreads();

    // ---- per-thread cells: (b0=bb, b1=bb+32) x j ----
    const int jl = tid & 7;
    const int bb = tid >> 3;                                // 0..31
    const int j  = jt + jl;
    const float* XG = dir ? XGb : XGf;
    const float* bv = bias + (size_t)dir * G_;
    float bg[4];
#pragma unroll
    for (int g = 0; g < 4; ++g) bg[g] = bv[g * H_ + j];
    const int len0 = lens[bb];
    const int len1 = lens[bb + 32];

    float c0 = 0.f, c1 = 0.f, h0 = 0.f, h1 = 0.f;

    const int arow = tid >> 3;                              // A-load row (0..31? no:)
    (void)arow;

    for (int t = 0; t < S_; ++t) {
        const __half* hcur = g_hppS + (size_t)(((t    ) & 1) * 2 + dir) * (B_ * KW_);
        __half*       hnxt = g_hppS + (size_t)(((t + 1) & 1) * 2 + dir) * (B_ * KW_);

        float acc[2][4];
#pragma unroll
        for (int ni = 0; ni < 2; ++ni)
#pragma unroll
            for (int f = 0; f < 4; ++f) acc[ni][f] = 0.f;

        // prologue: A chunk 0 (64 rows x 64 cols)
        {
#pragma unroll
            for (int i = 0; i < 2; ++i) {
                const int ch = tid + i * 256;               // 0..511
                const int row = ch >> 3, c8 = ch & 7;
                cp16(&sA0[row * LDS_ + c8 * 8], hcur + (size_t)row * KW_ + c8 * 8);
            }
            asm volatile("cp.async.commit_group;");
        }

        for (int kt = 0; kt < 24; ++kt) {
            __half* const sAr = (kt & 1) ? sA1 : sA0;
            if (kt + 1 < 24) {
                __half* const sAw = (kt & 1) ? sA0 : sA1;
                const int k0 = (kt + 1) << 6;
#pragma unroll
                for (int i = 0; i < 2; ++i) {
                    const int ch = tid + i * 256;
                    const int row = ch >> 3, c8 = ch & 7;
                    cp16(&sAw[row * LDS_ + c8 * 8], hcur + (size_t)row * KW_ + k0 + c8 * 8);
                }
                asm volatile("cp.async.commit_group;");
                asm volatile("cp.async.wait_group 1;");
            } else {
                asm volatile("cp.async.wait_group 0;");
            }
            __syncthreads();

#pragma unroll
            for (int ks = 0; ks < 4; ++ks) {
                uint32_t a[4], r0, r1, r2, r3;
                uint32_t addrA = (uint32_t)__cvta_generic_to_shared(
                    &sAr[(m0 + (lane & 15)) * LDS_ + ks*16 + (lane >> 4) * 8]);
                asm volatile("ldmatrix.sync.aligned.m8n8.x4.shared.b16 {%0,%1,%2,%3}, [%4];"
                    : "=r"(a[0]), "=r"(a[1]), "=r"(a[2]), "=r"(a[3]) : "r"(addrA));
                uint32_t addrB = (uint32_t)__cvta_generic_to_shared(
                    &sW[(n0 + (lane & 15)) * WST_ + kt*64 + ks*16 + (lane >> 4) * 8]);
                asm volatile("ldmatrix.sync.aligned.m8n8.x4.shared.b16 {%0,%1,%2,%3}, [%4];"
                    : "=r"(r0), "=r"(r1), "=r"(r2), "=r"(r3) : "r"(addrB));
                asm volatile(
                    "mma.sync.aligned.m16n8k16.row.col.f32.f16.f16.f32 "
                    "{%0,%1,%2,%3}, {%4,%5,%6,%7}, {%8,%9}, {%0,%1,%2,%3};"
                    : "+f"(acc[0][0]), "+f"(acc[0][1]), "+f"(acc[0][2]), "+f"(acc[0][3])
                    : "r"(a[0]), "r"(a[1]), "r"(a[2]), "r"(a[3]), "r"(r0), "r"(r2));
                asm volatile(
                    "mma.sync.aligned.m16n8k16.row.col.f32.f16.f16.f32 "
                    "{%0,%1,%2,%3}, {%4,%5,%6,%7}, {%8,%9}, {%0,%1,%2,%3};"
                    : "+f"(acc[1][0]), "+f"(acc[1][1]), "+f"(acc[1][2]), "+f"(acc[1][3])
                    : "r"(a[0]), "r"(a[1]), "r"(a[2]), "r"(a[3]), "r"(r1), "r"(r3));
            }
            __syncthreads();
        }

        // stage Z fragments to smem
        {
            const int r = m0 + (lane >> 2);
            const int c = n0 + (lane & 3) * 2;
#pragma unroll
            for (int ni = 0; ni < 2; ++ni) {
                Zs[r * 36 + c + ni*8]           = acc[ni][0];
                Zs[r * 36 + c + ni*8 + 1]       = acc[ni][1];
                Zs[(r + 8) * 36 + c + ni*8]     = acc[ni][2];
                Zs[(r + 8) * 36 + c + ni*8 + 1] = acc[ni][3];
            }
        }
        __syncthreads();

        // ---- fused LSTM cell (2 cells per thread) ----
#pragma unroll
        for (int half2i = 0; half2i < 2; ++half2i) {
            const int b = bb + half2i * 32;
            const int len = half2i ? len1 : len0;
            const bool valid = t < len;
            const int src = (dir == 0) ? t : (valid ? (len - 1 - t) : t);
            float4 z = *(float4*)&Zs[b * 36 + jl * 4];
            const float* xg = XG + (size_t)(b * S_ + src) * G_ + j;
            const float zi = z.x + xg[0]      + bg[0];
            const float zf = z.y + xg[H_]     + bg[1];
            const float zg = z.z + xg[2*H_]   + bg[2];
            const float zo = z.w + xg[3*H_]   + bg[3];
            const float c_old = half2i ? c1 : c0;
            const float cn = sigf(zf) * c_old + sigf(zi) * tanhf_fast(zg);
            const float hn = sigf(zo) * tanhf_fast(cn);
            const float h_old = half2i ? h1 : h0;
            const float h_out = valid ? hn : h_old;
            const float c_out = valid ? cn : c_old;
            if (half2i) { c1 = c_out; h1 = h_out; }
            else        { c0 = c_out; h0 = h_out; }
            __half hi, lo; h16split(h_out, hi, lo);
            __half* hb = hnxt + (size_t)b * KW_ + j;
            __stcg(hb, hi); __stcg(hb + H_, hi); __stcg(hb + 2*H_, lo);
            if (dir == 0) {
                if (valid) {
                    if (Hout)  Hout [(size_t)(b * S_ + t) * CH_ + j] = hn;
                    if (HoutH) HoutH[(size_t)(b * S_ + t) * CH_ + j] = __float2half(hn);
                }
            } else if (valid) {
                if (Hout)  Hout [(size_t)(b * S_ + src) * CH_ + H_ + j] = hn;
                if (HoutH) HoutH[(size_t)(b * S_ + src) * CH_ + H_ + j] = __float2half(hn);
            }
        }

        if (t < S_ - 1) {
            __syncthreads();
            if (tid == 0) {
                __threadfence();
                atomicAdd(&g_bar, 1u);
                const unsigned tgt = (unsigned)(t + 1) * (unsigned)NBLK_;
                volatile unsigned* p = &g_bar;
                while (*p < tgt) __nanosleep(64);
            }
            __syncthreads();
        }
    }
}

// ---------------- word embedding gather (fp16) ----------------
__global__ void embed_words(const int* __restrict__ words, const float* __restrict__ emb)
{
    const int m = blockIdx.x;
    const int e = threadIdx.x;
    g_XembH[(size_t)m*E_ + e] = __float2half(emb[(size_t)words[m] * E_ + e]);
}

// ---------------- final head ----------------
__global__ __launch_bounds__(256)
void final_linear(const int* __restrict__ wnum, const float* __restrict__ W,
                  const float* __restrict__ bias, float* __restrict__ out)
{
    const int row = blockIdx.x;
    const int b = row >> 7;
    const int s = row & (S_ - 1);
    const bool valid = s < wnum[b];
    const int slot = g_iperm[row];
    __shared__ float v[CH_];
    __shared__ float sred[8*NC_];
    const int tid = threadIdx.x;
    for (int j = tid; j < CH_; j += 256) {
        float x = g_H1[(size_t)row*CH_ + j];
        if (valid) x += g_ch[(size_t)slot*CH_ + j];
        v[j] = x;
    }
    __syncthreads();
    float acc[NC_];
#pragma unroll
    for (int c2 = 0; c2 < NC_; ++c2) acc[c2] = 0.f;
    for (int j = tid; j < CH_; j += 256) {
        float x = v[j];
#pragma unroll
        for (int c2 = 0; c2 < NC_; ++c2)
            acc[c2] = fmaf(x, W[c2*CH_ + j], acc[c2]);
    }
#pragma unroll
    for (int c2 = 0; c2 < NC_; ++c2)
#pragma unroll
        for (int off = 16; off > 0; off >>= 1)
            acc[c2] += __shfl_down_sync(0xffffffffu, acc[c2], off);
    const int lane = tid & 31, w = tid >> 5;
    if (lane == 0)
#pragma unroll
        for (int c2 = 0; c2 < NC_; ++c2) sred[w*NC_ + c2] = acc[c2];
    __syncthreads();
    if (tid < NC_) {
        float sum = bias[tid];
#pragma unroll
        for (int w2 = 0; w2 < 8; ++w2) sum += sred[w2*NC_ + tid];
        out[(size_t)row*NC_ + tid] = sum;
    }
}

// ================================================================================
extern "C" void kernel_launch(void* const* d_in, const int* in_sizes, int n_in,
                              void* d_out, int out_size)
{
    (void)in_sizes; (void)n_in; (void)out_size;
    const int*   words     = (const int*)  d_in[0];
    const int*   words_num = (const int*)  d_in[1];
    const int*   chars     = (const int*)  d_in[2];
    const int*   char_lens = (const int*)  d_in[3];
    const float* word_emb  = (const float*)d_in[4];
    const float* char_emb  = (const float*)d_in[5];
    const float* l0_Wih    = (const float*)d_in[6];
    const float* l0_Whh    = (const float*)d_in[7];
    const float* l0_b      = (const float*)d_in[8];
    const float* l1_Wih    = (const float*)d_in[9];
    const float* l1_Whh    = (const float*)d_in[10];
    const float* l1_b      = (const float*)d_in[11];
    const float* c_Wih     = (const float*)d_in[12];
    const float* c_Whh     = (const float*)d_in[13];
    const float* c_b       = (const float*)d_in[14];
    const float* lin_W     = (const float*)d_in[15];
    const float* lin_b     = (const float*)d_in[16];
    float* out = (float*)d_out;

    float *XGf, *XGb, *H1, *P;
    __half *XembH, *Wih0H, *Wih1H, *WhhS0, *WhhS1, *H0h, *hppS, *hsA, *hsB, *Wc2;
    unsigned* bar;
    int *hist;
    cudaGetSymbolAddress((void**)&XembH, g_XembH);
    cudaGetSymbolAddress((void**)&Wih0H, g_Wih0H);
    cudaGetSymbolAddress((void**)&Wih1H, g_Wih1H);
    cudaGetSymbolAddress((void**)&WhhS0, g_WhhS0);
    cudaGetSymbolAddress((void**)&WhhS1, g_WhhS1);
    cudaGetSymbolAddress((void**)&XGf,  g_XGf);
    cudaGetSymbolAddress((void**)&XGb,  g_XGb);
    cudaGetSymbolAddress((void**)&H0h,  g_H0h);
    cudaGetSymbolAddress((void**)&H1,   g_H1);
    cudaGetSymbolAddress((void**)&hppS, g_hppS);
    cudaGetSymbolAddress((void**)&bar,  g_bar);
    cudaGetSymbolAddress((void**)&P,    g_P);
    cudaGetSymbolAddress((void**)&hsA,  g_hsA);
    cudaGetSymbolAddress((void**)&hsB,  g_hsB);
    cudaGetSymbolAddress((void**)&Wc2,  g_Wc2);
    cudaGetSymbolAddress((void**)&hist, g_hist);

    cudaFuncSetAttribute(hgemm_lstm,    cudaFuncAttributeMaxDynamicSharedMemorySize, (int)HS_BYTES);
    cudaFuncSetAttribute(hgemm_f,       cudaFuncAttributeMaxDynamicSharedMemorySize, (int)HS_BYTES);
    cudaFuncSetAttribute(word_layer_mma,cudaFuncAttributeMaxDynamicSharedMemorySize, WP_SMEM);

    // ---- fork-join streams ----
    static cudaStream_t s_char = nullptr;
    static cudaEvent_t ev_fork = nullptr, ev_join = nullptr;
    if (!s_char) {
        cudaStreamCreateWithFlags(&s_char, cudaStreamNonBlocking);
        cudaEventCreateWithFlags(&ev_fork, cudaEventDisableTiming);
        cudaEventCreateWithFlags(&ev_join, cudaEventDisableTiming);
    }
    cudaEventRecord(ev_fork, 0);
    cudaStreamWaitEvent(s_char, ev_fork, 0);

    // ======================= char path (stream s_char) ==========================
    cudaMemsetAsync(hist, 0, (Wc_ + 1) * sizeof(int), s_char);
    hist_k<<<NW_/256, 256, 0, s_char>>>(char_lens);
    scan_k<<<1, 32, 0, s_char>>>();
    scatter_k<<<NW_/256, 256, 0, s_char>>>(char_lens);
    half_remap_k<<<(CG_*CH_ + 255)/256, 256, 0, s_char>>>(c_Whh, Wc2);
    sgemm128<<<dim3(CG_/128, 1), 256, 0, s_char>>>(char_emb, c_Wih, P, 128, CG_, E_);
    reorderP_k<<<(128*CG_ + 255)/256, 256, 0, s_char>>>(c_b);
    char_gate0<<<dim3(CH_/256, NW_), 256, 0, s_char>>>(chars, hsA);
    for (int t = 1; t < Wc_; ++t) {
        const __half* rd = ((t - 1) & 1) ? hsB : hsA;
        __half*       wr = (t & 1)       ? hsB : hsA;
        hgemm_lstm<<<dim3(CG_/128, NW_/128), 256, HS_BYTES, s_char>>>(rd, Wc2, wr, chars, t);
    }
    cudaEventRecord(ev_join, s_char);

    // ======================= word path (capture stream) =========================
    half_k<<<(2*G_*E_ + 255)/256, 256>>>(l0_Wih, Wih0H, 2*G_*E_);
    half_k<<<(2*G_*CH_ + 255)/256, 256>>>(l1_Wih, Wih1H, 2*G_*CH_);
    whh_split_k<<<(2*G_*H_ + 255)/256, 256>>>(l0_Whh, WhhS0);
    whh_split_k<<<(2*G_*H_ + 255)/256, 256>>>(l1_Whh, WhhS1);
    embed_words<<<NW_, E_>>>(words, word_emb);

    {   // layer 0 (fp16 x-proj, K=256)
        hgemm_f<<<dim3(G_/128, NW_/128), 256, HS_BYTES>>>(XembH, Wih0H,                  XGf, NW_, G_, E_);
        hgemm_f<<<dim3(G_/128, NW_/128), 256, HS_BYTES>>>(XembH, Wih0H + (size_t)G_*E_,  XGb, NW_, G_, E_);
        cudaMemsetAsync(H0h,  0, (size_t)NW_*CH_*sizeof(__half), 0);
        cudaMemsetAsync(hppS, 0, (size_t)2*2*B_*KW_*sizeof(__half), 0);
        cudaMemsetAsync(bar,  0, sizeof(unsigned), 0);
        word_layer_mma<<<NBLK_, 256, WP_SMEM>>>(WhhS0, XGf, XGb, words_num, l0_b, nullptr, H0h);
    }
    {   // layer 1 (fp16 x-proj, K=1024)
        hgemm_f<<<dim3(G_/128, NW_/128), 256, HS_BYTES>>>(H0h, Wih1H,                   XGf, NW_, G_, CH_);
        hgemm_f<<<dim3(G_/128, NW_/128), 256, HS_BYTES>>>(H0h, Wih1H + (size_t)G_*CH_,  XGb, NW_, G_, CH_);
        cudaMemsetAsync(H1,   0, (size_t)NW_*CH_*sizeof(float), 0);
        cudaMemsetAsync(hppS, 0, (size_t)2*2*B_*KW_*sizeof(__half), 0);
        cudaMemsetAsync(bar,  0, sizeof(unsigned), 0);
        word_layer_mma<<<NBLK_, 256, WP_SMEM>>>(WhhS1, XGf, XGb, words_num, l1_b, H1, nullptr);
    }

    // ======================= join + head =========================
    cudaStreamWaitEvent(0, ev_join, 0);
    final_linear<<<NW_, 256>>>(words_num, lin_W, lin_b, out);
}

// round 14
// speedup vs baseline: 3.2461x; 1.3792x over previous
#include <cuda_runtime.h>
#include <cuda_fp16.h>
#include <cstdint>
#include <cstddef>

// Problem constants
#define B_   64
#define S_   128
#define Wc_  16
#define E_   256
#define H_   512
#define NC_  20
#define NW_  (B_*S_)        // 8192 words total
#define G_   (4*H_)         // 2048 word-LSTM gate width
#define CH_  (2*H_)         // 1024 char-LSTM hidden
#define CG_  (4*CH_)        // 4096 char-LSTM gate width
#define KW_  (2*H_)         // 1024: fp16x2-split K for word recurrence

#define NBLK_ 128           // persistent word-layer blocks
#define LDS_  72            // GEMM smem halfword stride (64 + 8 pad)
#define LDSA_ 136           // word persist A stride (128 + 8)
#define WST_  1032          // resident-W smem halfword stride (1024 + 8)
#define HS_BYTES ((size_t)4 * 128 * LDS_ * sizeof(__half))   // 73728
// word persist smem: A stages 2*64*136*2 + W 32*1032*2 + Zs 64*36*4
#define WP_SMEM (34816 + 66048 + 9216)                       // 110080

// ---------------- scratch (static device globals; no allocation) ----------------
__device__ __half g_XembH[(size_t)NW_*E_];             // word embeddings fp16
__device__ __half g_Wih0H[(size_t)2*G_*E_];            // l0_Wih fp16
__device__ __half g_Wih1H[(size_t)2*G_*CH_];           // l1_Wih fp16
__device__ __half g_WhhS0[(size_t)2*G_*KW_];           // l0_Whh [hi|hi] remap [2][2048][1024]
__device__ __half g_WhhS1[(size_t)2*G_*KW_];           // l1_Whh [hi|hi] remap
__device__ float g_XGf [(size_t)NW_*G_];               // fwd x-gates
__device__ float g_XGb [(size_t)NW_*G_];               // bwd x-gates
__device__ __half g_H0h[(size_t)NW_*CH_];              // layer0 out fp16
__device__ float g_H1  [(size_t)NW_*CH_];              // layer1 output fp32
__device__ __half g_hppS[(size_t)2*2*B_*KW_];          // h ping-pong [hi|lo] [buf][dir][64][1024]
__device__ unsigned g_bar;                             // grid barrier counter
__device__ float g_P  [(size_t)128*CG_];               // char_emb @ c_Wih.T (gate-major)
__device__ float g_Pp [(size_t)128*CG_];               // P interleaved j*4+g, + bias
__device__ float g_ch [(size_t)NW_*CH_];               // char h fp32 (sorted slots)
__device__ float g_cc [(size_t)NW_*CH_];               // char c state (sorted)
__device__ __half g_hsA[(size_t)NW_*CH_];              // char h fp16 buf A
__device__ __half g_hsB[(size_t)NW_*CH_];              // char h fp16 buf B
__device__ __half g_Wc2[(size_t)CG_*CH_];              // c_Whh fp16, rows j*4+g

// ---- length-sort bookkeeping ----
__device__ int g_hist[Wc_ + 1];
__device__ int g_off [Wc_ + 1];
__device__ int g_act [Wc_ + 1];
__device__ int g_perm [NW_];
__device__ int g_iperm[NW_];
__device__ int g_slen [NW_];

// ---- transcendentals ----
__device__ __forceinline__ float sigf(float x)
{
    return __fdividef(1.f, 1.f + __expf(-x));
}
__device__ __forceinline__ float tanhf_fast(float x)
{
    return __fdividef(2.f, 1.f + __expf(-2.f * x)) - 1.f;
}
__device__ __forceinline__ float tanh_ap(float x)
{
    float y;
    asm("tanh.approx.f32 %0, %1;" : "=f"(y) : "f"(x));
    return y;
}
__device__ __forceinline__ float sig_ap(float x)
{
    return fmaf(tanh_ap(0.5f * x), 0.5f, 0.5f);
}

__device__ __forceinline__ void cp16(void* dst, const void* src)
{
    uint32_t d = (uint32_t)__cvta_generic_to_shared(dst);
    asm volatile("cp.async.cg.shared.global [%0], [%1], 16;" :: "r"(d), "l"(src));
}
__device__ __forceinline__ void h16split(float x, __half& hi, __half& lo)
{
    hi = __float2half(x);
    lo = __float2half(x - __half2float(hi));
}

// ---------------- counting sort by char_lens (descending) ----------------
__global__ void hist_k(const int* __restrict__ clens)
{
    const int i = blockIdx.x * blockDim.x + threadIdx.x;
    if (i < NW_) atomicAdd(&g_hist[clens[i]], 1);
}
__global__ void scan_k()
{
    if (threadIdx.x == 0) {
        int off = 0;
        for (int len = Wc_; len >= 1; --len) { g_off[len] = off; off += g_hist[len]; }
        for (int t = 0; t <= Wc_; ++t) {
            int a = 0;
            for (int l = t + 1; l <= Wc_; ++l) a += g_hist[l];
            g_act[t] = a;
        }
    }
}
__global__ void scatter_k(const int* __restrict__ clens)
{
    const int i = blockIdx.x * blockDim.x + threadIdx.x;
    if (i < NW_) {
        const int len = clens[i];
        const int s = atomicAdd(&g_off[len], 1);
        g_perm[s] = i;
        g_iperm[i] = s;
        g_slen[s] = len;
    }
}

// generic fp32 -> fp16 copy
__global__ void half_k(const float* __restrict__ src, __half* __restrict__ dst, int total)
{
    const int i = blockIdx.x * blockDim.x + threadIdx.x;
    if (i < total) dst[i] = __float2half(src[i]);
}

// c_Whh -> fp16, gate-interleaved row remap (src r = g*CH+j -> dst j*4+g)
__global__ void half_remap_k(const float* __restrict__ src, __half* __restrict__ dst)
{
    const int i = blockIdx.x * blockDim.x + threadIdx.x;
    if (i >= CG_ * CH_) return;
    const int r = i / CH_, k = i % CH_;
    const int g = r / CH_, j = r % CH_;
    const int outr = j * 4 + g;
    dst[(size_t)outr * CH_ + k] = __float2half(src[i]);
}

// word Whh -> fp16 [hi|hi] duplicate + gate-interleave per dir.
// src: [2][2048][512], src row r = g*H+j ; dst: [2][2048][1024], dst row j*4+g
__global__ void whh_split_k(const float* __restrict__ src, __half* __restrict__ dst)
{
    const int i = blockIdx.x * blockDim.x + threadIdx.x;
    if (i >= 2 * G_ * H_) return;
    const int d = i / (G_ * H_);
    const int rem = i - d * (G_ * H_);
    const int r = rem / H_, k = rem % H_;
    const int g = r >> 9, j = r & (H_ - 1);
    const int outr = j * 4 + g;
    const __half hi = __float2half(src[i]);
    const size_t base = ((size_t)d * G_ + outr) * KW_;
    dst[base + k] = hi; dst[base + H_ + k] = hi;
}

// P reorder to interleaved + fold bias
__global__ void reorderP_k(const float* __restrict__ cbias)
{
    const int i = blockIdx.x * blockDim.x + threadIdx.x;
    if (i >= 128 * CG_) return;
    const int tok = i / CG_, col = i % CG_;
    const int j = col >> 2, g = col & 3;
    const int src = g * CH_ + j;
    g_Pp[i] = g_P[(size_t)tok * CG_ + src] + cbias[src];
}

// ---------------- fp16 tensor-core GEMM: C[M,N] = A[M,K] @ B[N,K]^T (fp32 C) ----
__global__ __launch_bounds__(256)
void hgemm_f(const __half* __restrict__ A, const __half* __restrict__ Bm,
             float* __restrict__ C, int M, int N, int K)
{
    const int row0 = blockIdx.y * 128;
    const int col0 = blockIdx.x * 128;

    extern __shared__ __half smem_[];
    __half* const sA[2] = { smem_,                smem_ + 2*128*LDS_ };
    __half* const sB[2] = { smem_ + 128*LDS_,     smem_ + 3*128*LDS_ };

    const int tid  = threadIdx.x;
    const int lane = tid & 31;
    const int wid  = tid >> 5;
    const int wm   = (wid & 1) * 64;
    const int wn   = (wid >> 1) * 32;

    const int lr = tid >> 1;
    const int cb = (tid & 1) * 4;

    float acc[4][4][4];
#pragma unroll
    for (int mi = 0; mi < 4; ++mi)
#pragma unroll
        for (int ni = 0; ni < 4; ++ni)
#pragma unroll
            for (int f = 0; f < 4; ++f) acc[mi][ni][f] = 0.f;

    const int KT = K >> 6;

    {
        const __half* Ap = A  + (size_t)(row0 + lr) * K + cb * 8;
        const __half* Bp = Bm + (size_t)(col0 + lr) * K + cb * 8;
#pragma unroll
        for (int c = 0; c < 4; ++c) {
            cp16(&sA[0][lr * LDS_ + (cb + c) * 8], Ap + c * 8);
            cp16(&sB[0][lr * LDS_ + (cb + c) * 8], Bp + c * 8);
        }
        asm volatile("cp.async.commit_group;");
    }

    for (int kt = 0; kt < KT; ++kt) {
        const int buf = kt & 1;
        if (kt + 1 < KT) {
            const int k0 = (kt + 1) << 6;
            const __half* Ap = A  + (size_t)(row0 + lr) * K + k0 + cb * 8;
            const __half* Bp = Bm + (size_t)(col0 + lr) * K + k0 + cb * 8;
#pragma unroll
            for (int c = 0; c < 4; ++c) {
                cp16(&sA[buf ^ 1][lr * LDS_ + (cb + c) * 8], Ap + c * 8);
                cp16(&sB[buf ^ 1][lr * LDS_ + (cb + c) * 8], Bp + c * 8);
            }
            asm volatile("cp.async.commit_group;");
            asm volatile("cp.async.wait_group 1;");
        } else {
            asm volatile("cp.async.wait_group 0;");
        }
        __syncthreads();

        const __half* As = sA[buf];
        const __half* Bs = sB[buf];
#pragma unroll
        for (int ks = 0; ks < 4; ++ks) {
            uint32_t a[4][4], b[4][2];
#pragma unroll
            for (int mi = 0; mi < 4; ++mi) {
                uint32_t addr = (uint32_t)__cvta_generic_to_shared(
                    &As[(wm + mi*16 + (lane & 15)) * LDS_ + ks*16 + (lane >> 4) * 8]);
                asm volatile("ldmatrix.sync.aligned.m8n8.x4.shared.b16 {%0,%1,%2,%3}, [%4];"
                    : "=r"(a[mi][0]), "=r"(a[mi][1]), "=r"(a[mi][2]), "=r"(a[mi][3])
                    : "r"(addr));
            }
#pragma unroll
            for (int ni = 0; ni < 4; ++ni) {
                uint32_t addr = (uint32_t)__cvta_generic_to_shared(
                    &Bs[(wn + ni*8 + (lane & 7)) * LDS_ + ks*16 + ((lane >> 3) & 1) * 8]);
                asm volatile("ldmatrix.sync.aligned.m8n8.x2.shared.b16 {%0,%1}, [%2];"
                    : "=r"(b[ni][0]), "=r"(b[ni][1]) : "r"(addr));
            }
#pragma unroll
            for (int mi = 0; mi < 4; ++mi)
#pragma unroll
                for (int ni = 0; ni < 4; ++ni) {
                    asm volatile(
                        "mma.sync.aligned.m16n8k16.row.col.f32.f16.f16.f32 "
                        "{%0,%1,%2,%3}, {%4,%5,%6,%7}, {%8,%9}, {%0,%1,%2,%3};"
                        : "+f"(acc[mi][ni][0]), "+f"(acc[mi][ni][1]),
                          "+f"(acc[mi][ni][2]), "+f"(acc[mi][ni][3])
                        : "r"(a[mi][0]), "r"(a[mi][1]), "r"(a[mi][2]), "r"(a[mi][3]),
                          "r"(b[ni][0]), "r"(b[ni][1]));
                }
        }
        __syncthreads();
    }

#pragma unroll
    for (int mi = 0; mi < 4; ++mi)
#pragma unroll
        for (int ni = 0; ni < 4; ++ni) {
            const int r = row0 + wm + mi*16 + (lane >> 2);
            const int c = col0 + wn + ni*8 + (lane & 3) * 2;
            float2 v0 = make_float2(acc[mi][ni][0], acc[mi][ni][1]);
            float2 v1 = make_float2(acc[mi][ni][2], acc[mi][ni][3]);
            *(float2*)&C[(size_t)r * N + c]       = v0;
            *(float2*)&C[(size_t)(r + 8) * N + c] = v1;
        }
}

// ========== fused char-LSTM GEMM step ====
__global__ __launch_bounds__(256)
void hgemm_lstm(const __half* __restrict__ A, const __half* __restrict__ Bm,
                __half* __restrict__ hsW, const int* __restrict__ chars, int t)
{
    const int act_t = g_act[t];
    const int row0 = blockIdx.y * 128;
    if (row0 >= act_t) return;
    const int col0 = blockIdx.x * 128;
    const int K = CH_;

    extern __shared__ __half smem_[];
    __half* const sA[2] = { smem_,                smem_ + 2*128*LDS_ };
    __half* const sB[2] = { smem_ + 128*LDS_,     smem_ + 3*128*LDS_ };

    const int tid  = threadIdx.x;
    const int lane = tid & 31;
    const int wid  = tid >> 5;
    const int wm   = (wid & 1) * 64;
    const int wn   = (wid >> 1) * 32;

    const int lr = tid >> 1;
    const int cb = (tid & 1) * 4;

    float acc[4][4][4];
#pragma unroll
    for (int mi = 0; mi < 4; ++mi)
#pragma unroll
        for (int ni = 0; ni < 4; ++ni)
#pragma unroll
            for (int f = 0; f < 4; ++f) acc[mi][ni][f] = 0.f;

    const int KT = K >> 6;

    {
        const __half* Ap = A  + (size_t)(row0 + lr) * K + cb * 8;
        const __half* Bp = Bm + (size_t)(col0 + lr) * K + cb * 8;
#pragma unroll
        for (int c = 0; c < 4; ++c) {
            cp16(&sA[0][lr * LDS_ + (cb + c) * 8], Ap + c * 8);
            cp16(&sB[0][lr * LDS_ + (cb + c) * 8], Bp + c * 8);
        }
        asm volatile("cp.async.commit_group;");
    }

    for (int kt = 0; kt < KT; ++kt) {
        const int buf = kt & 1;
        if (kt + 1 < KT) {
            const int k0 = (kt + 1) << 6;
            const __half* Ap = A  + (size_t)(row0 + lr) * K + k0 + cb * 8;
            const __half* Bp = Bm + (size_t)(col0 + lr) * K + k0 + cb * 8;
#pragma unroll
            for (int c = 0; c < 4; ++c) {
                cp16(&sA[buf ^ 1][lr * LDS_ + (cb + c) * 8], Ap + c * 8);
                cp16(&sB[buf ^ 1][lr * LDS_ + (cb + c) * 8], Bp + c * 8);
            }
            asm volatile("cp.async.commit_group;");
            asm volatile("cp.async.wait_group 1;");
        } else {
            asm volatile("cp.async.wait_group 0;");
        }
        __syncthreads();

        const __half* As = sA[buf];
        const __half* Bs = sB[buf];
#pragma unroll
        for (int ks = 0; ks < 4; ++ks) {
            uint32_t a[4][4], b[4][2];
#pragma unroll
            for (int mi = 0; mi < 4; ++mi) {
                uint32_t addr = (uint32_t)__cvta_generic_to_shared(
                    &As[(wm + mi*16 + (lane & 15)) * LDS_ + ks*16 + (lane >> 4) * 8]);
                asm volatile("ldmatrix.sync.aligned.m8n8.x4.shared.b16 {%0,%1,%2,%3}, [%4];"
                    : "=r"(a[mi][0]), "=r"(a[mi][1]), "=r"(a[mi][2]), "=r"(a[mi][3])
                    : "r"(addr));
            }
#pragma unroll
            for (int ni = 0; ni < 4; ++ni) {
                uint32_t addr = (uint32_t)__cvta_generic_to_shared(
                    &Bs[(wn + ni*8 + (lane & 7)) * LDS_ + ks*16 + ((lane >> 3) & 1) * 8]);
                asm volatile("ldmatrix.sync.aligned.m8n8.x2.shared.b16 {%0,%1}, [%2];"
                    : "=r"(b[ni][0]), "=r"(b[ni][1]) : "r"(addr));
            }
#pragma unroll
            for (int mi = 0; mi < 4; ++mi)
#pragma unroll
                for (int ni = 0; ni < 4; ++ni) {
                    asm volatile(
                        "mma.sync.aligned.m16n8k16.row.col.f32.f16.f16.f32 "
                        "{%0,%1,%2,%3}, {%4,%5,%6,%7}, {%8,%9}, {%0,%1,%2,%3};"
                        : "+f"(acc[mi][ni][0]), "+f"(acc[mi][ni][1]),
                          "+f"(acc[mi][ni][2]), "+f"(acc[mi][ni][3])
                        : "r"(a[mi][0]), "r"(a[mi][1]), "r"(a[mi][2]), "r"(a[mi][3]),
                          "r"(b[ni][0]), "r"(b[ni][1]));
                }
        }
        __syncthreads();
    }

    float* Sg = (float*)smem_;
#pragma unroll
    for (int mi = 0; mi < 4; ++mi)
#pragma unroll
        for (int ni = 0; ni < 4; ++ni) {
            const int r = wm + mi*16 + (lane >> 2);
            const int c = wn + ni*8 + (lane & 3) * 2;
            Sg[r * 132 + c]           = acc[mi][ni][0];
            Sg[r * 132 + c + 1]       = acc[mi][ni][1];
            Sg[(r + 8) * 132 + c]     = acc[mi][ni][2];
            Sg[(r + 8) * 132 + c + 1] = acc[mi][ni][3];
        }
    __syncthreads();

    const int jb = col0 >> 2;
#pragma unroll
    for (int q = 0; q < 16; ++q) {
        const int cid = tid + q * 256;
        const int nl = cid >> 5, jl = cid & 31;
        const int n = row0 + nl;
        if (n >= act_t) continue;
        const int j = jb + jl;
        float4 z = *(float4*)&Sg[nl * 132 + jl * 4];
        const int tok = chars[g_perm[n] * Wc_ + t];
        float4 p = *(const float4*)&g_Pp[(size_t)tok * CG_ + j * 4];
        const float zi = z.x + p.x, zf = z.y + p.y, zg = z.z + p.z, zo = z.w + p.w;
        const float c_old = g_cc[(size_t)n * CH_ + j];
        const float cn = sig_ap(zf) * c_old + sig_ap(zi) * tanh_ap(zg);
        const float hn = sig_ap(zo) * tanh_ap(cn);
        g_cc[(size_t)n * CH_ + j] = cn;
        g_ch[(size_t)n * CH_ + j] = hn;
        hsW[(size_t)n * CH_ + j] = __float2half(hn);
    }
}

// ---------------- char t=0 gate ----------------
__global__ void char_gate0(const int* __restrict__ chars, __half* __restrict__ hsW)
{
    const int n = blockIdx.y;
    const int j = blockIdx.x * blockDim.x + threadIdx.x;
    const int tok = chars[g_perm[n] * Wc_ + 0];
    float4 p = *(const float4*)&g_Pp[(size_t)tok * CG_ + j * 4];
    const float cn = sig_ap(p.x) * tanh_ap(p.z);
    const float hn = sig_ap(p.w) * tanh_ap(cn);
    g_cc[(size_t)n * CH_ + j] = cn;
    g_ch[(size_t)n * CH_ + j] = hn;
    hsW[(size_t)n * CH_ + j] = __float2half(hn);
}

// ---------------- fp32 SGEMM (only for P = char_emb @ c_Wih.T, M=128) ----------
__global__ __launch_bounds__(256)
void sgemm128(const float* __restrict__ A, const float* __restrict__ Bm,
              float* __restrict__ C, int M, int N, int K)
{
    __shared__ float As[8][128];
    __shared__ float Bs[8][128];
    const int tid = threadIdx.x;
    const int tx  = tid & 15;
    const int ty  = tid >> 4;
    const int row0 = blockIdx.y * 128;
    const int col0 = blockIdx.x * 128;
    const int lr = tid >> 1;
    const int lk = (tid & 1) * 4;

    const float* Ap = A  + (size_t)(row0 + lr) * K + lk;
    const float* Bp = Bm + (size_t)(col0 + lr) * K + lk;

    float acc[8][8];
#pragma unroll
    for (int i = 0; i < 8; ++i)
#pragma unroll
        for (int j = 0; j < 8; ++j) acc[i][j] = 0.f;

    {
        float4 a = *(const float4*)Ap;
        float4 b = *(const float4*)Bp;
        As[lk+0][lr] = a.x; As[lk+1][lr] = a.y; As[lk+2][lr] = a.z; As[lk+3][lr] = a.w;
        Bs[lk+0][lr] = b.x; Bs[lk+1][lr] = b.y; Bs[lk+2][lr] = b.z; Bs[lk+3][lr] = b.w;
    }
    __syncthreads();

    int k0 = 0;
    while (true) {
        const int kn = k0 + 8;
        const bool more = kn < K;
        float4 an, bn;
        if (more) { an = *(const float4*)(Ap + kn); bn = *(const float4*)(Bp + kn); }
#pragma unroll
        for (int k = 0; k < 8; ++k) {
            float4 a0 = *(const float4*)&As[k][ty*8];
            float4 a1 = *(const float4*)&As[k][ty*8+4];
            float4 b0 = *(const float4*)&Bs[k][tx*8];
            float4 b1 = *(const float4*)&Bs[k][tx*8+4];
            float av[8] = {a0.x,a0.y,a0.z,a0.w,a1.x,a1.y,a1.z,a1.w};
            float bv[8] = {b0.x,b0.y,b0.z,b0.w,b1.x,b1.y,b1.z,b1.w};
#pragma unroll
            for (int i = 0; i < 8; ++i)
#pragma unroll
                for (int j = 0; j < 8; ++j)
                    acc[i][j] = fmaf(av[i], bv[j], acc[i][j]);
        }
        if (!more) break;
        __syncthreads();
        As[lk+0][lr] = an.x; As[lk+1][lr] = an.y; As[lk+2][lr] = an.z; As[lk+3][lr] = an.w;
        Bs[lk+0][lr] = bn.x; Bs[lk+1][lr] = bn.y; Bs[lk+2][lr] = bn.z; Bs[lk+3][lr] = bn.w;
        __syncthreads();
        k0 = kn;
    }

#pragma unroll
    for (int i = 0; i < 8; ++i) {
        const int r = row0 + ty*8 + i;
        float4 o0, o1;
        o0.x = acc[i][0]; o0.y = acc[i][1]; o0.z = acc[i][2]; o0.w = acc[i][3];
        o1.x = acc[i][4]; o1.y = acc[i][5]; o1.z = acc[i][6]; o1.w = acc[i][7];
        *(float4*)(C + (size_t)r*N + col0 + tx*8)     = o0;
        *(float4*)(C + (size_t)r*N + col0 + tx*8 + 4) = o1;
    }
}

// ============ persistent word BiLSTM layer on tensor cores (fp16x2 split) =======
// A = [h_hi | h_lo] (state exact), B = [w_hi | w_hi] (static weight quantization).
// 128 blocks: dir = blk>>6, 8 j per block. Per step: Z[64x32] = A[64x1024] @
// W[32x1024]^T via HMMA (W resident in smem), fused LSTM cell (c/h fp32 regs).
__global__ __launch_bounds__(256)
void word_layer_mma(const __half* __restrict__ WhhS,
                    const float* __restrict__ XGf, const float* __restrict__ XGb,
                    const int* __restrict__ lens, const float* __restrict__ bias,
                    float* __restrict__ Hout, __half* __restrict__ HoutH)
{
    extern __shared__ char sm_[];
    __half* const sA0 = (__half*)sm_;                       // [2][64][136]
    __half* const sA1 = sA0 + 64 * LDSA_;
    __half* const sW  = (__half*)(sm_ + 34816);             // [32][1032]
    float*  const Zs  = (float*)(sm_ + 34816 + 66048);      // [64][36]

    const int tid  = threadIdx.x;
    const int lane = tid & 31;
    const int wid  = tid >> 5;
    const int dir  = blockIdx.x >> 6;
    const int jt   = (blockIdx.x & 63) << 3;                // 8 j per block
    const int m0   = (wid >> 1) * 16;                       // warp m row
    const int n0   = (wid & 1) * 16;                        // warp n row

    // ---- load resident W slice: rows jt*4 .. jt*4+32 of [2048][1024] ----
    {
        const __half* Wg = WhhS + ((size_t)dir * G_ + (size_t)jt * 4) * KW_;
#pragma unroll
        for (int i = 0; i < 16; ++i) {
            const int chunk = tid + i * 256;                // 0..4095
            const int row = chunk >> 7, c8 = chunk & 127;
            cp16(&sW[row * WST_ + c8 * 8], Wg + (size_t)row * KW_ + c8 * 8);
        }
        asm volatile("cp.async.commit_group;");
        asm volatile("cp.async.wait_group 0;");
    }
    __syncthreads();

    // ---- per-thread cells: (b0=bb, b1=bb+32) x j ----
    const int jl = tid & 7;
    const int bb = tid >> 3;                                // 0..31
    const int j  = jt + jl;
    const float* XG = dir ? XGb : XGf;
    const float* bv = bias + (size_t)dir * G_;
    float bg[4];
#pragma unroll
    for (int g = 0; g < 4; ++g) bg[g] = bv[g * H_ + j];
    const int len0 = lens[bb];
    const int len1 = lens[bb + 32];

    float c0 = 0.f, c1 = 0.f, h0 = 0.f, h1 = 0.f;

    for (int t = 0; t < S_; ++t) {
        const __half* hcur = g_hppS + (size_t)(((t    ) & 1) * 2 + dir) * (B_ * KW_);
        __half*       hnxt = g_hppS + (size_t)(((t + 1) & 1) * 2 + dir) * (B_ * KW_);

        float acc[2][4];
#pragma unroll
        for (int ni = 0; ni < 2; ++ni)
#pragma unroll
            for (int f = 0; f < 4; ++f) acc[ni][f] = 0.f;

        // prologue: A chunk 0 (64 rows x 128 cols)
        {
#pragma unroll
            for (int i = 0; i < 4; ++i) {
                const int ch = tid + i * 256;               // 0..1023
                const int row = ch >> 4, c8 = ch & 15;
                cp16(&sA0[row * LDSA_ + c8 * 8], hcur + (size_t)row * KW_ + c8 * 8);
            }
            asm volatile("cp.async.commit_group;");
        }

        for (int kt = 0; kt < 8; ++kt) {
            __half* const sAr = (kt & 1) ? sA1 : sA0;
            if (kt + 1 < 8) {
                __half* const sAw = (kt & 1) ? sA0 : sA1;
                const int k0 = (kt + 1) << 7;
#pragma unroll
                for (int i = 0; i < 4; ++i) {
                    const int ch = tid + i * 256;
                    const int row = ch >> 4, c8 = ch & 15;
                    cp16(&sAw[row * LDSA_ + c8 * 8], hcur + (size_t)row * KW_ + k0 + c8 * 8);
                }
                asm volatile("cp.async.commit_group;");
                asm volatile("cp.async.wait_group 1;");
            } else {
                asm volatile("cp.async.wait_group 0;");
            }
            __syncthreads();

#pragma unroll
            for (int ks = 0; ks < 8; ++ks) {
                uint32_t a[4], r0, r1, r2, r3;
                uint32_t addrA = (uint32_t)__cvta_generic_to_shared(
                    &sAr[(m0 + (lane & 15)) * LDSA_ + ks*16 + (lane >> 4) * 8]);
                asm volatile("ldmatrix.sync.aligned.m8n8.x4.shared.b16 {%0,%1,%2,%3}, [%4];"
                    : "=r"(a[0]), "=r"(a[1]), "=r"(a[2]), "=r"(a[3]) : "r"(addrA));
                uint32_t addrB = (uint32_t)__cvta_generic_to_shared(
                    &sW[(n0 + (lane & 15)) * WST_ + kt*128 + ks*16 + (lane >> 4) * 8]);
                asm volatile("ldmatrix.sync.aligned.m8n8.x4.shared.b16 {%0,%1,%2,%3}, [%4];"
                    : "=r"(r0), "=r"(r1), "=r"(r2), "=r"(r3) : "r"(addrB));
                asm volatile(
                    "mma.sync.aligned.m16n8k16.row.col.f32.f16.f16.f32 "
                    "{%0,%1,%2,%3}, {%4,%5,%6,%7}, {%8,%9}, {%0,%1,%2,%3};"
                    : "+f"(acc[0][0]), "+f"(acc[0][1]), "+f"(acc[0][2]), "+f"(acc[0][3])
                    : "r"(a[0]), "r"(a[1]), "r"(a[2]), "r"(a[3]), "r"(r0), "r"(r2));
                asm volatile(
                    "mma.sync.aligned.m16n8k16.row.col.f32.f16.f16.f32 "
                    "{%0,%1,%2,%3}, {%4,%5,%6,%7}, {%8,%9}, {%0,%1,%2,%3};"
                    : "+f"(acc[1][0]), "+f"(acc[1][1]), "+f"(acc[1][2]), "+f"(acc[1][3])
                    : "r"(a[0]), "r"(a[1]), "r"(a[2]), "r"(a[3]), "r"(r1), "r"(r3));
            }
            __syncthreads();
        }

        // stage Z fragments to smem
        {
            const int r = m0 + (lane >> 2);
            const int c = n0 + (lane & 3) * 2;
#pragma unroll
            for (int ni = 0; ni < 2; ++ni) {
                Zs[r * 36 + c + ni*8]           = acc[ni][0];
                Zs[r * 36 + c + ni*8 + 1]       = acc[ni][1];
                Zs[(r + 8) * 36 + c + ni*8]     = acc[ni][2];
                Zs[(r + 8) * 36 + c + ni*8 + 1] = acc[ni][3];
            }
        }
        __syncthreads();

        // ---- fused LSTM cell (2 cells per thread) ----
#pragma unroll
        for (int half2i = 0; half2i < 2; ++half2i) {
            const int b = bb + half2i * 32;
            const int len = half2i ? len1 : len0;
            const bool valid = t < len;
            const int src = (dir == 0) ? t : (valid ? (len - 1 - t) : t);
            float4 z = *(float4*)&Zs[b * 36 + jl * 4];
            const float* xg = XG + (size_t)(b * S_ + src) * G_ + j;
            const float zi = z.x + xg[0]      + bg[0];
            const float zf = z.y + xg[H_]     + bg[1];
            const float zg = z.z + xg[2*H_]   + bg[2];
            const float zo = z.w + xg[3*H_]   + bg[3];
            const float c_old = half2i ? c1 : c0;
            const float cn = sigf(zf) * c_old + sigf(zi) * tanhf_fast(zg);
            const float hn = sigf(zo) * tanhf_fast(cn);
            const float h_old = half2i ? h1 : h0;
            const float h_out = valid ? hn : h_old;
            const float c_out = valid ? cn : c_old;
            if (half2i) { c1 = c_out; h1 = h_out; }
            else        { c0 = c_out; h0 = h_out; }
            __half hi, lo; h16split(h_out, hi, lo);
            __half* hb = hnxt + (size_t)b * KW_ + j;
            __stcg(hb, hi); __stcg(hb + H_, lo);
            if (dir == 0) {
                if (valid) {
                    if (Hout)  Hout [(size_t)(b * S_ + t) * CH_ + j] = hn;
                    if (HoutH) HoutH[(size_t)(b * S_ + t) * CH_ + j] = __float2half(hn);
                }
            } else if (valid) {
                if (Hout)  Hout [(size_t)(b * S_ + src) * CH_ + H_ + j] = hn;
                if (HoutH) HoutH[(size_t)(b * S_ + src) * CH_ + H_ + j] = __float2half(hn);
            }
        }

        if (t < S_ - 1) {
            __syncthreads();
            if (tid == 0) {
                __threadfence();
                atomicAdd(&g_bar, 1u);
                const unsigned tgt = (unsigned)(t + 1) * (unsigned)NBLK_;
                volatile unsigned* p = &g_bar;
                while (*p < tgt) __nanosleep(64);
            }
            __syncthreads();
        }
    }
}

// ---------------- word embedding gather (fp16) ----------------
__global__ void embed_words(const int* __restrict__ words, const float* __restrict__ emb)
{
    const int m = blockIdx.x;
    const int e = threadIdx.x;
    g_XembH[(size_t)m*E_ + e] = __float2half(emb[(size_t)words[m] * E_ + e]);
}

// ---------------- final head ----------------
__global__ __launch_bounds__(256)
void final_linear(const int* __restrict__ wnum, const float* __restrict__ W,
                  const float* __restrict__ bias, float* __restrict__ out)
{
    const int row = blockIdx.x;
    const int b = row >> 7;
    const int s = row & (S_ - 1);
    const bool valid = s < wnum[b];
    const int slot = g_iperm[row];
    __shared__ float v[CH_];
    __shared__ float sred[8*NC_];
    const int tid = threadIdx.x;
    for (int j = tid; j < CH_; j += 256) {
        float x = g_H1[(size_t)row*CH_ + j];
        if (valid) x += g_ch[(size_t)slot*CH_ + j];
        v[j] = x;
    }
    __syncthreads();
    float acc[NC_];
#pragma unroll
    for (int c2 = 0; c2 < NC_; ++c2) acc[c2] = 0.f;
    for (int j = tid; j < CH_; j += 256) {
        float x = v[j];
#pragma unroll
        for (int c2 = 0; c2 < NC_; ++c2)
            acc[c2] = fmaf(x, W[c2*CH_ + j], acc[c2]);
    }
#pragma unroll
    for (int c2 = 0; c2 < NC_; ++c2)
#pragma unroll
        for (int off = 16; off > 0; off >>= 1)
            acc[c2] += __shfl_down_sync(0xffffffffu, acc[c2], off);
    const int lane = tid & 31, w = tid >> 5;
    if (lane == 0)
#pragma unroll
        for (int c2 = 0; c2 < NC_; ++c2) sred[w*NC_ + c2] = acc[c2];
    __syncthreads();
    if (tid < NC_) {
        float sum = bias[tid];
#pragma unroll
        for (int w2 = 0; w2 < 8; ++w2) sum += sred[w2*NC_ + tid];
        out[(size_t)row*NC_ + tid] = sum;
    }
}

// ================================================================================
extern "C" void kernel_launch(void* const* d_in, const int* in_sizes, int n_in,
                              void* d_out, int out_size)
{
    (void)in_sizes; (void)n_in; (void)out_size;
    const int*   words     = (const int*)  d_in[0];
    const int*   words_num = (const int*)  d_in[1];
    const int*   chars     = (const int*)  d_in[2];
    const int*   char_lens = (const int*)  d_in[3];
    const float* word_emb  = (const float*)d_in[4];
    const float* char_emb  = (const float*)d_in[5];
    const float* l0_Wih    = (const float*)d_in[6];
    const float* l0_Whh    = (const float*)d_in[7];
    const float* l0_b      = (const float*)d_in[8];
    const float* l1_Wih    = (const float*)d_in[9];
    const float* l1_Whh    = (const float*)d_in[10];
    const float* l1_b      = (const float*)d_in[11];
    const float* c_Wih     = (const float*)d_in[12];
    const float* c_Whh     = (const float*)d_in[13];
    const float* c_b       = (const float*)d_in[14];
    const float* lin_W     = (const float*)d_in[15];
    const float* lin_b     = (const float*)d_in[16];
    float* out = (float*)d_out;

    float *XGf, *XGb, *H1, *P;
    __half *XembH, *Wih0H, *Wih1H, *WhhS0, *WhhS1, *H0h, *hppS, *hsA, *hsB, *Wc2;
    unsigned* bar;
    int *hist;
    cudaGetSymbolAddress((void**)&XembH, g_XembH);
    cudaGetSymbolAddress((void**)&Wih0H, g_Wih0H);
    cudaGetSymbolAddress((void**)&Wih1H, g_Wih1H);
    cudaGetSymbolAddress((void**)&WhhS0, g_WhhS0);
    cudaGetSymbolAddress((void**)&WhhS1, g_WhhS1);
    cudaGetSymbolAddress((void**)&XGf,  g_XGf);
    cudaGetSymbolAddress((void**)&XGb,  g_XGb);
    cudaGetSymbolAddress((void**)&H0h,  g_H0h);
    cudaGetSymbolAddress((void**)&H1,   g_H1);
    cudaGetSymbolAddress((void**)&hppS, g_hppS);
    cudaGetSymbolAddress((void**)&bar,  g_bar);
    cudaGetSymbolAddress((void**)&P,    g_P);
    cudaGetSymbolAddress((void**)&hsA,  g_hsA);
    cudaGetSymbolAddress((void**)&hsB,  g_hsB);
    cudaGetSymbolAddress((void**)&Wc2,  g_Wc2);
    cudaGetSymbolAddress((void**)&hist, g_hist);

    cudaFuncSetAttribute(hgemm_lstm,    cudaFuncAttributeMaxDynamicSharedMemorySize, (int)HS_BYTES);
    cudaFuncSetAttribute(hgemm_f,       cudaFuncAttributeMaxDynamicSharedMemorySize, (int)HS_BYTES);
    cudaFuncSetAttribute(word_layer_mma,cudaFuncAttributeMaxDynamicSharedMemorySize, WP_SMEM);

    // ---- fork-join streams ----
    static cudaStream_t s_char = nullptr;
    static cudaEvent_t ev_fork = nullptr, ev_join = nullptr;
    if (!s_char) {
        cudaStreamCreateWithFlags(&s_char, cudaStreamNonBlocking);
        cudaEventCreateWithFlags(&ev_fork, cudaEventDisableTiming);
        cudaEventCreateWithFlags(&ev_join, cudaEventDisableTiming);
    }
    cudaEventRecord(ev_fork, 0);
    cudaStreamWaitEvent(s_char, ev_fork, 0);

    // ======================= char path (stream s_char) ==========================
    cudaMemsetAsync(hist, 0, (Wc_ + 1) * sizeof(int), s_char);
    hist_k<<<NW_/256, 256, 0, s_char>>>(char_lens);
    scan_k<<<1, 32, 0, s_char>>>();
    scatter_k<<<NW_/256, 256, 0, s_char>>>(char_lens);
    half_remap_k<<<(CG_*CH_ + 255)/256, 256, 0, s_char>>>(c_Whh, Wc2);
    sgemm128<<<dim3(CG_/128, 1), 256, 0, s_char>>>(char_emb, c_Wih, P, 128, CG_, E_);
    reorderP_k<<<(128*CG_ + 255)/256, 256, 0, s_char>>>(c_b);
    char_gate0<<<dim3(CH_/256, NW_), 256, 0, s_char>>>(chars, hsA);
    for (int t = 1; t < Wc_; ++t) {
        const __half* rd = ((t - 1) & 1) ? hsB : hsA;
        __half*       wr = (t & 1)       ? hsB : hsA;
        hgemm_lstm<<<dim3(CG_/128, NW_/128), 256, HS_BYTES, s_char>>>(rd, Wc2, wr, chars, t);
    }
    cudaEventRecord(ev_join, s_char);

    // ======================= word path (capture stream) =========================
    half_k<<<(2*G_*E_ + 255)/256, 256>>>(l0_Wih, Wih0H, 2*G_*E_);
    half_k<<<(2*G_*CH_ + 255)/256, 256>>>(l1_Wih, Wih1H, 2*G_*CH_);
    whh_split_k<<<(2*G_*H_ + 255)/256, 256>>>(l0_Whh, WhhS0);
    whh_split_k<<<(2*G_*H_ + 255)/256, 256>>>(l1_Whh, WhhS1);
    embed_words<<<NW_, E_>>>(words, word_emb);

    {   // layer 0 (fp16 x-proj, K=256)
        hgemm_f<<<dim3(G_/128, NW_/128), 256, HS_BYTES>>>(XembH, Wih0H,                  XGf, NW_, G_, E_);
        hgemm_f<<<dim3(G_/128, NW_/128), 256, HS_BYTES>>>(XembH, Wih0H + (size_t)G_*E_,  XGb, NW_, G_, E_);
        cudaMemsetAsync(H0h,  0, (size_t)NW_*CH_*sizeof(__half), 0);
        cudaMemsetAsync(hppS, 0, (size_t)2*2*B_*KW_*sizeof(__half), 0);
        cudaMemsetAsync(bar,  0, sizeof(unsigned), 0);
        word_layer_mma<<<NBLK_, 256, WP_SMEM>>>(WhhS0, XGf, XGb, words_num, l0_b, nullptr, H0h);
    }
    {   // layer 1 (fp16 x-proj, K=1024)
        hgemm_f<<<dim3(G_/128, NW_/128), 256, HS_BYTES>>>(H0h, Wih1H,                   XGf, NW_, G_, CH_);
        hgemm_f<<<dim3(G_/128, NW_/128), 256, HS_BYTES>>>(H0h, Wih1H + (size_t)G_*CH_,  XGb, NW_, G_, CH_);
        cudaMemsetAsync(H1,   0, (size_t)NW_*CH_*sizeof(float), 0);
        cudaMemsetAsync(hppS, 0, (size_t)2*2*B_*KW_*sizeof(__half), 0);
        cudaMemsetAsync(bar,  0, sizeof(unsigned), 0);
        word_layer_mma<<<NBLK_, 256, WP_SMEM>>>(WhhS1, XGf, XGb, words_num, l1_b, H1, nullptr);
    }

    // ======================= join + head =========================
    cudaStreamWaitEvent(0, ev_join, 0);
    final_linear<<<NW_, 256>>>(words_num, lin_W, lin_b, out);
}

// round 15
// speedup vs baseline: 3.4780x; 1.0714x over previous
#include <cuda_runtime.h>
#include <cuda_fp16.h>
#include <cstdint>
#include <cstddef>

// Problem constants
#define B_   64
#define S_   128
#define Wc_  16
#define E_   256
#define H_   512
#define NC_  20
#define NW_  (B_*S_)        // 8192 words total
#define G_   (4*H_)         // 2048 word-LSTM gate width
#define CH_  (2*H_)         // 1024 char-LSTM hidden
#define CG_  (4*CH_)        // 4096 char-LSTM gate width
#define KW_  (H_)           // 512: fp16x1 K for word recurrence

#define NBLK_ 128           // persistent word-layer blocks
#define LDS_  72            // GEMM smem halfword stride (64 + 8 pad)
#define LDSA_ 136           // word persist A stride (128 + 8)
#define WST_  520           // resident-W smem halfword stride (512 + 8)
#define HS_BYTES ((size_t)4 * 128 * LDS_ * sizeof(__half))   // 73728
// word persist smem: A stages 2*64*136*2 + W 32*520*2 + Zs 64*36*4
#define WP_SMEM (34816 + 33280 + 9216)                       // 77312

// ---------------- scratch (static device globals; no allocation) ----------------
__device__ __half g_XembH[(size_t)NW_*E_];             // word embeddings fp16
__device__ __half g_Wih0H[(size_t)2*G_*E_];            // l0_Wih fp16 [2dirs contiguous]
__device__ __half g_Wih1H[(size_t)2*G_*CH_];           // l1_Wih fp16
__device__ __half g_WhhS0[(size_t)2*G_*KW_];           // l0_Whh hi remap [2][2048][512]
__device__ __half g_WhhS1[(size_t)2*G_*KW_];           // l1_Whh hi remap
__device__ float g_XG  [(size_t)NW_*2*G_];             // x-gates [8192][2dirs*2048]
__device__ __half g_H0h[(size_t)NW_*CH_];              // layer0 out fp16
__device__ float g_H1  [(size_t)NW_*CH_];              // layer1 output fp32
__device__ __half g_hppS[(size_t)2*2*B_*KW_];          // h ping-pong hi [buf][dir][64][512]
__device__ unsigned g_bar;                             // grid barrier counter
__device__ float g_P  [(size_t)128*CG_];               // char_emb @ c_Wih.T (gate-major)
__device__ float g_Pp [(size_t)128*CG_];               // P interleaved j*4+g, + bias
__device__ float g_ch [(size_t)NW_*CH_];               // char h fp32 (sorted slots)
__device__ float g_cc [(size_t)NW_*CH_];               // char c state (sorted)
__device__ __half g_hsA[(size_t)NW_*CH_];              // char h fp16 buf A
__device__ __half g_hsB[(size_t)NW_*CH_];              // char h fp16 buf B
__device__ __half g_Wc2[(size_t)CG_*CH_];              // c_Whh fp16, rows j*4+g

// ---- length-sort bookkeeping ----
__device__ int g_hist[Wc_ + 1];
__device__ int g_off [Wc_ + 1];
__device__ int g_act [Wc_ + 1];
__device__ int g_perm [NW_];
__device__ int g_iperm[NW_];
__device__ int g_slen [NW_];

// ---- transcendentals ----
__device__ __forceinline__ float sigf(float x)
{
    return __fdividef(1.f, 1.f + __expf(-x));
}
__device__ __forceinline__ float tanhf_fast(float x)
{
    return __fdividef(2.f, 1.f + __expf(-2.f * x)) - 1.f;
}
__device__ __forceinline__ float tanh_ap(float x)
{
    float y;
    asm("tanh.approx.f32 %0, %1;" : "=f"(y) : "f"(x));
    return y;
}
__device__ __forceinline__ float sig_ap(float x)
{
    return fmaf(tanh_ap(0.5f * x), 0.5f, 0.5f);
}

__device__ __forceinline__ void cp16(void* dst, const void* src)
{
    uint32_t d = (uint32_t)__cvta_generic_to_shared(dst);
    asm volatile("cp.async.cg.shared.global [%0], [%1], 16;" :: "r"(d), "l"(src));
}

// ---------------- counting sort by char_lens (descending) ----------------
__global__ void hist_k(const int* __restrict__ clens)
{
    const int i = blockIdx.x * blockDim.x + threadIdx.x;
    if (i < NW_) atomicAdd(&g_hist[clens[i]], 1);
}
__global__ void scan_k()
{
    if (threadIdx.x == 0) {
        int off = 0;
        for (int len = Wc_; len >= 1; --len) { g_off[len] = off; off += g_hist[len]; }
        for (int t = 0; t <= Wc_; ++t) {
            int a = 0;
            for (int l = t + 1; l <= Wc_; ++l) a += g_hist[l];
            g_act[t] = a;
        }
    }
}
__global__ void scatter_k(const int* __restrict__ clens)
{
    const int i = blockIdx.x * blockDim.x + threadIdx.x;
    if (i < NW_) {
        const int len = clens[i];
        const int s = atomicAdd(&g_off[len], 1);
        g_perm[s] = i;
        g_iperm[i] = s;
        g_slen[s] = len;
    }
}

// generic fp32 -> fp16 copy
__global__ void half_k(const float* __restrict__ src, __half* __restrict__ dst, int total)
{
    const int i = blockIdx.x * blockDim.x + threadIdx.x;
    if (i < total) dst[i] = __float2half(src[i]);
}

// c_Whh -> fp16, gate-interleaved row remap (src r = g*CH+j -> dst j*4+g)
__global__ void half_remap_k(const float* __restrict__ src, __half* __restrict__ dst)
{
    const int i = blockIdx.x * blockDim.x + threadIdx.x;
    if (i >= CG_ * CH_) return;
    const int r = i / CH_, k = i % CH_;
    const int g = r / CH_, j = r % CH_;
    const int outr = j * 4 + g;
    dst[(size_t)outr * CH_ + k] = __float2half(src[i]);
}

// word Whh -> fp16 hi + gate-interleave per dir.
// src: [2][2048][512], src row r = g*H+j ; dst: [2][2048][512], dst row j*4+g
__global__ void whh_split_k(const float* __restrict__ src, __half* __restrict__ dst)
{
    const int i = blockIdx.x * blockDim.x + threadIdx.x;
    if (i >= 2 * G_ * H_) return;
    const int d = i / (G_ * H_);
    const int rem = i - d * (G_ * H_);
    const int r = rem / H_, k = rem % H_;
    const int g = r >> 9, j = r & (H_ - 1);
    const int outr = j * 4 + g;
    dst[((size_t)d * G_ + outr) * KW_ + k] = __float2half(src[i]);
}

// P reorder to interleaved + fold bias
__global__ void reorderP_k(const float* __restrict__ cbias)
{
    const int i = blockIdx.x * blockDim.x + threadIdx.x;
    if (i >= 128 * CG_) return;
    const int tok = i / CG_, col = i % CG_;
    const int j = col >> 2, g = col & 3;
    const int src = g * CH_ + j;
    g_Pp[i] = g_P[(size_t)tok * CG_ + src] + cbias[src];
}

// ---------------- fp16 tensor-core GEMM: C[M,N] = A[M,K] @ B[N,K]^T (fp32 C) ----
__global__ __launch_bounds__(256)
void hgemm_f(const __half* __restrict__ A, const __half* __restrict__ Bm,
             float* __restrict__ C, int M, int N, int K)
{
    const int row0 = blockIdx.y * 128;
    const int col0 = blockIdx.x * 128;

    extern __shared__ __half smem_[];
    __half* const sA[2] = { smem_,                smem_ + 2*128*LDS_ };
    __half* const sB[2] = { smem_ + 128*LDS_,     smem_ + 3*128*LDS_ };

    const int tid  = threadIdx.x;
    const int lane = tid & 31;
    const int wid  = tid >> 5;
    const int wm   = (wid & 1) * 64;
    const int wn   = (wid >> 1) * 32;

    const int lr = tid >> 1;
    const int cb = (tid & 1) * 4;

    float acc[4][4][4];
#pragma unroll
    for (int mi = 0; mi < 4; ++mi)
#pragma unroll
        for (int ni = 0; ni < 4; ++ni)
#pragma unroll
            for (int f = 0; f < 4; ++f) acc[mi][ni][f] = 0.f;

    const int KT = K >> 6;

    {
        const __half* Ap = A  + (size_t)(row0 + lr) * K + cb * 8;
        const __half* Bp = Bm + (size_t)(col0 + lr) * K + cb * 8;
#pragma unroll
        for (int c = 0; c < 4; ++c) {
            cp16(&sA[0][lr * LDS_ + (cb + c) * 8], Ap + c * 8);
            cp16(&sB[0][lr * LDS_ + (cb + c) * 8], Bp + c * 8);
        }
        asm volatile("cp.async.commit_group;");
    }

    for (int kt = 0; kt < KT; ++kt) {
        const int buf = kt & 1;
        if (kt + 1 < KT) {
            const int k0 = (kt + 1) << 6;
            const __half* Ap = A  + (size_t)(row0 + lr) * K + k0 + cb * 8;
            const __half* Bp = Bm + (size_t)(col0 + lr) * K + k0 + cb * 8;
#pragma unroll
            for (int c = 0; c < 4; ++c) {
                cp16(&sA[buf ^ 1][lr * LDS_ + (cb + c) * 8], Ap + c * 8);
                cp16(&sB[buf ^ 1][lr * LDS_ + (cb + c) * 8], Bp + c * 8);
            }
            asm volatile("cp.async.commit_group;");
            asm volatile("cp.async.wait_group 1;");
        } else {
            asm volatile("cp.async.wait_group 0;");
        }
        __syncthreads();

        const __half* As = sA[buf];
        const __half* Bs = sB[buf];
#pragma unroll
        for (int ks = 0; ks < 4; ++ks) {
            uint32_t a[4][4], b[4][2];
#pragma unroll
            for (int mi = 0; mi < 4; ++mi) {
                uint32_t addr = (uint32_t)__cvta_generic_to_shared(
                    &As[(wm + mi*16 + (lane & 15)) * LDS_ + ks*16 + (lane >> 4) * 8]);
                asm volatile("ldmatrix.sync.aligned.m8n8.x4.shared.b16 {%0,%1,%2,%3}, [%4];"
                    : "=r"(a[mi][0]), "=r"(a[mi][1]), "=r"(a[mi][2]), "=r"(a[mi][3])
                    : "r"(addr));
            }
#pragma unroll
            for (int ni = 0; ni < 4; ++ni) {
                uint32_t addr = (uint32_t)__cvta_generic_to_shared(
                    &Bs[(wn + ni*8 + (lane & 7)) * LDS_ + ks*16 + ((lane >> 3) & 1) * 8]);
                asm volatile("ldmatrix.sync.aligned.m8n8.x2.shared.b16 {%0,%1}, [%2];"
                    : "=r"(b[ni][0]), "=r"(b[ni][1]) : "r"(addr));
            }
#pragma unroll
            for (int mi = 0; mi < 4; ++mi)
#pragma unroll
                for (int ni = 0; ni < 4; ++ni) {
                    asm volatile(
                        "mma.sync.aligned.m16n8k16.row.col.f32.f16.f16.f32 "
                        "{%0,%1,%2,%3}, {%4,%5,%6,%7}, {%8,%9}, {%0,%1,%2,%3};"
                        : "+f"(acc[mi][ni][0]), "+f"(acc[mi][ni][1]),
                          "+f"(acc[mi][ni][2]), "+f"(acc[mi][ni][3])
                        : "r"(a[mi][0]), "r"(a[mi][1]), "r"(a[mi][2]), "r"(a[mi][3]),
                          "r"(b[ni][0]), "r"(b[ni][1]));
                }
        }
        __syncthreads();
    }

#pragma unroll
    for (int mi = 0; mi < 4; ++mi)
#pragma unroll
        for (int ni = 0; ni < 4; ++ni) {
            const int r = row0 + wm + mi*16 + (lane >> 2);
            const int c = col0 + wn + ni*8 + (lane & 3) * 2;
            float2 v0 = make_float2(acc[mi][ni][0], acc[mi][ni][1]);
            float2 v1 = make_float2(acc[mi][ni][2], acc[mi][ni][3]);
            *(float2*)&C[(size_t)r * N + c]       = v0;
            *(float2*)&C[(size_t)(r + 8) * N + c] = v1;
        }
}

// ========== fused char-LSTM GEMM step ====
__global__ __launch_bounds__(256)
void hgemm_lstm(const __half* __restrict__ A, const __half* __restrict__ Bm,
                __half* __restrict__ hsW, const int* __restrict__ chars, int t)
{
    const int act_t = g_act[t];
    const int row0 = blockIdx.y * 128;
    if (row0 >= act_t) return;
    const int col0 = blockIdx.x * 128;
    const int K = CH_;

    extern __shared__ __half smem_[];
    __half* const sA[2] = { smem_,                smem_ + 2*128*LDS_ };
    __half* const sB[2] = { smem_ + 128*LDS_,     smem_ + 3*128*LDS_ };

    const int tid  = threadIdx.x;
    const int lane = tid & 31;
    const int wid  = tid >> 5;
    const int wm   = (wid & 1) * 64;
    const int wn   = (wid >> 1) * 32;

    const int lr = tid >> 1;
    const int cb = (tid & 1) * 4;

    float acc[4][4][4];
#pragma unroll
    for (int mi = 0; mi < 4; ++mi)
#pragma unroll
        for (int ni = 0; ni < 4; ++ni)
#pragma unroll
            for (int f = 0; f < 4; ++f) acc[mi][ni][f] = 0.f;

    const int KT = K >> 6;

    {
        const __half* Ap = A  + (size_t)(row0 + lr) * K + cb * 8;
        const __half* Bp = Bm + (size_t)(col0 + lr) * K + cb * 8;
#pragma unroll
        for (int c = 0; c < 4; ++c) {
            cp16(&sA[0][lr * LDS_ + (cb + c) * 8], Ap + c * 8);
            cp16(&sB[0][lr * LDS_ + (cb + c) * 8], Bp + c * 8);
        }
        asm volatile("cp.async.commit_group;");
    }

    for (int kt = 0; kt < KT; ++kt) {
        const int buf = kt & 1;
        if (kt + 1 < KT) {
            const int k0 = (kt + 1) << 6;
            const __half* Ap = A  + (size_t)(row0 + lr) * K + k0 + cb * 8;
            const __half* Bp = Bm + (size_t)(col0 + lr) * K + k0 + cb * 8;
#pragma unroll
            for (int c = 0; c < 4; ++c) {
                cp16(&sA[buf ^ 1][lr * LDS_ + (cb + c) * 8], Ap + c * 8);
                cp16(&sB[buf ^ 1][lr * LDS_ + (cb + c) * 8], Bp + c * 8);
            }
            asm volatile("cp.async.commit_group;");
            asm volatile("cp.async.wait_group 1;");
        } else {
            asm volatile("cp.async.wait_group 0;");
        }
        __syncthreads();

        const __half* As = sA[buf];
        const __half* Bs = sB[buf];
#pragma unroll
        for (int ks = 0; ks < 4; ++ks) {
            uint32_t a[4][4], b[4][2];
#pragma unroll
            for (int mi = 0; mi < 4; ++mi) {
                uint32_t addr = (uint32_t)__cvta_generic_to_shared(
                    &As[(wm + mi*16 + (lane & 15)) * LDS_ + ks*16 + (lane >> 4) * 8]);
                asm volatile("ldmatrix.sync.aligned.m8n8.x4.shared.b16 {%0,%1,%2,%3}, [%4];"
                    : "=r"(a[mi][0]), "=r"(a[mi][1]), "=r"(a[mi][2]), "=r"(a[mi][3])
                    : "r"(addr));
            }
#pragma unroll
            for (int ni = 0; ni < 4; ++ni) {
                uint32_t addr = (uint32_t)__cvta_generic_to_shared(
                    &Bs[(wn + ni*8 + (lane & 7)) * LDS_ + ks*16 + ((lane >> 3) & 1) * 8]);
                asm volatile("ldmatrix.sync.aligned.m8n8.x2.shared.b16 {%0,%1}, [%2];"
                    : "=r"(b[ni][0]), "=r"(b[ni][1]) : "r"(addr));
            }
#pragma unroll
            for (int mi = 0; mi < 4; ++mi)
#pragma unroll
                for (int ni = 0; ni < 4; ++ni) {
                    asm volatile(
                        "mma.sync.aligned.m16n8k16.row.col.f32.f16.f16.f32 "
                        "{%0,%1,%2,%3}, {%4,%5,%6,%7}, {%8,%9}, {%0,%1,%2,%3};"
                        : "+f"(acc[mi][ni][0]), "+f"(acc[mi][ni][1]),
                          "+f"(acc[mi][ni][2]), "+f"(acc[mi][ni][3])
                        : "r"(a[mi][0]), "r"(a[mi][1]), "r"(a[mi][2]), "r"(a[mi][3]),
                          "r"(b[ni][0]), "r"(b[ni][1]));
                }
        }
        __syncthreads();
    }

    float* Sg = (float*)smem_;
#pragma unroll
    for (int mi = 0; mi < 4; ++mi)
#pragma unroll
        for (int ni = 0; ni < 4; ++ni) {
            const int r = wm + mi*16 + (lane >> 2);
            const int c = wn + ni*8 + (lane & 3) * 2;
            Sg[r * 132 + c]           = acc[mi][ni][0];
            Sg[r * 132 + c + 1]       = acc[mi][ni][1];
            Sg[(r + 8) * 132 + c]     = acc[mi][ni][2];
            Sg[(r + 8) * 132 + c + 1] = acc[mi][ni][3];
        }
    __syncthreads();

    const int jb = col0 >> 2;
#pragma unroll
    for (int q = 0; q < 16; ++q) {
        const int cid = tid + q * 256;
        const int nl = cid >> 5, jl = cid & 31;
        const int n = row0 + nl;
        if (n >= act_t) continue;
        const int j = jb + jl;
        float4 z = *(float4*)&Sg[nl * 132 + jl * 4];
        const int tok = chars[g_perm[n] * Wc_ + t];
        float4 p = *(const float4*)&g_Pp[(size_t)tok * CG_ + j * 4];
        const float zi = z.x + p.x, zf = z.y + p.y, zg = z.z + p.z, zo = z.w + p.w;
        const float c_old = g_cc[(size_t)n * CH_ + j];
        const float cn = sig_ap(zf) * c_old + sig_ap(zi) * tanh_ap(zg);
        const float hn = sig_ap(zo) * tanh_ap(cn);
        g_cc[(size_t)n * CH_ + j] = cn;
        g_ch[(size_t)n * CH_ + j] = hn;
        hsW[(size_t)n * CH_ + j] = __float2half(hn);
    }
}

// ---------------- char t=0 gate ----------------
__global__ void char_gate0(const int* __restrict__ chars, __half* __restrict__ hsW)
{
    const int n = blockIdx.y;
    const int j = blockIdx.x * blockDim.x + threadIdx.x;
    const int tok = chars[g_perm[n] * Wc_ + 0];
    float4 p = *(const float4*)&g_Pp[(size_t)tok * CG_ + j * 4];
    const float cn = sig_ap(p.x) * tanh_ap(p.z);
    const float hn = sig_ap(p.w) * tanh_ap(cn);
    g_cc[(size_t)n * CH_ + j] = cn;
    g_ch[(size_t)n * CH_ + j] = hn;
    hsW[(size_t)n * CH_ + j] = __float2half(hn);
}

// ---------------- fp32 SGEMM (only for P = char_emb @ c_Wih.T, M=128) ----------
__global__ __launch_bounds__(256)
void sgemm128(const float* __restrict__ A, const float* __restrict__ Bm,
              float* __restrict__ C, int M, int N, int K)
{
    __shared__ float As[8][128];
    __shared__ float Bs[8][128];
    const int tid = threadIdx.x;
    const int tx  = tid & 15;
    const int ty  = tid >> 4;
    const int row0 = blockIdx.y * 128;
    const int col0 = blockIdx.x * 128;
    const int lr = tid >> 1;
    const int lk = (tid & 1) * 4;

    const float* Ap = A  + (size_t)(row0 + lr) * K + lk;
    const float* Bp = Bm + (size_t)(col0 + lr) * K + lk;

    float acc[8][8];
#pragma unroll
    for (int i = 0; i < 8; ++i)
#pragma unroll
        for (int j = 0; j < 8; ++j) acc[i][j] = 0.f;

    {
        float4 a = *(const float4*)Ap;
        float4 b = *(const float4*)Bp;
        As[lk+0][lr] = a.x; As[lk+1][lr] = a.y; As[lk+2][lr] = a.z; As[lk+3][lr] = a.w;
        Bs[lk+0][lr] = b.x; Bs[lk+1][lr] = b.y; Bs[lk+2][lr] = b.z; Bs[lk+3][lr] = b.w;
    }
    __syncthreads();

    int k0 = 0;
    while (true) {
        const int kn = k0 + 8;
        const bool more = kn < K;
        float4 an, bn;
        if (more) { an = *(const float4*)(Ap + kn); bn = *(const float4*)(Bp + kn); }
#pragma unroll
        for (int k = 0; k < 8; ++k) {
            float4 a0 = *(const float4*)&As[k][ty*8];
            float4 a1 = *(const float4*)&As[k][ty*8+4];
            float4 b0 = *(const float4*)&Bs[k][tx*8];
            float4 b1 = *(const float4*)&Bs[k][tx*8+4];
            float av[8] = {a0.x,a0.y,a0.z,a0.w,a1.x,a1.y,a1.z,a1.w};
            float bv[8] = {b0.x,b0.y,b0.z,b0.w,b1.x,b1.y,b1.z,b1.w};
#pragma unroll
            for (int i = 0; i < 8; ++i)
#pragma unroll
                for (int j = 0; j < 8; ++j)
                    acc[i][j] = fmaf(av[i], bv[j], acc[i][j]);
        }
        if (!more) break;
        __syncthreads();
        As[lk+0][lr] = an.x; As[lk+1][lr] = an.y; As[lk+2][lr] = an.z; As[lk+3][lr] = an.w;
        Bs[lk+0][lr] = bn.x; Bs[lk+1][lr] = bn.y; Bs[lk+2][lr] = bn.z; Bs[lk+3][lr] = bn.w;
        __syncthreads();
        k0 = kn;
    }

#pragma unroll
    for (int i = 0; i < 8; ++i) {
        const int r = row0 + ty*8 + i;
        float4 o0, o1;
        o0.x = acc[i][0]; o0.y = acc[i][1]; o0.z = acc[i][2]; o0.w = acc[i][3];
        o1.x = acc[i][4]; o1.y = acc[i][5]; o1.z = acc[i][6]; o1.w = acc[i][7];
        *(float4*)(C + (size_t)r*N + col0 + tx*8)     = o0;
        *(float4*)(C + (size_t)r*N + col0 + tx*8 + 4) = o1;
    }
}

// ============ persistent word BiLSTM layer on tensor cores (fp16x1) =============
// A = [h_hi] (state fp16-quantized each step), B = [w_hi]. K = 512.
// 128 blocks: dir = blk>>6, 8 j per block. Per step: Z[64x32] = A[64x512] @
// W[32x512]^T via HMMA (W resident in smem), fused LSTM cell (c/h fp32 regs).
__global__ __launch_bounds__(256)
void word_layer_mma(const __half* __restrict__ WhhS,
                    const float* __restrict__ XG,
                    const int* __restrict__ lens, const float* __restrict__ bias,
                    float* __restrict__ Hout, __half* __restrict__ HoutH)
{
    extern __shared__ char sm_[];
    __half* const sA0 = (__half*)sm_;                       // [2][64][136]
    __half* const sA1 = sA0 + 64 * LDSA_;
    __half* const sW  = (__half*)(sm_ + 34816);             // [32][520]
    float*  const Zs  = (float*)(sm_ + 34816 + 33280);      // [64][36]

    const int tid  = threadIdx.x;
    const int lane = tid & 31;
    const int wid  = tid >> 5;
    const int dir  = blockIdx.x >> 6;
    const int jt   = (blockIdx.x & 63) << 3;                // 8 j per block
    const int m0   = (wid >> 1) * 16;                       // warp m row
    const int n0   = (wid & 1) * 16;                        // warp n row

    // ---- load resident W slice: rows jt*4 .. jt*4+32 of [2048][512] ----
    {
        const __half* Wg = WhhS + ((size_t)dir * G_ + (size_t)jt * 4) * KW_;
#pragma unroll
        for (int i = 0; i < 8; ++i) {
            const int chunk = tid + i * 256;                // 0..2047
            const int row = chunk >> 6, c8 = chunk & 63;
            cp16(&sW[row * WST_ + c8 * 8], Wg + (size_t)row * KW_ + c8 * 8);
        }
        asm volatile("cp.async.commit_group;");
        asm volatile("cp.async.wait_group 0;");
    }
    __syncthreads();

    // ---- per-thread cells: (b0=bb, b1=bb+32) x j ----
    const int jl = tid & 7;
    const int bb = tid >> 3;                                // 0..31
    const int j  = jt + jl;
    const float* bv = bias + (size_t)dir * G_;
    float bg[4];
#pragma unroll
    for (int g = 0; g < 4; ++g) bg[g] = bv[g * H_ + j];
    const int len0 = lens[bb];
    const int len1 = lens[bb + 32];

    float c0 = 0.f, c1 = 0.f, h0 = 0.f, h1 = 0.f;

    for (int t = 0; t < S_; ++t) {
        const __half* hcur = g_hppS + (size_t)(((t    ) & 1) * 2 + dir) * (B_ * KW_);
        __half*       hnxt = g_hppS + (size_t)(((t + 1) & 1) * 2 + dir) * (B_ * KW_);

        float acc[2][4];
#pragma unroll
        for (int ni = 0; ni < 2; ++ni)
#pragma unroll
            for (int f = 0; f < 4; ++f) acc[ni][f] = 0.f;

        // prologue: A chunk 0 (64 rows x 128 cols)
        {
#pragma unroll
            for (int i = 0; i < 4; ++i) {
                const int ch = tid + i * 256;               // 0..1023
                const int row = ch >> 4, c8 = ch & 15;
                cp16(&sA0[row * LDSA_ + c8 * 8], hcur + (size_t)row * KW_ + c8 * 8);
            }
            asm volatile("cp.async.commit_group;");
        }

        for (int kt = 0; kt < 4; ++kt) {
            __half* const sAr = (kt & 1) ? sA1 : sA0;
            if (kt + 1 < 4) {
                __half* const sAw = (kt & 1) ? sA0 : sA1;
                const int k0 = (kt + 1) << 7;
#pragma unroll
                for (int i = 0; i < 4; ++i) {
                    const int ch = tid + i * 256;
                    const int row = ch >> 4, c8 = ch & 15;
                    cp16(&sAw[row * LDSA_ + c8 * 8], hcur + (size_t)row * KW_ + k0 + c8 * 8);
                }
                asm volatile("cp.async.commit_group;");
                asm volatile("cp.async.wait_group 1;");
            } else {
                asm volatile("cp.async.wait_group 0;");
            }
            __syncthreads();

#pragma unroll
            for (int ks = 0; ks < 8; ++ks) {
                uint32_t a[4], r0, r1, r2, r3;
                uint32_t addrA = (uint32_t)__cvta_generic_to_shared(
                    &sAr[(m0 + (lane & 15)) * LDSA_ + ks*16 + (lane >> 4) * 8]);
                asm volatile("ldmatrix.sync.aligned.m8n8.x4.shared.b16 {%0,%1,%2,%3}, [%4];"
                    : "=r"(a[0]), "=r"(a[1]), "=r"(a[2]), "=r"(a[3]) : "r"(addrA));
                uint32_t addrB = (uint32_t)__cvta_generic_to_shared(
                    &sW[(n0 + (lane & 15)) * WST_ + kt*128 + ks*16 + (lane >> 4) * 8]);
                asm volatile("ldmatrix.sync.aligned.m8n8.x4.shared.b16 {%0,%1,%2,%3}, [%4];"
                    : "=r"(r0), "=r"(r1), "=r"(r2), "=r"(r3) : "r"(addrB));
                asm volatile(
                    "mma.sync.aligned.m16n8k16.row.col.f32.f16.f16.f32 "
                    "{%0,%1,%2,%3}, {%4,%5,%6,%7}, {%8,%9}, {%0,%1,%2,%3};"
                    : "+f"(acc[0][0]), "+f"(acc[0][1]), "+f"(acc[0][2]), "+f"(acc[0][3])
                    : "r"(a[0]), "r"(a[1]), "r"(a[2]), "r"(a[3]), "r"(r0), "r"(r2));
                asm volatile(
                    "mma.sync.aligned.m16n8k16.row.col.f32.f16.f16.f32 "
                    "{%0,%1,%2,%3}, {%4,%5,%6,%7}, {%8,%9}, {%0,%1,%2,%3};"
                    : "+f"(acc[1][0]), "+f"(acc[1][1]), "+f"(acc[1][2]), "+f"(acc[1][3])
                    : "r"(a[0]), "r"(a[1]), "r"(a[2]), "r"(a[3]), "r"(r1), "r"(r3));
            }
            __syncthreads();
        }

        // stage Z fragments to smem
        {
            const int r = m0 + (lane >> 2);
            const int c = n0 + (lane & 3) * 2;
#pragma unroll
            for (int ni = 0; ni < 2; ++ni) {
                Zs[r * 36 + c + ni*8]           = acc[ni][0];
                Zs[r * 36 + c + ni*8 + 1]       = acc[ni][1];
                Zs[(r + 8) * 36 + c + ni*8]     = acc[ni][2];
                Zs[(r + 8) * 36 + c + ni*8 + 1] = acc[ni][3];
            }
        }
        __syncthreads();

        // ---- fused LSTM cell (2 cells per thread) ----
#pragma unroll
        for (int half2i = 0; half2i < 2; ++half2i) {
            const int b = bb + half2i * 32;
            const int len = half2i ? len1 : len0;
            const bool valid = t < len;
            const int src = (dir == 0) ? t : (valid ? (len - 1 - t) : t);
            float4 z = *(float4*)&Zs[b * 36 + jl * 4];
            const float* xg = XG + (size_t)(b * S_ + src) * (2 * G_) + (size_t)dir * G_ + j;
            const float zi = z.x + xg[0]      + bg[0];
            const float zf = z.y + xg[H_]     + bg[1];
            const float zg = z.z + xg[2*H_]   + bg[2];
            const float zo = z.w + xg[3*H_]   + bg[3];
            const float c_old = half2i ? c1 : c0;
            const float cn = sigf(zf) * c_old + sigf(zi) * tanhf_fast(zg);
            const float hn = sigf(zo) * tanhf_fast(cn);
            const float h_old = half2i ? h1 : h0;
            const float h_out = valid ? hn : h_old;
            const float c_out = valid ? cn : c_old;
            if (half2i) { c1 = c_out; h1 = h_out; }
            else        { c0 = c_out; h0 = h_out; }
            __stcg(hnxt + (size_t)b * KW_ + j, __float2half(h_out));
            if (dir == 0) {
                if (valid) {
                    if (Hout)  Hout [(size_t)(b * S_ + t) * CH_ + j] = hn;
                    if (HoutH) HoutH[(size_t)(b * S_ + t) * CH_ + j] = __float2half(hn);
                }
            } else if (valid) {
                if (Hout)  Hout [(size_t)(b * S_ + src) * CH_ + H_ + j] = hn;
                if (HoutH) HoutH[(size_t)(b * S_ + src) * CH_ + H_ + j] = __float2half(hn);
            }
        }

        if (t < S_ - 1) {
            __syncthreads();
            if (tid == 0) {
                __threadfence();
                atomicAdd(&g_bar, 1u);
                const unsigned tgt = (unsigned)(t + 1) * (unsigned)NBLK_;
                volatile unsigned* p = &g_bar;
                while (*p < tgt) __nanosleep(64);
            }
            __syncthreads();
        }
    }
}

// ---------------- word embedding gather (fp16) ----------------
__global__ void embed_words(const int* __restrict__ words, const float* __restrict__ emb)
{
    const int m = blockIdx.x;
    const int e = threadIdx.x;
    g_XembH[(size_t)m*E_ + e] = __float2half(emb[(size_t)words[m] * E_ + e]);
}

// ---------------- final head ----------------
__global__ __launch_bounds__(256)
void final_linear(const int* __restrict__ wnum, const float* __restrict__ W,
                  const float* __restrict__ bias, float* __restrict__ out)
{
    const int row = blockIdx.x;
    const int b = row >> 7;
    const int s = row & (S_ - 1);
    const bool valid = s < wnum[b];
    const int slot = g_iperm[row];
    __shared__ float v[CH_];
    __shared__ float sred[8*NC_];
    const int tid = threadIdx.x;
    for (int j = tid; j < CH_; j += 256) {
        float x = g_H1[(size_t)row*CH_ + j];
        if (valid) x += g_ch[(size_t)slot*CH_ + j];
        v[j] = x;
    }
    __syncthreads();
    float acc[NC_];
#pragma unroll
    for (int c2 = 0; c2 < NC_; ++c2) acc[c2] = 0.f;
    for (int j = tid; j < CH_; j += 256) {
        float x = v[j];
#pragma unroll
        for (int c2 = 0; c2 < NC_; ++c2)
            acc[c2] = fmaf(x, W[c2*CH_ + j], acc[c2]);
    }
#pragma unroll
    for (int c2 = 0; c2 < NC_; ++c2)
#pragma unroll
        for (int off = 16; off > 0; off >>= 1)
            acc[c2] += __shfl_down_sync(0xffffffffu, acc[c2], off);
    const int lane = tid & 31, w = tid >> 5;
    if (lane == 0)
#pragma unroll
        for (int c2 = 0; c2 < NC_; ++c2) sred[w*NC_ + c2] = acc[c2];
    __syncthreads();
    if (tid < NC_) {
        float sum = bias[tid];
#pragma unroll
        for (int w2 = 0; w2 < 8; ++w2) sum += sred[w2*NC_ + tid];
        out[(size_t)row*NC_ + tid] = sum;
    }
}

// ================================================================================
extern "C" void kernel_launch(void* const* d_in, const int* in_sizes, int n_in,
                              void* d_out, int out_size)
{
    (void)in_sizes; (void)n_in; (void)out_size;
    const int*   words     = (const int*)  d_in[0];
    const int*   words_num = (const int*)  d_in[1];
    const int*   chars     = (const int*)  d_in[2];
    const int*   char_lens = (const int*)  d_in[3];
    const float* word_emb  = (const float*)d_in[4];
    const float* char_emb  = (const float*)d_in[5];
    const float* l0_Wih    = (const float*)d_in[6];
    const float* l0_Whh    = (const float*)d_in[7];
    const float* l0_b      = (const float*)d_in[8];
    const float* l1_Wih    = (const float*)d_in[9];
    const float* l1_Whh    = (const float*)d_in[10];
    const float* l1_b      = (const float*)d_in[11];
    const float* c_Wih     = (const float*)d_in[12];
    const float* c_Whh     = (const float*)d_in[13];
    const float* c_b       = (const float*)d_in[14];
    const float* lin_W     = (const float*)d_in[15];
    const float* lin_b     = (const float*)d_in[16];
    float* out = (float*)d_out;

    float *XG, *H1, *P;
    __half *XembH, *Wih0H, *Wih1H, *WhhS0, *WhhS1, *H0h, *hppS, *hsA, *hsB, *Wc2;
    unsigned* bar;
    int *hist;
    cudaGetSymbolAddress((void**)&XembH, g_XembH);
    cudaGetSymbolAddress((void**)&Wih0H, g_Wih0H);
    cudaGetSymbolAddress((void**)&Wih1H, g_Wih1H);
    cudaGetSymbolAddress((void**)&WhhS0, g_WhhS0);
    cudaGetSymbolAddress((void**)&WhhS1, g_WhhS1);
    cudaGetSymbolAddress((void**)&XG,   g_XG);
    cudaGetSymbolAddress((void**)&H0h,  g_H0h);
    cudaGetSymbolAddress((void**)&H1,   g_H1);
    cudaGetSymbolAddress((void**)&hppS, g_hppS);
    cudaGetSymbolAddress((void**)&bar,  g_bar);
    cudaGetSymbolAddress((void**)&P,    g_P);
    cudaGetSymbolAddress((void**)&hsA,  g_hsA);
    cudaGetSymbolAddress((void**)&hsB,  g_hsB);
    cudaGetSymbolAddress((void**)&Wc2,  g_Wc2);
    cudaGetSymbolAddress((void**)&hist, g_hist);

    cudaFuncSetAttribute(hgemm_lstm,    cudaFuncAttributeMaxDynamicSharedMemorySize, (int)HS_BYTES);
    cudaFuncSetAttribute(hgemm_f,       cudaFuncAttributeMaxDynamicSharedMemorySize, (int)HS_BYTES);
    cudaFuncSetAttribute(word_layer_mma,cudaFuncAttributeMaxDynamicSharedMemorySize, WP_SMEM);

    // ---- fork-join streams ----
    static cudaStream_t s_char = nullptr;
    static cudaEvent_t ev_fork = nullptr, ev_join = nullptr;
    if (!s_char) {
        cudaStreamCreateWithFlags(&s_char, cudaStreamNonBlocking);
        cudaEventCreateWithFlags(&ev_fork, cudaEventDisableTiming);
        cudaEventCreateWithFlags(&ev_join, cudaEventDisableTiming);
    }
    cudaEventRecord(ev_fork, 0);
    cudaStreamWaitEvent(s_char, ev_fork, 0);

    // ======================= char path (stream s_char) ==========================
    cudaMemsetAsync(hist, 0, (Wc_ + 1) * sizeof(int), s_char);
    hist_k<<<NW_/256, 256, 0, s_char>>>(char_lens);
    scan_k<<<1, 32, 0, s_char>>>();
    scatter_k<<<NW_/256, 256, 0, s_char>>>(char_lens);
    half_remap_k<<<(CG_*CH_ + 255)/256, 256, 0, s_char>>>(c_Whh, Wc2);
    sgemm128<<<dim3(CG_/128, 1), 256, 0, s_char>>>(char_emb, c_Wih, P, 128, CG_, E_);
    reorderP_k<<<(128*CG_ + 255)/256, 256, 0, s_char>>>(c_b);
    char_gate0<<<dim3(CH_/256, NW_), 256, 0, s_char>>>(chars, hsA);
    for (int t = 1; t < Wc_; ++t) {
        const __half* rd = ((t - 1) & 1) ? hsB : hsA;
        __half*       wr = (t & 1)       ? hsB : hsA;
        hgemm_lstm<<<dim3(CG_/128, NW_/128), 256, HS_BYTES, s_char>>>(rd, Wc2, wr, chars, t);
    }
    cudaEventRecord(ev_join, s_char);

    // ======================= word path (capture stream) =========================
    half_k<<<(2*G_*E_ + 255)/256, 256>>>(l0_Wih, Wih0H, 2*G_*E_);
    half_k<<<(2*G_*CH_ + 255)/256, 256>>>(l1_Wih, Wih1H, 2*G_*CH_);
    whh_split_k<<<(2*G_*H_ + 255)/256, 256>>>(l0_Whh, WhhS0);
    whh_split_k<<<(2*G_*H_ + 255)/256, 256>>>(l1_Whh, WhhS1);
    embed_words<<<NW_, E_>>>(words, word_emb);

    {   // layer 0 (fp16 x-proj, K=256; both dirs in one GEMM, N=4096)
        hgemm_f<<<dim3((2*G_)/128, NW_/128), 256, HS_BYTES>>>(XembH, Wih0H, XG, NW_, 2*G_, E_);
        cudaMemsetAsync(H0h,  0, (size_t)NW_*CH_*sizeof(__half), 0);
        cudaMemsetAsync(hppS, 0, (size_t)2*2*B_*KW_*sizeof(__half), 0);
        cudaMemsetAsync(bar,  0, sizeof(unsigned), 0);
        word_layer_mma<<<NBLK_, 256, WP_SMEM>>>(WhhS0, XG, words_num, l0_b, nullptr, H0h);
    }
    {   // layer 1 (fp16 x-proj, K=1024; both dirs in one GEMM)
        hgemm_f<<<dim3((2*G_)/128, NW_/128), 256, HS_BYTES>>>(H0h, Wih1H, XG, NW_, 2*G_, CH_);
        cudaMemsetAsync(H1,   0, (size_t)NW_*CH_*sizeof(float), 0);
        cudaMemsetAsync(hppS, 0, (size_t)2*2*B_*KW_*sizeof(__half), 0);
        cudaMemsetAsync(bar,  0, sizeof(unsigned), 0);
        word_layer_mma<<<NBLK_, 256, WP_SMEM>>>(WhhS1, XG, words_num, l1_b, H1, nullptr);
    }

    // ======================= join + head =========================
    cudaStreamWaitEvent(0, ev_join, 0);
    final_linear<<<NW_, 256>>>(words_num, lin_W, lin_b, out);
}